// round 1
// baseline (speedup 1.0000x reference)
#include <cuda_runtime.h>
#include <math.h>

#define BATCH 2
#define SEQ 2048
#define DM 2048
#define NH 16
#define DH 128
#define MROWS (BATCH*SEQ)   // 4096
#define HALF (DH/2)         // 64

// Scratch (allocation-free rule: __device__ globals)
__device__ float g_Q[BATCH*NH*SEQ*DH];
__device__ float g_K[BATCH*NH*SEQ*DH];
__device__ float g_V[BATCH*NH*SEQ*DH];
__device__ float g_Hb[BATCH*SEQ*DM];
__device__ float2 g_rope[SEQ*HALF];

// ---------------------------------------------------------------------------
// RoPE table: replicate the reference's fp32 angle bits exactly:
//   inv_freq fp32 = correctly-rounded(10000^(-2i/128))  (computed in fp64)
//   freq = fp32(pos) * fp32(inv_freq)                    (fp32 multiply)
//   cos/sin of that exact fp32 angle, evaluated in fp64, rounded to fp32.
// ---------------------------------------------------------------------------
__global__ void rope_table_kernel(const int* __restrict__ pos) {
    int s = blockIdx.x;
    int i = threadIdx.x;   // 0..63
    double inv = exp(-((double)(2 * i) / (double)DH) * log(10000.0));
    float invf = (float)inv;
    float freq = (float)pos[s] * invf;   // fp32 product, like the reference
    double a = (double)freq;
    g_rope[s * HALF + i] = make_float2((float)cos(a), (float)sin(a));
}

// ---------------------------------------------------------------------------
// NT GEMM: C[m,n] = sum_k A[m,k] * W[n,k], M=4096, N=2048, K=2048 (fp32)
// MODE 0: A = g_Hb (internal), write Out[m*DM+n]        (final O-proj)
// MODE 1: A = param (x), write g_Q with RoPE, [B,H,S,Dh]
// MODE 2: same -> g_K with RoPE
// MODE 3: same -> g_V plain, [B,H,S,Dh]
// 64x64 tile, BK=32, 256 threads, 4x4 per thread.
// ---------------------------------------------------------------------------
template<int MODE>
__global__ void __launch_bounds__(256) gemm_nt(const float* __restrict__ Aparam,
                                               const float* __restrict__ Wt,
                                               float* __restrict__ OutParam) {
    const int BK = 32;
    __shared__ float As[64][BK + 4];   // stride 36 floats: float4-friendly, low conflict
    __shared__ float Bs[64][BK + 4];

    const float* A = (MODE == 0) ? (const float*)g_Hb : Aparam;

    int m0 = blockIdx.y * 64;
    int n0 = blockIdx.x * 64;
    int tid = threadIdx.x;
    int tx = tid & 15;          // 0..15
    int ty = tid >> 4;          // 0..15

    float acc[4][4] = {};

    for (int k0 = 0; k0 < DM; k0 += BK) {
        // Load 64x32 floats per operand = 512 float4; 256 threads -> 2 each
        #pragma unroll
        for (int rep = 0; rep < 2; rep++) {
            int e = tid + rep * 256;       // 0..511
            int r = e >> 3;
            int c4 = (e & 7) * 4;
            float4 va = *(const float4*)(A + (m0 + r) * DM + k0 + c4);
            As[r][c4 + 0] = va.x; As[r][c4 + 1] = va.y;
            As[r][c4 + 2] = va.z; As[r][c4 + 3] = va.w;
            float4 vb = *(const float4*)(Wt + (n0 + r) * DM + k0 + c4);
            Bs[r][c4 + 0] = vb.x; Bs[r][c4 + 1] = vb.y;
            Bs[r][c4 + 2] = vb.z; Bs[r][c4 + 3] = vb.w;
        }
        __syncthreads();

        #pragma unroll
        for (int k = 0; k < BK; k += 4) {
            float4 a4[4], b4[4];
            #pragma unroll
            for (int i = 0; i < 4; i++) a4[i] = *(const float4*)&As[ty * 4 + i][k];
            #pragma unroll
            for (int j = 0; j < 4; j++) b4[j] = *(const float4*)&Bs[tx * 4 + j][k];
            #pragma unroll
            for (int i = 0; i < 4; i++) {
                #pragma unroll
                for (int j = 0; j < 4; j++) {
                    acc[i][j] += a4[i].x * b4[j].x;
                    acc[i][j] += a4[i].y * b4[j].y;
                    acc[i][j] += a4[i].z * b4[j].z;
                    acc[i][j] += a4[i].w * b4[j].w;
                }
            }
        }
        __syncthreads();
    }

    // Epilogue
    int coln = n0 + tx * 4;   // aligned to 4; d = coln&127 aligned to 4, pairs intact
    #pragma unroll
    for (int i = 0; i < 4; i++) {
        int row = m0 + ty * 4 + i;      // m = b*SEQ + s
        if (MODE == 0) {
            float* dst = OutParam + row * DM + coln;
            dst[0] = acc[i][0]; dst[1] = acc[i][1];
            dst[2] = acc[i][2]; dst[3] = acc[i][3];
        } else {
            int b = row >> 11;
            int s = row & (SEQ - 1);
            int h = coln >> 7;
            int d = coln & (DH - 1);
            float* dst = g_V;
            if (MODE == 1) dst = g_Q;
            if (MODE == 2) dst = g_K;
            dst += ((b * NH + h) * SEQ + s) * DH;
            if (MODE == 3) {
                dst[d + 0] = acc[i][0]; dst[d + 1] = acc[i][1];
                dst[d + 2] = acc[i][2]; dst[d + 3] = acc[i][3];
            } else {
                float2 cs0 = g_rope[s * HALF + (d >> 1)];
                float2 cs1 = g_rope[s * HALF + (d >> 1) + 1];
                dst[d + 0] = acc[i][0] * cs0.x - acc[i][1] * cs0.y;
                dst[d + 1] = acc[i][0] * cs0.y + acc[i][1] * cs0.x;
                dst[d + 2] = acc[i][2] * cs1.x - acc[i][3] * cs1.y;
                dst[d + 3] = acc[i][2] * cs1.y + acc[i][3] * cs1.x;
            }
        }
    }
}

// ---------------------------------------------------------------------------
// Fused causal attention (flash-style, fp32). One block per (b*h, q-tile of 64).
// Online softmax; Q/K/V tiles in dynamic smem; O accumulators in registers.
// ---------------------------------------------------------------------------
#define QSTR 132
#define SSTR 68
#define FLASH_SMEM ((3*64*QSTR + 64*SSTR + 3*64) * 4)

__global__ void __launch_bounds__(256) flash_kernel() {
    extern __shared__ float sm[];
    float (*Qs)[QSTR] = (float(*)[QSTR])sm;
    float (*Ks)[QSTR] = (float(*)[QSTR])(sm + 64 * QSTR);
    float (*Vs)[QSTR] = (float(*)[QSTR])(sm + 2 * 64 * QSTR);
    float (*Ss)[SSTR] = (float(*)[SSTR])(sm + 3 * 64 * QSTR);
    float* mrow = sm + 3 * 64 * QSTR + 64 * SSTR;
    float* lrow = mrow + 64;
    float* crow = lrow + 64;

    int bh = blockIdx.y;   // 0..31
    int qt = blockIdx.x;   // 0..31
    int tid = threadIdx.x;
    int tx = tid & 15;
    int ty = tid >> 4;

    const float* Qp = g_Q + (bh * SEQ + qt * 64) * DH;
    const float* Kp = g_K + bh * SEQ * DH;
    const float* Vp = g_V + bh * SEQ * DH;

    // Load Q tile (64x128 floats = 2048 float4, 8 per thread)
    #pragma unroll
    for (int rep = 0; rep < 8; rep++) {
        int e = tid + rep * 256;
        int r = e >> 5;
        int c4 = (e & 31) * 4;
        float4 v = *(const float4*)(Qp + r * DH + c4);
        Qs[r][c4 + 0] = v.x; Qs[r][c4 + 1] = v.y;
        Qs[r][c4 + 2] = v.z; Qs[r][c4 + 3] = v.w;
    }
    if (tid < 64) { mrow[tid] = -INFINITY; lrow[tid] = 0.f; }

    float acc[4][8] = {};               // rows ty*4+i, cols tx*8+c
    const float scale = 0.08838834764831845f;  // 1/sqrt(128)

    for (int kt = 0; kt <= qt; kt++) {
        __syncthreads();  // Q ready (iter 0); prior PV reads of Ks/Vs done (iter>0)

        // Load K,V tiles
        #pragma unroll
        for (int rep = 0; rep < 8; rep++) {
            int e = tid + rep * 256;
            int r = e >> 5;
            int c4 = (e & 31) * 4;
            float4 vk = *(const float4*)(Kp + (kt * 64 + r) * DH + c4);
            Ks[r][c4 + 0] = vk.x; Ks[r][c4 + 1] = vk.y;
            Ks[r][c4 + 2] = vk.z; Ks[r][c4 + 3] = vk.w;
            float4 vv = *(const float4*)(Vp + (kt * 64 + r) * DH + c4);
            Vs[r][c4 + 0] = vv.x; Vs[r][c4 + 1] = vv.y;
            Vs[r][c4 + 2] = vv.z; Vs[r][c4 + 3] = vv.w;
        }
        __syncthreads();

        // Scores: 4x4 per thread, dot over DH=128
        float sc[4][4] = {};
        #pragma unroll 4
        for (int k = 0; k < DH; k += 4) {
            float4 q4[4], k4[4];
            #pragma unroll
            for (int i = 0; i < 4; i++) q4[i] = *(const float4*)&Qs[ty * 4 + i][k];
            #pragma unroll
            for (int j = 0; j < 4; j++) k4[j] = *(const float4*)&Ks[tx * 4 + j][k];
            #pragma unroll
            for (int i = 0; i < 4; i++) {
                #pragma unroll
                for (int j = 0; j < 4; j++) {
                    sc[i][j] += q4[i].x * k4[j].x;
                    sc[i][j] += q4[i].y * k4[j].y;
                    sc[i][j] += q4[i].z * k4[j].z;
                    sc[i][j] += q4[i].w * k4[j].w;
                }
            }
        }
        bool diag = (kt == qt);
        #pragma unroll
        for (int i = 0; i < 4; i++) {
            int r = ty * 4 + i;
            #pragma unroll
            for (int j = 0; j < 4; j++) {
                int c = tx * 4 + j;
                float v = sc[i][j] * scale;
                if (diag && c > r) v = -INFINITY;
                Ss[r][c] = v;
            }
        }
        __syncthreads();

        // Online softmax: 4 threads per row
        {
            int row = tid >> 2;
            int l4 = tid & 3;
            float* srow = Ss[row];
            float mt = -INFINITY;
            #pragma unroll
            for (int j = 0; j < 16; j++) mt = fmaxf(mt, srow[l4 * 16 + j]);
            mt = fmaxf(mt, __shfl_xor_sync(0xffffffffu, mt, 1));
            mt = fmaxf(mt, __shfl_xor_sync(0xffffffffu, mt, 2));
            float mold = mrow[row];
            float mnew = fmaxf(mold, mt);
            float lt = 0.f;
            #pragma unroll
            for (int j = 0; j < 16; j++) {
                float p = expf(srow[l4 * 16 + j] - mnew);
                srow[l4 * 16 + j] = p;
                lt += p;
            }
            lt += __shfl_xor_sync(0xffffffffu, lt, 1);
            lt += __shfl_xor_sync(0xffffffffu, lt, 2);
            if (l4 == 0) {
                float corr = expf(mold - mnew);   // exp(-inf)=0 on first tile
                crow[row] = corr;
                lrow[row] = lrow[row] * corr + lt;
                mrow[row] = mnew;
            }
        }
        __syncthreads();

        // PV: rows ty*4+i, cols tx*8..tx*8+7
        float cr[4];
        #pragma unroll
        for (int i = 0; i < 4; i++) {
            cr[i] = crow[ty * 4 + i];
            #pragma unroll
            for (int c = 0; c < 8; c++) acc[i][c] *= cr[i];
        }
        #pragma unroll 2
        for (int j = 0; j < 64; j++) {
            float4 v0 = *(const float4*)&Vs[j][tx * 8];
            float4 v1 = *(const float4*)&Vs[j][tx * 8 + 4];
            #pragma unroll
            for (int i = 0; i < 4; i++) {
                float p = Ss[ty * 4 + i][j];
                acc[i][0] += p * v0.x; acc[i][1] += p * v0.y;
                acc[i][2] += p * v0.z; acc[i][3] += p * v0.w;
                acc[i][4] += p * v1.x; acc[i][5] += p * v1.y;
                acc[i][6] += p * v1.z; acc[i][7] += p * v1.w;
            }
        }
    }

    // Write H rows: Hb[(b*SEQ+s)*DM + h*DH + col]
    int b = bh >> 4;
    int h = bh & (NH - 1);
    #pragma unroll
    for (int i = 0; i < 4; i++) {
        int r = ty * 4 + i;
        int s = qt * 64 + r;
        float linv = 1.f / lrow[r];
        float* dst = g_Hb + (b * SEQ + s) * DM + h * DH + tx * 8;
        #pragma unroll
        for (int c = 0; c < 8; c++) dst[c] = acc[i][c] * linv;
    }
}

// ---------------------------------------------------------------------------
extern "C" void kernel_launch(void* const* d_in, const int* in_sizes, int n_in,
                              void* d_out, int out_size) {
    const float* x  = (const float*)d_in[0];
    const float* wq = (const float*)d_in[1];
    const float* wk = (const float*)d_in[2];
    const float* wv = (const float*)d_in[3];
    const float* wo = (const float*)d_in[4];
    const int* tok  = (const int*)d_in[5];
    float* out = (float*)d_out;

    cudaFuncSetAttribute(flash_kernel,
                         cudaFuncAttributeMaxDynamicSharedMemorySize, FLASH_SMEM);

    rope_table_kernel<<<SEQ, HALF>>>(tok);

    dim3 ggrid(DM / 64, MROWS / 64);   // (32, 64)
    gemm_nt<1><<<ggrid, 256>>>(x, wq, nullptr);
    gemm_nt<2><<<ggrid, 256>>>(x, wk, nullptr);
    gemm_nt<3><<<ggrid, 256>>>(x, wv, nullptr);

    dim3 fgrid(SEQ / 64, BATCH * NH);  // (32, 32)
    flash_kernel<<<fgrid, 256, FLASH_SMEM>>>();

    gemm_nt<0><<<ggrid, 256>>>(nullptr, wo, out);
}

// round 3
// speedup vs baseline: 1.8264x; 1.8264x over previous
#include <cuda_runtime.h>
#include <cuda_bf16.h>
#include <math.h>
#include <stdint.h>

#define BATCH 2
#define SEQ 2048
#define DM 2048
#define NH 16
#define DH 128
#define MROWS (BATCH*SEQ)   // 4096
#define HALF (DH/2)         // 64

// ---------------------------------------------------------------------------
// Scratch (__device__ globals; allocation-free rule)
// ---------------------------------------------------------------------------
__device__ float g_Q[BATCH*NH*SEQ*DH];
__device__ float g_K[BATCH*NH*SEQ*DH];
__device__ float g_V[BATCH*NH*SEQ*DH];
__device__ float g_Hb[BATCH*SEQ*DM];
__device__ float2 g_rope[SEQ*HALF];
// 2-way bf16 split planes (a = a0 + a1, residual ~2^-18)
__device__ __nv_bfloat16 g_xs[2][MROWS*DM];
__device__ __nv_bfloat16 g_hs[2][MROWS*DM];
__device__ __nv_bfloat16 g_ws[4][2][DM*DM];

// ---------------------------------------------------------------------------
// RoPE table (fp64-accurate angles, matching reference bit patterns)
// ---------------------------------------------------------------------------
__global__ void rope_table_kernel(const int* __restrict__ pos) {
    int s = blockIdx.x;
    int i = threadIdx.x;
    double inv = exp(-((double)(2 * i) / (double)DH) * log(10000.0));
    float invf = (float)inv;
    float freq = (float)pos[s] * invf;
    double a = (double)freq;
    g_rope[s * HALF + i] = make_float2((float)cos(a), (float)sin(a));
}

// ---------------------------------------------------------------------------
// 2-way bf16 split: a ≈ b0 + b1
// TGT: 0=x->g_xs, 1..4=w->g_ws[TGT-1], 5=g_Hb->g_hs
// ---------------------------------------------------------------------------
template<int TGT>
__global__ void split2_kernel(const float* __restrict__ srcp) {
    const int n4 = (TGT == 0 || TGT == 5) ? (MROWS * DM / 4) : (DM * DM / 4);
    int i = blockIdx.x * 256 + threadIdx.x;
    if (i >= n4) return;
    const float* src = (TGT == 5) ? (const float*)g_Hb : srcp;
    __nv_bfloat16* p0;
    __nv_bfloat16* p1;
    if (TGT == 0)      { p0 = g_xs[0]; p1 = g_xs[1]; }
    else if (TGT == 5) { p0 = g_hs[0]; p1 = g_hs[1]; }
    else               { p0 = g_ws[TGT-1][0]; p1 = g_ws[TGT-1][1]; }

    float4 a = ((const float4*)src)[i];
    float x[4] = {a.x, a.y, a.z, a.w};
    __nv_bfloat16 b0[4], b1[4];
    #pragma unroll
    for (int k = 0; k < 4; k++) {
        b0[k] = __float2bfloat16(x[k]);
        float r = x[k] - __bfloat162float(b0[k]);
        b1[k] = __float2bfloat16(r);
    }
    __nv_bfloat162* q0 = (__nv_bfloat162*)p0;
    __nv_bfloat162* q1 = (__nv_bfloat162*)p1;
    __nv_bfloat162 t;
    t.x = b0[0]; t.y = b0[1]; q0[i*2]   = t;
    t.x = b0[2]; t.y = b0[3]; q0[i*2+1] = t;
    t.x = b1[0]; t.y = b1[1]; q1[i*2]   = t;
    t.x = b1[2]; t.y = b1[3]; q1[i*2+1] = t;
}

// ---------------------------------------------------------------------------
// mma.sync bf16 GEMM with fp32 emulation (3 cross-terms of 2-way split).
// C[m,n] = sum_k A[m,k]*W[n,k]. M=4096, N=2048, K=2048.
// CTA tile 128x128, BK=32, 8 warps, warp tile 64x32 (m16n8k16 fragments).
// MODE 1: out=g_Q (+RoPE, head-split)   MODE 2: g_K (+RoPE)
// MODE 3: g_V (head-split)              MODE 0: Out row-major (O-proj)
// ---------------------------------------------------------------------------
#define BK 32
#define TSTR 40   // smem row stride in bf16 (80B: 16B-aligned, conflict-free)

__device__ __forceinline__ void mma16816(float* d, const uint32_t* a,
                                         const uint32_t* b) {
    asm volatile(
        "mma.sync.aligned.m16n8k16.row.col.f32.bf16.bf16.f32 "
        "{%0,%1,%2,%3}, {%4,%5,%6,%7}, {%8,%9}, {%0,%1,%2,%3};\n"
        : "+f"(d[0]), "+f"(d[1]), "+f"(d[2]), "+f"(d[3])
        : "r"(a[0]), "r"(a[1]), "r"(a[2]), "r"(a[3]), "r"(b[0]), "r"(b[1]));
}

template<int MODE>
__global__ void __launch_bounds__(256, 1) gemm_mma(float* __restrict__ Out) {
    // Ts[0]=A0, Ts[1]=A1, Ts[2]=B0, Ts[3]=B1  (128 rows x 32 bf16, stride 40)
    __shared__ __align__(16) __nv_bfloat16 Ts[4][128 * TSTR];

    int tid = threadIdx.x;
    int lane = tid & 31;
    int wid = tid >> 5;
    int m0 = blockIdx.y * 128;
    int n0 = blockIdx.x * 128;
    int wm = (wid & 1) * 64;
    int wn = (wid >> 1) * 32;
    int gr = lane >> 2;   // 0..7
    int gq = lane & 3;    // 0..3

    constexpr int W = (MODE == 0) ? 3 : (MODE - 1);
    const __nv_bfloat16* A0 = (MODE == 0) ? g_hs[0] : g_xs[0];
    const __nv_bfloat16* A1 = (MODE == 0) ? g_hs[1] : g_xs[1];
    const __nv_bfloat16* B0 = g_ws[W][0];
    const __nv_bfloat16* B1 = g_ws[W][1];

    float acc[4][4][4] = {};   // [m-block][n-block][c0..c3]

    for (int kb = 0; kb < DM / BK; kb++) {
        int k0 = kb * BK;
        // Load 4 tiles: 4*512 uint4 over 256 threads = 8 uint4 each
        #pragma unroll
        for (int it = 0; it < 8; it++) {
            int e = tid + it * 256;       // 0..2047
            int t = e >> 9;               // tile 0..3
            int e5 = e & 511;
            int r = e5 >> 2;              // 0..127
            int c8 = (e5 & 3) * 8;        // 0,8,16,24
            const __nv_bfloat16* src =
                (t == 0) ? A0 + (size_t)(m0 + r) * DM + k0 + c8 :
                (t == 1) ? A1 + (size_t)(m0 + r) * DM + k0 + c8 :
                (t == 2) ? B0 + (size_t)(n0 + r) * DM + k0 + c8 :
                           B1 + (size_t)(n0 + r) * DM + k0 + c8;
            *(uint4*)&Ts[t][r * TSTR + c8] = *(const uint4*)src;
        }
        __syncthreads();

        #pragma unroll
        for (int ks = 0; ks < BK; ks += 16) {
            uint32_t af[2][4][4];
            #pragma unroll
            for (int p = 0; p < 2; p++) {
                #pragma unroll
                for (int i = 0; i < 4; i++) {
                    const __nv_bfloat16* ap = Ts[p];
                    int row = wm + i * 16 + gr;
                    int c = ks + gq * 2;
                    af[p][i][0] = *(const uint32_t*)&ap[row * TSTR + c];
                    af[p][i][1] = *(const uint32_t*)&ap[(row + 8) * TSTR + c];
                    af[p][i][2] = *(const uint32_t*)&ap[row * TSTR + c + 8];
                    af[p][i][3] = *(const uint32_t*)&ap[(row + 8) * TSTR + c + 8];
                }
            }
            uint32_t bf[2][4][2];
            #pragma unroll
            for (int p = 0; p < 2; p++) {
                #pragma unroll
                for (int j = 0; j < 4; j++) {
                    const __nv_bfloat16* bp = Ts[2 + p];
                    int n = wn + j * 8 + gr;
                    int c = ks + gq * 2;
                    bf[p][j][0] = *(const uint32_t*)&bp[n * TSTR + c];
                    bf[p][j][1] = *(const uint32_t*)&bp[n * TSTR + c + 8];
                }
            }
            #pragma unroll
            for (int i = 0; i < 4; i++) {
                #pragma unroll
                for (int j = 0; j < 4; j++) {
                    mma16816(acc[i][j], af[0][i], bf[0][j]);  // a0*b0
                    mma16816(acc[i][j], af[0][i], bf[1][j]);  // a0*b1
                    mma16816(acc[i][j], af[1][i], bf[0][j]);  // a1*b0
                }
            }
        }
        __syncthreads();
    }

    // Epilogue from registers. c0,c1 = (row, col), (row, col+1);
    // c2,c3 = (row+8, col), (row+8, col+1). col even -> RoPE pair intact.
    int h = blockIdx.x;   // BN == DH
    #pragma unroll
    for (int i = 0; i < 4; i++) {
        #pragma unroll
        for (int half = 0; half < 2; half++) {
            int row = m0 + wm + i * 16 + gr + half * 8;   // global m
            int s = row & (SEQ - 1);
            int b = row >> 11;
            #pragma unroll
            for (int j = 0; j < 4; j++) {
                int d = wn + j * 8 + gq * 2;              // local col (even)
                float e = acc[i][j][half * 2 + 0];
                float o = acc[i][j][half * 2 + 1];
                if (MODE == 0) {
                    *(float2*)(Out + (size_t)row * DM + n0 + d) =
                        make_float2(e, o);
                } else {
                    float* tgt = (MODE == 1) ? g_Q : (MODE == 2) ? g_K : g_V;
                    float* dst = tgt + ((size_t)(b * NH + h) * SEQ + s) * DH;
                    if (MODE == 3) {
                        *(float2*)(dst + d) = make_float2(e, o);
                    } else {
                        float2 cs = g_rope[s * HALF + (d >> 1)];
                        *(float2*)(dst + d) = make_float2(e * cs.x - o * cs.y,
                                                          e * cs.y + o * cs.x);
                    }
                }
            }
        }
    }
}

// ---------------------------------------------------------------------------
// Fused causal attention (unchanged from Round 1 — fp32 flash)
// ---------------------------------------------------------------------------
#define QSTR 132
#define SSTR 68
#define FLASH_SMEM ((3*64*QSTR + 64*SSTR + 3*64) * 4)

__global__ void __launch_bounds__(256) flash_kernel() {
    extern __shared__ float smf[];
    float (*Qs)[QSTR] = (float(*)[QSTR])smf;
    float (*Ks)[QSTR] = (float(*)[QSTR])(smf + 64 * QSTR);
    float (*Vs)[QSTR] = (float(*)[QSTR])(smf + 2 * 64 * QSTR);
    float (*Ss)[SSTR] = (float(*)[SSTR])(smf + 3 * 64 * QSTR);
    float* mrow = smf + 3 * 64 * QSTR + 64 * SSTR;
    float* lrow = mrow + 64;
    float* crow = lrow + 64;

    int bh = blockIdx.y;
    int qt = blockIdx.x;
    int tid = threadIdx.x;
    int tx = tid & 15;
    int ty = tid >> 4;

    const float* Qp = g_Q + (bh * SEQ + qt * 64) * DH;
    const float* Kp = g_K + bh * SEQ * DH;
    const float* Vp = g_V + bh * SEQ * DH;

    #pragma unroll
    for (int rep = 0; rep < 8; rep++) {
        int e = tid + rep * 256;
        int r = e >> 5;
        int c4 = (e & 31) * 4;
        float4 v = *(const float4*)(Qp + r * DH + c4);
        Qs[r][c4 + 0] = v.x; Qs[r][c4 + 1] = v.y;
        Qs[r][c4 + 2] = v.z; Qs[r][c4 + 3] = v.w;
    }
    if (tid < 64) { mrow[tid] = -INFINITY; lrow[tid] = 0.f; }

    float acc[4][8] = {};
    const float scale = 0.08838834764831845f;

    for (int kt = 0; kt <= qt; kt++) {
        __syncthreads();
        #pragma unroll
        for (int rep = 0; rep < 8; rep++) {
            int e = tid + rep * 256;
            int r = e >> 5;
            int c4 = (e & 31) * 4;
            float4 vk = *(const float4*)(Kp + (kt * 64 + r) * DH + c4);
            Ks[r][c4 + 0] = vk.x; Ks[r][c4 + 1] = vk.y;
            Ks[r][c4 + 2] = vk.z; Ks[r][c4 + 3] = vk.w;
            float4 vv = *(const float4*)(Vp + (kt * 64 + r) * DH + c4);
            Vs[r][c4 + 0] = vv.x; Vs[r][c4 + 1] = vv.y;
            Vs[r][c4 + 2] = vv.z; Vs[r][c4 + 3] = vv.w;
        }
        __syncthreads();

        float sc[4][4] = {};
        #pragma unroll 4
        for (int k = 0; k < DH; k += 4) {
            float4 q4[4], k4[4];
            #pragma unroll
            for (int i = 0; i < 4; i++) q4[i] = *(const float4*)&Qs[ty * 4 + i][k];
            #pragma unroll
            for (int j = 0; j < 4; j++) k4[j] = *(const float4*)&Ks[tx * 4 + j][k];
            #pragma unroll
            for (int i = 0; i < 4; i++) {
                #pragma unroll
                for (int j = 0; j < 4; j++) {
                    sc[i][j] += q4[i].x * k4[j].x;
                    sc[i][j] += q4[i].y * k4[j].y;
                    sc[i][j] += q4[i].z * k4[j].z;
                    sc[i][j] += q4[i].w * k4[j].w;
                }
            }
        }
        bool diag = (kt == qt);
        #pragma unroll
        for (int i = 0; i < 4; i++) {
            int r = ty * 4 + i;
            #pragma unroll
            for (int j = 0; j < 4; j++) {
                int c = tx * 4 + j;
                float v = sc[i][j] * scale;
                if (diag && c > r) v = -INFINITY;
                Ss[r][c] = v;
            }
        }
        __syncthreads();

        {
            int row = tid >> 2;
            int l4 = tid & 3;
            float* srow = Ss[row];
            float mt = -INFINITY;
            #pragma unroll
            for (int j = 0; j < 16; j++) mt = fmaxf(mt, srow[l4 * 16 + j]);
            mt = fmaxf(mt, __shfl_xor_sync(0xffffffffu, mt, 1));
            mt = fmaxf(mt, __shfl_xor_sync(0xffffffffu, mt, 2));
            float mold = mrow[row];
            float mnew = fmaxf(mold, mt);
            float lt = 0.f;
            #pragma unroll
            for (int j = 0; j < 16; j++) {
                float p = expf(srow[l4 * 16 + j] - mnew);
                srow[l4 * 16 + j] = p;
                lt += p;
            }
            lt += __shfl_xor_sync(0xffffffffu, lt, 1);
            lt += __shfl_xor_sync(0xffffffffu, lt, 2);
            if (l4 == 0) {
                float corr = expf(mold - mnew);
                crow[row] = corr;
                lrow[row] = lrow[row] * corr + lt;
                mrow[row] = mnew;
            }
        }
        __syncthreads();

        float cr[4];
        #pragma unroll
        for (int i = 0; i < 4; i++) {
            cr[i] = crow[ty * 4 + i];
            #pragma unroll
            for (int c = 0; c < 8; c++) acc[i][c] *= cr[i];
        }
        #pragma unroll 2
        for (int j = 0; j < 64; j++) {
            float4 v0 = *(const float4*)&Vs[j][tx * 8];
            float4 v1 = *(const float4*)&Vs[j][tx * 8 + 4];
            #pragma unroll
            for (int i = 0; i < 4; i++) {
                float p = Ss[ty * 4 + i][j];
                acc[i][0] += p * v0.x; acc[i][1] += p * v0.y;
                acc[i][2] += p * v0.z; acc[i][3] += p * v0.w;
                acc[i][4] += p * v1.x; acc[i][5] += p * v1.y;
                acc[i][6] += p * v1.z; acc[i][7] += p * v1.w;
            }
        }
    }

    int b = bh >> 4;
    int h = bh & (NH - 1);
    #pragma unroll
    for (int i = 0; i < 4; i++) {
        int r = ty * 4 + i;
        int s = qt * 64 + r;
        float linv = 1.f / lrow[r];
        float* dst = g_Hb + (b * SEQ + s) * DM + h * DH + tx * 8;
        #pragma unroll
        for (int c = 0; c < 8; c++) dst[c] = acc[i][c] * linv;
    }
}

// ---------------------------------------------------------------------------
extern "C" void kernel_launch(void* const* d_in, const int* in_sizes, int n_in,
                              void* d_out, int out_size) {
    const float* x  = (const float*)d_in[0];
    const float* wq = (const float*)d_in[1];
    const float* wk = (const float*)d_in[2];
    const float* wv = (const float*)d_in[3];
    const float* wo = (const float*)d_in[4];
    const int* tok  = (const int*)d_in[5];
    float* out = (float*)d_out;

    cudaFuncSetAttribute(flash_kernel,
                         cudaFuncAttributeMaxDynamicSharedMemorySize, FLASH_SMEM);

    rope_table_kernel<<<SEQ, HALF>>>(tok);
    split2_kernel<0><<<MROWS*DM/4/256, 256>>>(x);
    split2_kernel<1><<<DM*DM/4/256, 256>>>(wq);
    split2_kernel<2><<<DM*DM/4/256, 256>>>(wk);
    split2_kernel<3><<<DM*DM/4/256, 256>>>(wv);
    split2_kernel<4><<<DM*DM/4/256, 256>>>(wo);

    dim3 gg(DM / 128, MROWS / 128);   // (16, 32)
    gemm_mma<1><<<gg, 256>>>(nullptr);
    gemm_mma<2><<<gg, 256>>>(nullptr);
    gemm_mma<3><<<gg, 256>>>(nullptr);

    dim3 fgrid(SEQ / 64, BATCH * NH);
    flash_kernel<<<fgrid, 256, FLASH_SMEM>>>();

    split2_kernel<5><<<MROWS*DM/4/256, 256>>>(nullptr);
    gemm_mma<0><<<gg, 256>>>(out);
}

// round 4
// speedup vs baseline: 3.0467x; 1.6682x over previous
#include <cuda_runtime.h>
#include <cuda_bf16.h>
#include <math.h>
#include <stdint.h>

#define BATCH 2
#define SEQ 2048
#define DM 2048
#define NH 16
#define DH 128
#define MROWS (BATCH*SEQ)   // 4096
#define HALF (DH/2)         // 64

// ---------------------------------------------------------------------------
// Scratch (__device__ globals; allocation-free rule)
// ---------------------------------------------------------------------------
__device__ float g_Q[BATCH*NH*SEQ*DH];
__device__ float g_K[BATCH*NH*SEQ*DH];
__device__ float g_V[BATCH*NH*SEQ*DH];
__device__ float g_Hb[BATCH*SEQ*DM];
__device__ float2 g_rope[SEQ*HALF];
// 2-way bf16 split planes (a = a0 + a1, residual ~2^-18)
__device__ __nv_bfloat16 g_xs[2][MROWS*DM];
__device__ __nv_bfloat16 g_hs[2][MROWS*DM];
__device__ __nv_bfloat16 g_ws[4][2][DM*DM];

// ---------------------------------------------------------------------------
// RoPE table (fp64-accurate angles, matching reference bit patterns)
// ---------------------------------------------------------------------------
__global__ void rope_table_kernel(const int* __restrict__ pos) {
    int s = blockIdx.x;
    int i = threadIdx.x;
    double inv = exp(-((double)(2 * i) / (double)DH) * log(10000.0));
    float invf = (float)inv;
    float freq = (float)pos[s] * invf;
    double a = (double)freq;
    g_rope[s * HALF + i] = make_float2((float)cos(a), (float)sin(a));
}

// ---------------------------------------------------------------------------
// 2-way bf16 split: a ≈ b0 + b1
// TGT: 0=x->g_xs, 1..4=w->g_ws[TGT-1], 5=g_Hb->g_hs
// ---------------------------------------------------------------------------
template<int TGT>
__global__ void split2_kernel(const float* __restrict__ srcp) {
    const int n4 = (TGT == 0 || TGT == 5) ? (MROWS * DM / 4) : (DM * DM / 4);
    int i = blockIdx.x * 256 + threadIdx.x;
    if (i >= n4) return;
    const float* src = (TGT == 5) ? (const float*)g_Hb : srcp;
    __nv_bfloat16* p0;
    __nv_bfloat16* p1;
    if (TGT == 0)      { p0 = g_xs[0]; p1 = g_xs[1]; }
    else if (TGT == 5) { p0 = g_hs[0]; p1 = g_hs[1]; }
    else               { p0 = g_ws[TGT-1][0]; p1 = g_ws[TGT-1][1]; }

    float4 a = ((const float4*)src)[i];
    float x[4] = {a.x, a.y, a.z, a.w};
    __nv_bfloat16 b0[4], b1[4];
    #pragma unroll
    for (int k = 0; k < 4; k++) {
        b0[k] = __float2bfloat16(x[k]);
        float r = x[k] - __bfloat162float(b0[k]);
        b1[k] = __float2bfloat16(r);
    }
    __nv_bfloat162* q0 = (__nv_bfloat162*)p0;
    __nv_bfloat162* q1 = (__nv_bfloat162*)p1;
    __nv_bfloat162 t;
    t.x = b0[0]; t.y = b0[1]; q0[i*2]   = t;
    t.x = b0[2]; t.y = b0[3]; q0[i*2+1] = t;
    t.x = b1[0]; t.y = b1[1]; q1[i*2]   = t;
    t.x = b1[2]; t.y = b1[3]; q1[i*2+1] = t;
}

// ---------------------------------------------------------------------------
// mma.sync bf16 GEMM, fp32 emulation (3 cross-terms of 2-way split).
// ldmatrix fragment loads + cp.async 2-stage pipeline.
// CTA tile 128x128, BK=32, 8 warps (warp tile 64x32).
// MODE 1 (QKV fused): blockIdx.z = 0/1/2 -> g_Q(+RoPE)/g_K(+RoPE)/g_V
// MODE 0 (O-proj):    Out row-major
// ---------------------------------------------------------------------------
#define BK 32
#define NKB (DM/BK)  // 64
#define TSTR 40      // smem row stride in bf16 (80B)
#define GEMM_SMEM (2*4*128*TSTR*2)   // 81920 B

__device__ __forceinline__ void mma16816(float* d, const uint32_t* a,
                                         const uint32_t* b) {
    asm volatile(
        "mma.sync.aligned.m16n8k16.row.col.f32.bf16.bf16.f32 "
        "{%0,%1,%2,%3}, {%4,%5,%6,%7}, {%8,%9}, {%0,%1,%2,%3};\n"
        : "+f"(d[0]), "+f"(d[1]), "+f"(d[2]), "+f"(d[3])
        : "r"(a[0]), "r"(a[1]), "r"(a[2]), "r"(a[3]), "r"(b[0]), "r"(b[1]));
}
#define LDSM_X4(r0, r1, r2, r3, addr) \
    asm volatile("ldmatrix.sync.aligned.m8n8.x4.shared.b16 {%0,%1,%2,%3}, [%4];" \
        : "=r"(r0), "=r"(r1), "=r"(r2), "=r"(r3) : "r"(addr))
#define CP_ASYNC16(dst, src) \
    asm volatile("cp.async.cg.shared.global [%0], [%1], 16;" :: "r"(dst), "l"(src))
#define CP_COMMIT() asm volatile("cp.async.commit_group;" ::: "memory")
#define CP_WAIT1()  asm volatile("cp.async.wait_group 1;" ::: "memory")

__device__ __forceinline__ uint32_t smem_u32(const void* p) {
    uint32_t a;
    asm("{ .reg .u64 t; cvta.to.shared.u64 t, %1; cvt.u32.u64 %0, t; }"
        : "=r"(a) : "l"(p));
    return a;
}

template<int MODE>
__global__ void __launch_bounds__(256, 1) gemm_mma(float* __restrict__ Out) {
    extern __shared__ __align__(128) __nv_bfloat16 dsm[];
    uint32_t sbase = smem_u32(dsm);

    int tid = threadIdx.x;
    int lane = tid & 31;
    int wid = tid >> 5;
    int m0 = blockIdx.y * 128;
    int n0 = blockIdx.x * 128;
    int z = (MODE == 1) ? blockIdx.z : 3;
    int wm = (wid & 1) * 64;
    int wn = (wid >> 1) * 32;
    int gr = lane >> 2;   // 0..7
    int gq = lane & 3;    // 0..3
    int lq = lane & 7;
    int quad = lane >> 3;

    const __nv_bfloat16* srcs[4];
    srcs[0] = ((MODE == 0) ? g_hs[0] : g_xs[0]) + (size_t)m0 * DM;
    srcs[1] = ((MODE == 0) ? g_hs[1] : g_xs[1]) + (size_t)m0 * DM;
    srcs[2] = g_ws[z][0] + (size_t)n0 * DM;
    srcs[3] = g_ws[z][1] + (size_t)n0 * DM;

    // stage loader: 2048 16B-chunks over 256 threads = 8 each
    #define LOAD_STAGE(kb, st) { \
        int k0 = (kb) * BK; \
        _Pragma("unroll") \
        for (int it = 0; it < 8; it++) { \
            int e = tid + it * 256; \
            int t = e >> 9; \
            int e5 = e & 511; \
            int r = e5 >> 2; \
            int c = (e5 & 3) * 8; \
            const __nv_bfloat16* src = srcs[t] + (size_t)r * DM + k0 + c; \
            uint32_t dst = sbase + ((((st) * 4 + t) * 128 + r) * TSTR + c) * 2; \
            CP_ASYNC16(dst, src); \
        } }

    LOAD_STAGE(0, 0) CP_COMMIT();
    LOAD_STAGE(1, 1) CP_COMMIT();

    float acc[4][4][4] = {};

    for (int kb = 0; kb < NKB; kb++) {
        int st = kb & 1;
        CP_WAIT1();
        __syncthreads();

        uint32_t ab[2], bb[2];
        ab[0] = sbase + ((st * 4 + 0) * 128) * TSTR * 2;
        ab[1] = sbase + ((st * 4 + 1) * 128) * TSTR * 2;
        bb[0] = sbase + ((st * 4 + 2) * 128) * TSTR * 2;
        bb[1] = sbase + ((st * 4 + 3) * 128) * TSTR * 2;

        #pragma unroll
        for (int ks = 0; ks < BK; ks += 16) {
            // A fragments: 4 m16 tiles x 2 planes, one ldmatrix.x4 each
            int arow = lq + (quad & 1) * 8;         // within m16 tile
            int acol = ks + (quad >> 1) * 8;
            uint32_t af[2][4][4];
            #pragma unroll
            for (int p = 0; p < 2; p++) {
                #pragma unroll
                for (int i = 0; i < 4; i++) {
                    uint32_t ad = ab[p] + ((wm + i * 16 + arow) * TSTR + acol) * 2;
                    LDSM_X4(af[p][i][0], af[p][i][1], af[p][i][2], af[p][i][3], ad);
                }
            }
            // B fragments: 4 n8 tiles x 2 planes, one x4 covers two n8 tiles
            int brow = lq + (quad >> 1) * 8;
            int bcol = ks + (quad & 1) * 8;
            uint32_t bf[2][4][2];
            #pragma unroll
            for (int p = 0; p < 2; p++) {
                #pragma unroll
                for (int j = 0; j < 4; j += 2) {
                    uint32_t bd = bb[p] + ((wn + j * 8 + brow) * TSTR + bcol) * 2;
                    LDSM_X4(bf[p][j][0], bf[p][j][1], bf[p][j+1][0], bf[p][j+1][1], bd);
                }
            }
            #pragma unroll
            for (int i = 0; i < 4; i++) {
                #pragma unroll
                for (int j = 0; j < 4; j++) {
                    mma16816(acc[i][j], af[0][i], bf[0][j]);  // a0*b0
                    mma16816(acc[i][j], af[0][i], bf[1][j]);  // a0*b1
                    mma16816(acc[i][j], af[1][i], bf[0][j]);  // a1*b0
                }
            }
        }
        __syncthreads();
        if (kb + 2 < NKB) { LOAD_STAGE(kb + 2, st) }
        CP_COMMIT();
    }
    #undef LOAD_STAGE

    // Epilogue from registers. c0,c1 = (row,col),(row,col+1); c2,c3 = row+8.
    int h = blockIdx.x;   // BN == DH
    #pragma unroll
    for (int i = 0; i < 4; i++) {
        #pragma unroll
        for (int half = 0; half < 2; half++) {
            int row = m0 + wm + i * 16 + gr + half * 8;
            int s = row & (SEQ - 1);
            int b = row >> 11;
            #pragma unroll
            for (int j = 0; j < 4; j++) {
                int d = wn + j * 8 + gq * 2;
                float e = acc[i][j][half * 2 + 0];
                float o = acc[i][j][half * 2 + 1];
                if (MODE == 0) {
                    *(float2*)(Out + (size_t)row * DM + n0 + d) =
                        make_float2(e, o);
                } else {
                    float* tgt = (z == 0) ? g_Q : (z == 1) ? g_K : g_V;
                    float* dst = tgt + ((size_t)(b * NH + h) * SEQ + s) * DH;
                    if (z == 2) {
                        *(float2*)(dst + d) = make_float2(e, o);
                    } else {
                        float2 cs = g_rope[s * HALF + (d >> 1)];
                        *(float2*)(dst + d) = make_float2(e * cs.x - o * cs.y,
                                                          e * cs.y + o * cs.x);
                    }
                }
            }
        }
    }
}

// ---------------------------------------------------------------------------
// Fused causal attention (unchanged — fp32 flash)
// ---------------------------------------------------------------------------
#define QSTR 132
#define SSTR 68
#define FLASH_SMEM ((3*64*QSTR + 64*SSTR + 3*64) * 4)

__global__ void __launch_bounds__(256) flash_kernel() {
    extern __shared__ float smf[];
    float (*Qs)[QSTR] = (float(*)[QSTR])smf;
    float (*Ks)[QSTR] = (float(*)[QSTR])(smf + 64 * QSTR);
    float (*Vs)[QSTR] = (float(*)[QSTR])(smf + 2 * 64 * QSTR);
    float (*Ss)[SSTR] = (float(*)[SSTR])(smf + 3 * 64 * QSTR);
    float* mrow = smf + 3 * 64 * QSTR + 64 * SSTR;
    float* lrow = mrow + 64;
    float* crow = lrow + 64;

    int bh = blockIdx.y;
    int qt = blockIdx.x;
    int tid = threadIdx.x;
    int tx = tid & 15;
    int ty = tid >> 4;

    const float* Qp = g_Q + (bh * SEQ + qt * 64) * DH;
    const float* Kp = g_K + bh * SEQ * DH;
    const float* Vp = g_V + bh * SEQ * DH;

    #pragma unroll
    for (int rep = 0; rep < 8; rep++) {
        int e = tid + rep * 256;
        int r = e >> 5;
        int c4 = (e & 31) * 4;
        float4 v = *(const float4*)(Qp + r * DH + c4);
        Qs[r][c4 + 0] = v.x; Qs[r][c4 + 1] = v.y;
        Qs[r][c4 + 2] = v.z; Qs[r][c4 + 3] = v.w;
    }
    if (tid < 64) { mrow[tid] = -INFINITY; lrow[tid] = 0.f; }

    float acc[4][8] = {};
    const float scale = 0.08838834764831845f;

    for (int kt = 0; kt <= qt; kt++) {
        __syncthreads();
        #pragma unroll
        for (int rep = 0; rep < 8; rep++) {
            int e = tid + rep * 256;
            int r = e >> 5;
            int c4 = (e & 31) * 4;
            float4 vk = *(const float4*)(Kp + (kt * 64 + r) * DH + c4);
            Ks[r][c4 + 0] = vk.x; Ks[r][c4 + 1] = vk.y;
            Ks[r][c4 + 2] = vk.z; Ks[r][c4 + 3] = vk.w;
            float4 vv = *(const float4*)(Vp + (kt * 64 + r) * DH + c4);
            Vs[r][c4 + 0] = vv.x; Vs[r][c4 + 1] = vv.y;
            Vs[r][c4 + 2] = vv.z; Vs[r][c4 + 3] = vv.w;
        }
        __syncthreads();

        float sc[4][4] = {};
        #pragma unroll 4
        for (int k = 0; k < DH; k += 4) {
            float4 q4[4], k4[4];
            #pragma unroll
            for (int i = 0; i < 4; i++) q4[i] = *(const float4*)&Qs[ty * 4 + i][k];
            #pragma unroll
            for (int j = 0; j < 4; j++) k4[j] = *(const float4*)&Ks[tx * 4 + j][k];
            #pragma unroll
            for (int i = 0; i < 4; i++) {
                #pragma unroll
                for (int j = 0; j < 4; j++) {
                    sc[i][j] += q4[i].x * k4[j].x;
                    sc[i][j] += q4[i].y * k4[j].y;
                    sc[i][j] += q4[i].z * k4[j].z;
                    sc[i][j] += q4[i].w * k4[j].w;
                }
            }
        }
        bool diag = (kt == qt);
        #pragma unroll
        for (int i = 0; i < 4; i++) {
            int r = ty * 4 + i;
            #pragma unroll
            for (int j = 0; j < 4; j++) {
                int c = tx * 4 + j;
                float v = sc[i][j] * scale;
                if (diag && c > r) v = -INFINITY;
                Ss[r][c] = v;
            }
        }
        __syncthreads();

        {
            int row = tid >> 2;
            int l4 = tid & 3;
            float* srow = Ss[row];
            float mt = -INFINITY;
            #pragma unroll
            for (int j = 0; j < 16; j++) mt = fmaxf(mt, srow[l4 * 16 + j]);
            mt = fmaxf(mt, __shfl_xor_sync(0xffffffffu, mt, 1));
            mt = fmaxf(mt, __shfl_xor_sync(0xffffffffu, mt, 2));
            float mold = mrow[row];
            float mnew = fmaxf(mold, mt);
            float lt = 0.f;
            #pragma unroll
            for (int j = 0; j < 16; j++) {
                float p = expf(srow[l4 * 16 + j] - mnew);
                srow[l4 * 16 + j] = p;
                lt += p;
            }
            lt += __shfl_xor_sync(0xffffffffu, lt, 1);
            lt += __shfl_xor_sync(0xffffffffu, lt, 2);
            if (l4 == 0) {
                float corr = expf(mold - mnew);
                crow[row] = corr;
                lrow[row] = lrow[row] * corr + lt;
                mrow[row] = mnew;
            }
        }
        __syncthreads();

        float cr[4];
        #pragma unroll
        for (int i = 0; i < 4; i++) {
            cr[i] = crow[ty * 4 + i];
            #pragma unroll
            for (int c = 0; c < 8; c++) acc[i][c] *= cr[i];
        }
        #pragma unroll 2
        for (int j = 0; j < 64; j++) {
            float4 v0 = *(const float4*)&Vs[j][tx * 8];
            float4 v1 = *(const float4*)&Vs[j][tx * 8 + 4];
            #pragma unroll
            for (int i = 0; i < 4; i++) {
                float p = Ss[ty * 4 + i][j];
                acc[i][0] += p * v0.x; acc[i][1] += p * v0.y;
                acc[i][2] += p * v0.z; acc[i][3] += p * v0.w;
                acc[i][4] += p * v1.x; acc[i][5] += p * v1.y;
                acc[i][6] += p * v1.z; acc[i][7] += p * v1.w;
            }
        }
    }

    int b = bh >> 4;
    int h = bh & (NH - 1);
    #pragma unroll
    for (int i = 0; i < 4; i++) {
        int r = ty * 4 + i;
        int s = qt * 64 + r;
        float linv = 1.f / lrow[r];
        float* dst = g_Hb + (b * SEQ + s) * DM + h * DH + tx * 8;
        #pragma unroll
        for (int c = 0; c < 8; c++) dst[c] = acc[i][c] * linv;
    }
}

// ---------------------------------------------------------------------------
extern "C" void kernel_launch(void* const* d_in, const int* in_sizes, int n_in,
                              void* d_out, int out_size) {
    const float* x  = (const float*)d_in[0];
    const float* wq = (const float*)d_in[1];
    const float* wk = (const float*)d_in[2];
    const float* wv = (const float*)d_in[3];
    const float* wo = (const float*)d_in[4];
    const int* tok  = (const int*)d_in[5];
    float* out = (float*)d_out;

    cudaFuncSetAttribute(flash_kernel,
                         cudaFuncAttributeMaxDynamicSharedMemorySize, FLASH_SMEM);
    cudaFuncSetAttribute(gemm_mma<0>,
                         cudaFuncAttributeMaxDynamicSharedMemorySize, GEMM_SMEM);
    cudaFuncSetAttribute(gemm_mma<1>,
                         cudaFuncAttributeMaxDynamicSharedMemorySize, GEMM_SMEM);

    rope_table_kernel<<<SEQ, HALF>>>(tok);
    split2_kernel<0><<<MROWS*DM/4/256, 256>>>(x);
    split2_kernel<1><<<DM*DM/4/256, 256>>>(wq);
    split2_kernel<2><<<DM*DM/4/256, 256>>>(wk);
    split2_kernel<3><<<DM*DM/4/256, 256>>>(wv);
    split2_kernel<4><<<DM*DM/4/256, 256>>>(wv == wk ? wv : wo);  // wo

    dim3 gq(DM / 128, MROWS / 128, 3);   // fused QKV
    gemm_mma<1><<<gq, 256, GEMM_SMEM>>>(nullptr);

    dim3 fgrid(SEQ / 64, BATCH * NH);
    flash_kernel<<<fgrid, 256, FLASH_SMEM>>>();

    split2_kernel<5><<<MROWS*DM/4/256, 256>>>(nullptr);
    dim3 go(DM / 128, MROWS / 128);
    gemm_mma<0><<<go, 256, GEMM_SMEM>>>(out);
}

// round 5
// speedup vs baseline: 5.9023x; 1.9373x over previous
#include <cuda_runtime.h>
#include <cuda_bf16.h>
#include <math.h>
#include <stdint.h>

#define BATCH 2
#define SEQ 2048
#define DM 2048
#define NH 16
#define DH 128
#define MROWS (BATCH*SEQ)   // 4096
#define HALF (DH/2)         // 64

// ---------------------------------------------------------------------------
// Scratch (__device__ globals; allocation-free rule)
// ---------------------------------------------------------------------------
__device__ float2 g_rope[SEQ*HALF];
__device__ __nv_bfloat16 g_xs[2][MROWS*DM];          // x split planes
__device__ __nv_bfloat16 g_hs[2][MROWS*DM];          // attention-out split planes
__device__ __nv_bfloat16 g_ws[4][2][DM*DM];          // wq,wk,wv,wo split planes
__device__ __nv_bfloat16 g_qs[2][BATCH*NH*SEQ*DH];   // Q (post-RoPE) split planes
__device__ __nv_bfloat16 g_ks[2][BATCH*NH*SEQ*DH];
__device__ __nv_bfloat16 g_vs[2][BATCH*NH*SEQ*DH];

// ---------------------------------------------------------------------------
// Helpers
// ---------------------------------------------------------------------------
__device__ __forceinline__ uint32_t smem_u32(const void* p) {
    uint32_t a;
    asm("{ .reg .u64 t; cvta.to.shared.u64 t, %1; cvt.u32.u64 %0, t; }"
        : "=r"(a) : "l"(p));
    return a;
}
__device__ __forceinline__ void mma16816(float* d, const uint32_t* a,
                                         const uint32_t* b) {
    asm volatile(
        "mma.sync.aligned.m16n8k16.row.col.f32.bf16.bf16.f32 "
        "{%0,%1,%2,%3}, {%4,%5,%6,%7}, {%8,%9}, {%0,%1,%2,%3};\n"
        : "+f"(d[0]), "+f"(d[1]), "+f"(d[2]), "+f"(d[3])
        : "r"(a[0]), "r"(a[1]), "r"(a[2]), "r"(a[3]), "r"(b[0]), "r"(b[1]));
}
#define LDSM_X4(r0, r1, r2, r3, addr) \
    asm volatile("ldmatrix.sync.aligned.m8n8.x4.shared.b16 {%0,%1,%2,%3}, [%4];" \
        : "=r"(r0), "=r"(r1), "=r"(r2), "=r"(r3) : "r"(addr))
#define LDSM_X4_T(r0, r1, r2, r3, addr) \
    asm volatile("ldmatrix.sync.aligned.m8n8.x4.trans.shared.b16 {%0,%1,%2,%3}, [%4];" \
        : "=r"(r0), "=r"(r1), "=r"(r2), "=r"(r3) : "r"(addr))
#define CP_ASYNC16(dst, src) \
    asm volatile("cp.async.cg.shared.global [%0], [%1], 16;" :: "r"(dst), "l"(src))
#define CP_COMMIT() asm volatile("cp.async.commit_group;" ::: "memory")
#define CP_WAIT1()  asm volatile("cp.async.wait_group 1;" ::: "memory")

// split x,y to bf16 hi-planes (m0) and residual planes (m1), packed as b16x2
__device__ __forceinline__ void split_pack(float x, float y,
                                           uint32_t& m0, uint32_t& m1) {
    __nv_bfloat16 x0 = __float2bfloat16_rn(x);
    __nv_bfloat16 y0 = __float2bfloat16_rn(y);
    __nv_bfloat16 x1 = __float2bfloat16_rn(x - __bfloat162float(x0));
    __nv_bfloat16 y1 = __float2bfloat16_rn(y - __bfloat162float(y0));
    __nv_bfloat162 a = {x0, y0};
    __nv_bfloat162 b = {x1, y1};
    m0 = *(uint32_t*)&a;
    m1 = *(uint32_t*)&b;
}

// ---------------------------------------------------------------------------
// RoPE table (fp64-accurate angles, matching reference bit patterns)
// ---------------------------------------------------------------------------
__global__ void rope_table_kernel(const int* __restrict__ pos) {
    int s = blockIdx.x;
    int i = threadIdx.x;
    double inv = exp(-((double)(2 * i) / (double)DH) * log(10000.0));
    float invf = (float)inv;
    float freq = (float)pos[s] * invf;
    double a = (double)freq;
    g_rope[s * HALF + i] = make_float2((float)cos(a), (float)sin(a));
}

// ---------------------------------------------------------------------------
// 2-way bf16 split. TGT: 0=x->g_xs, 1..4=w->g_ws[TGT-1]
// ---------------------------------------------------------------------------
template<int TGT>
__global__ void split2_kernel(const float* __restrict__ src) {
    const int n4 = (TGT == 0) ? (MROWS * DM / 4) : (DM * DM / 4);
    int i = blockIdx.x * 256 + threadIdx.x;
    if (i >= n4) return;
    __nv_bfloat16* p0;
    __nv_bfloat16* p1;
    if (TGT == 0) { p0 = g_xs[0]; p1 = g_xs[1]; }
    else          { p0 = g_ws[TGT-1][0]; p1 = g_ws[TGT-1][1]; }

    float4 a = ((const float4*)src)[i];
    uint32_t u0a, u1a, u0b, u1b;
    split_pack(a.x, a.y, u0a, u1a);
    split_pack(a.z, a.w, u0b, u1b);
    ((uint32_t*)p0)[i*2]   = u0a;
    ((uint32_t*)p0)[i*2+1] = u0b;
    ((uint32_t*)p1)[i*2]   = u1a;
    ((uint32_t*)p1)[i*2+1] = u1b;
}

// ---------------------------------------------------------------------------
// mma.sync bf16 GEMM, fp32 emulation (3 cross-terms of 2-way split).
// MODE 1 (QKV fused): z=0/1/2 -> g_qs(+RoPE)/g_ks(+RoPE)/g_vs split planes
// MODE 0 (O-proj):    Out row-major fp32
// ---------------------------------------------------------------------------
#define BK 32
#define NKB (DM/BK)  // 64
#define TSTR 40      // smem row stride in bf16 (80B)
#define GEMM_SMEM (2*4*128*TSTR*2)   // 81920 B

template<int MODE>
__global__ void __launch_bounds__(256, 1) gemm_mma(float* __restrict__ Out) {
    extern __shared__ __align__(128) __nv_bfloat16 dsm[];
    uint32_t sbase = smem_u32(dsm);

    int tid = threadIdx.x;
    int lane = tid & 31;
    int wid = tid >> 5;
    int m0 = blockIdx.y * 128;
    int n0 = blockIdx.x * 128;
    int z = (MODE == 1) ? blockIdx.z : 3;
    int wm = (wid & 1) * 64;
    int wn = (wid >> 1) * 32;
    int gr = lane >> 2;
    int gq = lane & 3;
    int lq = lane & 7;
    int quad = lane >> 3;

    const __nv_bfloat16* srcs[4];
    srcs[0] = ((MODE == 0) ? g_hs[0] : g_xs[0]) + (size_t)m0 * DM;
    srcs[1] = ((MODE == 0) ? g_hs[1] : g_xs[1]) + (size_t)m0 * DM;
    srcs[2] = g_ws[z][0] + (size_t)n0 * DM;
    srcs[3] = g_ws[z][1] + (size_t)n0 * DM;

    #define LOAD_STAGE(kb, st) { \
        int k0 = (kb) * BK; \
        _Pragma("unroll") \
        for (int it = 0; it < 8; it++) { \
            int e = tid + it * 256; \
            int t = e >> 9; \
            int e5 = e & 511; \
            int r = e5 >> 2; \
            int c = (e5 & 3) * 8; \
            const __nv_bfloat16* src = srcs[t] + (size_t)r * DM + k0 + c; \
            uint32_t dst = sbase + ((((st) * 4 + t) * 128 + r) * TSTR + c) * 2; \
            CP_ASYNC16(dst, src); \
        } }

    LOAD_STAGE(0, 0) CP_COMMIT();
    LOAD_STAGE(1, 1) CP_COMMIT();

    float acc[4][4][4] = {};

    for (int kb = 0; kb < NKB; kb++) {
        int st = kb & 1;
        CP_WAIT1();
        __syncthreads();

        uint32_t ab[2], bb[2];
        ab[0] = sbase + ((st * 4 + 0) * 128) * TSTR * 2;
        ab[1] = sbase + ((st * 4 + 1) * 128) * TSTR * 2;
        bb[0] = sbase + ((st * 4 + 2) * 128) * TSTR * 2;
        bb[1] = sbase + ((st * 4 + 3) * 128) * TSTR * 2;

        #pragma unroll
        for (int ks = 0; ks < BK; ks += 16) {
            int arow = lq + (quad & 1) * 8;
            int acol = ks + (quad >> 1) * 8;
            uint32_t af[2][4][4];
            #pragma unroll
            for (int p = 0; p < 2; p++) {
                #pragma unroll
                for (int i = 0; i < 4; i++) {
                    uint32_t ad = ab[p] + ((wm + i * 16 + arow) * TSTR + acol) * 2;
                    LDSM_X4(af[p][i][0], af[p][i][1], af[p][i][2], af[p][i][3], ad);
                }
            }
            int brow = lq + (quad >> 1) * 8;
            int bcol = ks + (quad & 1) * 8;
            uint32_t bf[2][4][2];
            #pragma unroll
            for (int p = 0; p < 2; p++) {
                #pragma unroll
                for (int j = 0; j < 4; j += 2) {
                    uint32_t bd = bb[p] + ((wn + j * 8 + brow) * TSTR + bcol) * 2;
                    LDSM_X4(bf[p][j][0], bf[p][j][1], bf[p][j+1][0], bf[p][j+1][1], bd);
                }
            }
            #pragma unroll
            for (int i = 0; i < 4; i++) {
                #pragma unroll
                for (int j = 0; j < 4; j++) {
                    mma16816(acc[i][j], af[0][i], bf[0][j]);
                    mma16816(acc[i][j], af[0][i], bf[1][j]);
                    mma16816(acc[i][j], af[1][i], bf[0][j]);
                }
            }
        }
        __syncthreads();
        if (kb + 2 < NKB) { LOAD_STAGE(kb + 2, st) }
        CP_COMMIT();
    }
    #undef LOAD_STAGE

    int h = blockIdx.x;   // BN == DH
    #pragma unroll
    for (int i = 0; i < 4; i++) {
        #pragma unroll
        for (int half = 0; half < 2; half++) {
            int row = m0 + wm + i * 16 + gr + half * 8;
            int s = row & (SEQ - 1);
            int b = row >> 11;
            #pragma unroll
            for (int j = 0; j < 4; j++) {
                int d = wn + j * 8 + gq * 2;
                float e = acc[i][j][half * 2 + 0];
                float o = acc[i][j][half * 2 + 1];
                if (MODE == 0) {
                    *(float2*)(Out + (size_t)row * DM + n0 + d) =
                        make_float2(e, o);
                } else {
                    if (z < 2) {
                        float2 cs = g_rope[s * HALF + (d >> 1)];
                        float e2 = e * cs.x - o * cs.y;
                        o = e * cs.y + o * cs.x;
                        e = e2;
                    }
                    __nv_bfloat16* t0 = (z == 0) ? g_qs[0] : (z == 1) ? g_ks[0] : g_vs[0];
                    __nv_bfloat16* t1 = (z == 0) ? g_qs[1] : (z == 1) ? g_ks[1] : g_vs[1];
                    size_t off = ((size_t)(b * NH + h) * SEQ + s) * DH + d;
                    uint32_t u0, u1;
                    split_pack(e, o, u0, u1);
                    *(uint32_t*)(t0 + off) = u0;
                    *(uint32_t*)(t1 + off) = u1;
                }
            }
        }
    }
}

// ---------------------------------------------------------------------------
// Tensor-core flash attention, fp32-emulated bf16 (3-term).
// Q tile 128 x KV tile 64, 8 warps (warp = 16 q-rows), cp.async 2-stage KV.
// Softmax in registers; P reused directly as A-fragments; V via ldmatrix.trans.
// Output written as bf16 split planes to g_hs.
// ---------------------------------------------------------------------------
#define TS 136   // smem row stride bf16 (272B)
#define FQ 128
#define FK 64
#define QOFF 0
#define KOFF (2*FQ*TS)             // 34816
#define VOFF (KOFF + 4*FK*TS)      // 69632
#define FLASH_SMEM ((VOFF + 4*FK*TS)*2)  // 208896 B

__global__ void __launch_bounds__(256, 1) flash_mma() {
    extern __shared__ __align__(16) __nv_bfloat16 fsm[];
    uint32_t sb = smem_u32(fsm);
    int tid = threadIdx.x;
    int lane = tid & 31;
    int w = tid >> 5;
    int gr = lane >> 2;
    int gq = lane & 3;
    int lq = lane & 7;
    int quad = lane >> 3;
    int bh = blockIdx.y;
    int qt = (int)gridDim.x - 1 - (int)blockIdx.x;   // heavy tiles first
    int nkv = 2 * qt + 2;

    const __nv_bfloat16* qsrc[2] = {
        g_qs[0] + ((size_t)bh * SEQ + qt * FQ) * DH,
        g_qs[1] + ((size_t)bh * SEQ + qt * FQ) * DH };
    const __nv_bfloat16* ksrc[2] = {
        g_ks[0] + (size_t)bh * SEQ * DH, g_ks[1] + (size_t)bh * SEQ * DH };
    const __nv_bfloat16* vsrc[2] = {
        g_vs[0] + (size_t)bh * SEQ * DH, g_vs[1] + (size_t)bh * SEQ * DH };

    #define LOADKV(kt_, st_) { \
        _Pragma("unroll") \
        for (int it = 0; it < 8; it++) { \
            int e = tid + it * 256; \
            int p = e >> 10; \
            int r = (e >> 4) & 63; \
            int c = (e & 15) * 8; \
            CP_ASYNC16(sb + (KOFF + ((st_) * 2 + p) * FK * TS + r * TS + c) * 2, \
                       ksrc[p] + ((size_t)(kt_) * FK + r) * DH + c); \
            CP_ASYNC16(sb + (VOFF + ((st_) * 2 + p) * FK * TS + r * TS + c) * 2, \
                       vsrc[p] + ((size_t)(kt_) * FK + r) * DH + c); \
        } }

    // Q load (16/thread) + KV stage 0, then KV stage 1
    #pragma unroll
    for (int it = 0; it < 16; it++) {
        int e = tid + it * 256;
        int p = e >> 11;
        int r = (e >> 4) & 127;
        int c = (e & 15) * 8;
        CP_ASYNC16(sb + (QOFF + p * FQ * TS + r * TS + c) * 2,
                   qsrc[p] + (size_t)r * DH + c);
    }
    LOADKV(0, 0)
    CP_COMMIT();
    LOADKV(1, 1)
    CP_COMMIT();

    float hacc[16][4] = {};
    float mrow0 = -INFINITY, mrow1 = -INFINITY;
    float lrow0 = 0.f, lrow1 = 0.f;
    const float scale = 0.08838834764831845f;   // 1/sqrt(128)

    int arow = lq + (quad & 1) * 8;
    int acolh = (quad >> 1) * 8;
    int brow = lq + (quad >> 1) * 8;
    int bcolh = (quad & 1) * 8;
    int qrow0 = qt * FQ + w * 16 + gr;

    for (int kt = 0; kt < nkv; kt++) {
        int st = kt & 1;
        CP_WAIT1();
        __syncthreads();

        // ---- S = Q K^T (emulated) ----
        float sacc[8][4] = {};
        uint32_t qb0 = sb + (QOFF + (w * 16 + arow) * TS) * 2;
        uint32_t qb1 = qb0 + (FQ * TS) * 2;
        uint32_t kb0 = sb + (KOFF + (st * 2 + 0) * FK * TS) * 2;
        uint32_t kb1 = sb + (KOFF + (st * 2 + 1) * FK * TS) * 2;
        #pragma unroll
        for (int t = 0; t < 8; t++) {
            uint32_t a0[4], a1[4];
            LDSM_X4(a0[0], a0[1], a0[2], a0[3], qb0 + (16 * t + acolh) * 2);
            LDSM_X4(a1[0], a1[1], a1[2], a1[3], qb1 + (16 * t + acolh) * 2);
            uint32_t b0[8][2], b1[8][2];
            #pragma unroll
            for (int j = 0; j < 8; j += 2) {
                LDSM_X4(b0[j][0], b0[j][1], b0[j+1][0], b0[j+1][1],
                        kb0 + ((j * 8 + brow) * TS + 16 * t + bcolh) * 2);
                LDSM_X4(b1[j][0], b1[j][1], b1[j+1][0], b1[j+1][1],
                        kb1 + ((j * 8 + brow) * TS + 16 * t + bcolh) * 2);
            }
            #pragma unroll
            for (int j = 0; j < 8; j++) {
                mma16816(sacc[j], a0, b0[j]);
                mma16816(sacc[j], a0, b1[j]);
                mma16816(sacc[j], a1, b0[j]);
            }
        }

        // ---- scale + causal mask + row max ----
        bool maskblk = (kt >= 2 * qt);
        float mx0 = mrow0, mx1 = mrow1;
        #pragma unroll
        for (int j = 0; j < 8; j++) {
            int col = kt * FK + j * 8 + gq * 2;
            #pragma unroll
            for (int e = 0; e < 4; e++) {
                float v = sacc[j][e] * scale;
                if (maskblk) {
                    int cc = col + (e & 1);
                    int rr = qrow0 + (e >> 1) * 8;
                    if (cc > rr) v = -1e30f;
                }
                sacc[j][e] = v;
                if (e < 2) mx0 = fmaxf(mx0, v);
                else       mx1 = fmaxf(mx1, v);
            }
        }
        mx0 = fmaxf(mx0, __shfl_xor_sync(0xffffffffu, mx0, 1));
        mx0 = fmaxf(mx0, __shfl_xor_sync(0xffffffffu, mx0, 2));
        mx1 = fmaxf(mx1, __shfl_xor_sync(0xffffffffu, mx1, 1));
        mx1 = fmaxf(mx1, __shfl_xor_sync(0xffffffffu, mx1, 2));
        float c0 = __expf(mrow0 - mx0);
        float c1 = __expf(mrow1 - mx1);
        mrow0 = mx0; mrow1 = mx1;
        #pragma unroll
        for (int j2 = 0; j2 < 16; j2++) {
            hacc[j2][0] *= c0; hacc[j2][1] *= c0;
            hacc[j2][2] *= c1; hacc[j2][3] *= c1;
        }

        // ---- P = exp(S-m), accumulate l, split+pack to A-fragments ----
        float lt0 = 0.f, lt1 = 0.f;
        uint32_t pa0[4][4], pa1[4][4];
        #pragma unroll
        for (int t = 0; t < 4; t++) {
            #pragma unroll
            for (int half = 0; half < 2; half++) {
                int j = 2 * t + half;
                float p0 = __expf(sacc[j][0] - mx0);
                float p1 = __expf(sacc[j][1] - mx0);
                float p2 = __expf(sacc[j][2] - mx1);
                float p3 = __expf(sacc[j][3] - mx1);
                lt0 += p0 + p1;
                lt1 += p2 + p3;
                split_pack(p0, p1, pa0[t][half*2+0], pa1[t][half*2+0]);
                split_pack(p2, p3, pa0[t][half*2+1], pa1[t][half*2+1]);
            }
        }
        lt0 += __shfl_xor_sync(0xffffffffu, lt0, 1);
        lt0 += __shfl_xor_sync(0xffffffffu, lt0, 2);
        lt1 += __shfl_xor_sync(0xffffffffu, lt1, 1);
        lt1 += __shfl_xor_sync(0xffffffffu, lt1, 2);
        lrow0 = lrow0 * c0 + lt0;
        lrow1 = lrow1 * c1 + lt1;

        // NOTE on fragment identity: sacc tile j (cols 8j..8j+7) regs map to
        // PV A-operand k16 tile t=j/2 exactly: a0={P[gr][16t+2gq..]},
        // a1={P[gr+8][..]}, a2/a3 same for cols +8 — done in the packing above.

        // ---- H += P V (emulated), V^T via ldmatrix.trans ----
        uint32_t vb0 = sb + (VOFF + (st * 2 + 0) * FK * TS) * 2;
        uint32_t vb1 = sb + (VOFF + (st * 2 + 1) * FK * TS) * 2;
        int vrow = lq + (quad & 1) * 8;
        int vcolh = (quad >> 1) * 8;
        #pragma unroll
        for (int t = 0; t < 4; t++) {
            #pragma unroll
            for (int j2 = 0; j2 < 16; j2 += 2) {
                uint32_t bv0[2][2], bv1[2][2];
                LDSM_X4_T(bv0[0][0], bv0[0][1], bv0[1][0], bv0[1][1],
                          vb0 + ((16 * t + vrow) * TS + 8 * j2 + vcolh) * 2);
                LDSM_X4_T(bv1[0][0], bv1[0][1], bv1[1][0], bv1[1][1],
                          vb1 + ((16 * t + vrow) * TS + 8 * j2 + vcolh) * 2);
                mma16816(hacc[j2],   pa0[t], bv0[0]);
                mma16816(hacc[j2],   pa0[t], bv1[0]);
                mma16816(hacc[j2],   pa1[t], bv0[0]);
                mma16816(hacc[j2+1], pa0[t], bv0[1]);
                mma16816(hacc[j2+1], pa0[t], bv1[1]);
                mma16816(hacc[j2+1], pa1[t], bv0[1]);
            }
        }

        __syncthreads();
        if (kt + 2 < nkv) { LOADKV(kt + 2, st) }
        CP_COMMIT();
    }
    #undef LOADKV

    // ---- epilogue: H/l -> bf16 split planes in g_hs ----
    float li0 = 1.f / lrow0;
    float li1 = 1.f / lrow1;
    int b = bh >> 4;
    int hd = bh & (NH - 1);
    int s0 = qt * FQ + w * 16 + gr;
    size_t base0 = ((size_t)(b * SEQ + s0)) * DM + hd * DH;
    size_t base1 = ((size_t)(b * SEQ + s0 + 8)) * DM + hd * DH;
    #pragma unroll
    for (int j2 = 0; j2 < 16; j2++) {
        int d = j2 * 8 + gq * 2;
        uint32_t u0, u1;
        split_pack(hacc[j2][0] * li0, hacc[j2][1] * li0, u0, u1);
        *(uint32_t*)(g_hs[0] + base0 + d) = u0;
        *(uint32_t*)(g_hs[1] + base0 + d) = u1;
        split_pack(hacc[j2][2] * li1, hacc[j2][3] * li1, u0, u1);
        *(uint32_t*)(g_hs[0] + base1 + d) = u0;
        *(uint32_t*)(g_hs[1] + base1 + d) = u1;
    }
}

// ---------------------------------------------------------------------------
extern "C" void kernel_launch(void* const* d_in, const int* in_sizes, int n_in,
                              void* d_out, int out_size) {
    const float* x  = (const float*)d_in[0];
    const float* wq = (const float*)d_in[1];
    const float* wk = (const float*)d_in[2];
    const float* wv = (const float*)d_in[3];
    const float* wo = (const float*)d_in[4];
    const int* tok  = (const int*)d_in[5];
    float* out = (float*)d_out;

    cudaFuncSetAttribute(gemm_mma<0>,
                         cudaFuncAttributeMaxDynamicSharedMemorySize, GEMM_SMEM);
    cudaFuncSetAttribute(gemm_mma<1>,
                         cudaFuncAttributeMaxDynamicSharedMemorySize, GEMM_SMEM);
    cudaFuncSetAttribute(flash_mma,
                         cudaFuncAttributeMaxDynamicSharedMemorySize, FLASH_SMEM);

    rope_table_kernel<<<SEQ, HALF>>>(tok);
    split2_kernel<0><<<MROWS*DM/4/256, 256>>>(x);
    split2_kernel<1><<<DM*DM/4/256, 256>>>(wq);
    split2_kernel<2><<<DM*DM/4/256, 256>>>(wk);
    split2_kernel<3><<<DM*DM/4/256, 256>>>(wv);
    split2_kernel<4><<<DM*DM/4/256, 256>>>(wo);

    dim3 gq(DM / 128, MROWS / 128, 3);   // fused QKV
    gemm_mma<1><<<gq, 256, GEMM_SMEM>>>(nullptr);

    dim3 fgrid(SEQ / FQ, BATCH * NH);    // (16, 32)
    flash_mma<<<fgrid, 256, FLASH_SMEM>>>();

    dim3 go(DM / 128, MROWS / 128);
    gemm_mma<0><<<go, 256, GEMM_SMEM>>>(out);
}

// round 6
// speedup vs baseline: 6.6915x; 1.1337x over previous
#include <cuda_runtime.h>
#include <cuda_bf16.h>
#include <math.h>
#include <stdint.h>

#define BATCH 2
#define SEQ 2048
#define DM 2048
#define NH 16
#define DH 128
#define MROWS (BATCH*SEQ)   // 4096
#define HALF (DH/2)         // 64

// ---------------------------------------------------------------------------
// Scratch (__device__ globals; allocation-free rule)
// ---------------------------------------------------------------------------
__device__ float2 g_rope[SEQ*HALF];
__device__ __nv_bfloat16 g_xs[2][MROWS*DM];          // x split planes
__device__ __nv_bfloat16 g_hs[2][MROWS*DM];          // attention-out split planes
__device__ __nv_bfloat16 g_ws[4][2][DM*DM];          // wq,wk,wv,wo split planes
__device__ __nv_bfloat16 g_qs[2][BATCH*NH*SEQ*DH];   // Q (post-RoPE) split planes
__device__ __nv_bfloat16 g_ks[2][BATCH*NH*SEQ*DH];
__device__ __nv_bfloat16 g_vs[2][BATCH*NH*SEQ*DH];

// ---------------------------------------------------------------------------
// Helpers
// ---------------------------------------------------------------------------
__device__ __forceinline__ uint32_t smem_u32(const void* p) {
    uint32_t a;
    asm("{ .reg .u64 t; cvta.to.shared.u64 t, %1; cvt.u32.u64 %0, t; }"
        : "=r"(a) : "l"(p));
    return a;
}
__device__ __forceinline__ void mma16816(float* d, const uint32_t* a,
                                         const uint32_t* b) {
    asm volatile(
        "mma.sync.aligned.m16n8k16.row.col.f32.bf16.bf16.f32 "
        "{%0,%1,%2,%3}, {%4,%5,%6,%7}, {%8,%9}, {%0,%1,%2,%3};\n"
        : "+f"(d[0]), "+f"(d[1]), "+f"(d[2]), "+f"(d[3])
        : "r"(a[0]), "r"(a[1]), "r"(a[2]), "r"(a[3]), "r"(b[0]), "r"(b[1]));
}
#define LDSM_X4(r0, r1, r2, r3, addr) \
    asm volatile("ldmatrix.sync.aligned.m8n8.x4.shared.b16 {%0,%1,%2,%3}, [%4];" \
        : "=r"(r0), "=r"(r1), "=r"(r2), "=r"(r3) : "r"(addr))
#define LDSM_X4_T(r0, r1, r2, r3, addr) \
    asm volatile("ldmatrix.sync.aligned.m8n8.x4.trans.shared.b16 {%0,%1,%2,%3}, [%4];" \
        : "=r"(r0), "=r"(r1), "=r"(r2), "=r"(r3) : "r"(addr))
#define CP_ASYNC16(dst, src) \
    asm volatile("cp.async.cg.shared.global [%0], [%1], 16;" :: "r"(dst), "l"(src))
#define CP_COMMIT() asm volatile("cp.async.commit_group;" ::: "memory")
#define CP_WAIT1()  asm volatile("cp.async.wait_group 1;" ::: "memory")

// split x,y to bf16 hi-planes (m0) and residual planes (m1), packed as b16x2
__device__ __forceinline__ void split_pack(float x, float y,
                                           uint32_t& m0, uint32_t& m1) {
    __nv_bfloat16 x0 = __float2bfloat16_rn(x);
    __nv_bfloat16 y0 = __float2bfloat16_rn(y);
    __nv_bfloat16 x1 = __float2bfloat16_rn(x - __bfloat162float(x0));
    __nv_bfloat16 y1 = __float2bfloat16_rn(y - __bfloat162float(y0));
    __nv_bfloat162 a = {x0, y0};
    __nv_bfloat162 b = {x1, y1};
    m0 = *(uint32_t*)&a;
    m1 = *(uint32_t*)&b;
}

// ---------------------------------------------------------------------------
// RoPE table (fp64-accurate angles, matching reference bit patterns)
// ---------------------------------------------------------------------------
__global__ void rope_table_kernel(const int* __restrict__ pos) {
    int s = blockIdx.x;
    int i = threadIdx.x;
    double inv = exp(-((double)(2 * i) / (double)DH) * log(10000.0));
    float invf = (float)inv;
    float freq = (float)pos[s] * invf;
    double a = (double)freq;
    g_rope[s * HALF + i] = make_float2((float)cos(a), (float)sin(a));
}

// ---------------------------------------------------------------------------
// 2-way bf16 split. TGT: 0=x->g_xs, 1..4=w->g_ws[TGT-1]
// ---------------------------------------------------------------------------
template<int TGT>
__global__ void split2_kernel(const float* __restrict__ src) {
    const int n4 = (TGT == 0) ? (MROWS * DM / 4) : (DM * DM / 4);
    int i = blockIdx.x * 256 + threadIdx.x;
    if (i >= n4) return;
    __nv_bfloat16* p0;
    __nv_bfloat16* p1;
    if (TGT == 0) { p0 = g_xs[0]; p1 = g_xs[1]; }
    else          { p0 = g_ws[TGT-1][0]; p1 = g_ws[TGT-1][1]; }

    float4 a = ((const float4*)src)[i];
    uint32_t u0a, u1a, u0b, u1b;
    split_pack(a.x, a.y, u0a, u1a);
    split_pack(a.z, a.w, u0b, u1b);
    ((uint32_t*)p0)[i*2]   = u0a;
    ((uint32_t*)p0)[i*2+1] = u0b;
    ((uint32_t*)p1)[i*2]   = u1a;
    ((uint32_t*)p1)[i*2+1] = u1b;
}

// ---------------------------------------------------------------------------
// mma.sync bf16 GEMM, fp32 emulation (3 cross-terms of 2-way split).
// Low-register mainloop (target 2 CTAs/SM): A-frags resident, B-frags streamed.
// MODE 1 (QKV fused): z=0/1/2 -> g_qs(+RoPE)/g_ks(+RoPE)/g_vs split planes
// MODE 0 (O-proj):    Out row-major fp32
// ---------------------------------------------------------------------------
#define BK 32
#define NKB (DM/BK)  // 64
#define TSTR 40      // smem row stride in bf16 (80B)
#define GEMM_SMEM (2*4*128*TSTR*2)   // 81920 B

template<int MODE>
__global__ void __launch_bounds__(256, 2) gemm_mma(float* __restrict__ Out) {
    extern __shared__ __align__(128) __nv_bfloat16 dsm[];
    uint32_t sbase = smem_u32(dsm);

    int tid = threadIdx.x;
    int lane = tid & 31;
    int wid = tid >> 5;
    int m0 = blockIdx.y * 128;
    int n0 = blockIdx.x * 128;
    int z = (MODE == 1) ? blockIdx.z : 3;
    int wm = (wid & 1) * 64;
    int wn = (wid >> 1) * 32;
    int gr = lane >> 2;
    int gq = lane & 3;
    int lq = lane & 7;
    int quad = lane >> 3;

    const __nv_bfloat16* srcs[4];
    srcs[0] = ((MODE == 0) ? g_hs[0] : g_xs[0]) + (size_t)m0 * DM;
    srcs[1] = ((MODE == 0) ? g_hs[1] : g_xs[1]) + (size_t)m0 * DM;
    srcs[2] = g_ws[z][0] + (size_t)n0 * DM;
    srcs[3] = g_ws[z][1] + (size_t)n0 * DM;

    #define LOAD_STAGE(kb, st) { \
        int k0 = (kb) * BK; \
        _Pragma("unroll") \
        for (int it = 0; it < 8; it++) { \
            int e = tid + it * 256; \
            int t = e >> 9; \
            int e5 = e & 511; \
            int r = e5 >> 2; \
            int c = (e5 & 3) * 8; \
            const __nv_bfloat16* src = srcs[t] + (size_t)r * DM + k0 + c; \
            uint32_t dst = sbase + ((((st) * 4 + t) * 128 + r) * TSTR + c) * 2; \
            CP_ASYNC16(dst, src); \
        } }

    LOAD_STAGE(0, 0) CP_COMMIT();
    LOAD_STAGE(1, 1) CP_COMMIT();

    float acc[4][4][4] = {};

    int arow = lq + (quad & 1) * 8;
    int acolq = (quad >> 1) * 8;
    int brow = lq + (quad >> 1) * 8;
    int bcolq = (quad & 1) * 8;

    for (int kb = 0; kb < NKB; kb++) {
        int st = kb & 1;
        CP_WAIT1();
        __syncthreads();

        uint32_t ab0 = sbase + (((st * 4 + 0) * 128 + wm + arow) * TSTR) * 2;
        uint32_t ab1 = sbase + (((st * 4 + 1) * 128 + wm + arow) * TSTR) * 2;
        uint32_t bb0 = sbase + (((st * 4 + 2) * 128 + wn + brow) * TSTR) * 2;
        uint32_t bb1 = sbase + (((st * 4 + 3) * 128 + wn + brow) * TSTR) * 2;

        #pragma unroll
        for (int ks = 0; ks < BK; ks += 16) {
            // A fragments resident: 2 planes x 4 m16 tiles (32 regs)
            uint32_t af[2][4][4];
            #pragma unroll
            for (int i = 0; i < 4; i++) {
                LDSM_X4(af[0][i][0], af[0][i][1], af[0][i][2], af[0][i][3],
                        ab0 + (i * 16 * TSTR + ks + acolq) * 2);
                LDSM_X4(af[1][i][0], af[1][i][1], af[1][i][2], af[1][i][3],
                        ab1 + (i * 16 * TSTR + ks + acolq) * 2);
            }
            // B fragments streamed per j-pair (8 regs live)
            #pragma unroll
            for (int jj = 0; jj < 4; jj += 2) {
                uint32_t bf0[2][2], bf1[2][2];
                LDSM_X4(bf0[0][0], bf0[0][1], bf0[1][0], bf0[1][1],
                        bb0 + ((jj * 8) * TSTR + ks + bcolq) * 2);
                LDSM_X4(bf1[0][0], bf1[0][1], bf1[1][0], bf1[1][1],
                        bb1 + ((jj * 8) * TSTR + ks + bcolq) * 2);
                #pragma unroll
                for (int i = 0; i < 4; i++) {
                    mma16816(acc[i][jj],   af[0][i], bf0[0]);
                    mma16816(acc[i][jj],   af[0][i], bf1[0]);
                    mma16816(acc[i][jj],   af[1][i], bf0[0]);
                    mma16816(acc[i][jj+1], af[0][i], bf0[1]);
                    mma16816(acc[i][jj+1], af[0][i], bf1[1]);
                    mma16816(acc[i][jj+1], af[1][i], bf0[1]);
                }
            }
        }
        __syncthreads();
        if (kb + 2 < NKB) { LOAD_STAGE(kb + 2, st) }
        CP_COMMIT();
    }
    #undef LOAD_STAGE

    int h = blockIdx.x;   // BN == DH
    #pragma unroll
    for (int i = 0; i < 4; i++) {
        #pragma unroll
        for (int half = 0; half < 2; half++) {
            int row = m0 + wm + i * 16 + gr + half * 8;
            int s = row & (SEQ - 1);
            int b = row >> 11;
            #pragma unroll
            for (int j = 0; j < 4; j++) {
                int d = wn + j * 8 + gq * 2;
                float e = acc[i][j][half * 2 + 0];
                float o = acc[i][j][half * 2 + 1];
                if (MODE == 0) {
                    *(float2*)(Out + (size_t)row * DM + n0 + d) =
                        make_float2(e, o);
                } else {
                    if (z < 2) {
                        float2 cs = g_rope[s * HALF + (d >> 1)];
                        float e2 = e * cs.x - o * cs.y;
                        o = e * cs.y + o * cs.x;
                        e = e2;
                    }
                    __nv_bfloat16* t0 = (z == 0) ? g_qs[0] : (z == 1) ? g_ks[0] : g_vs[0];
                    __nv_bfloat16* t1 = (z == 0) ? g_qs[1] : (z == 1) ? g_ks[1] : g_vs[1];
                    size_t off = ((size_t)(b * NH + h) * SEQ + s) * DH + d;
                    uint32_t u0, u1;
                    split_pack(e, o, u0, u1);
                    *(uint32_t*)(t0 + off) = u0;
                    *(uint32_t*)(t1 + off) = u1;
                }
            }
        }
    }
}

// ---------------------------------------------------------------------------
// Tensor-core flash attention, fp32-emulated bf16 (3-term). Unchanged.
// ---------------------------------------------------------------------------
#define TS 136   // smem row stride bf16 (272B)
#define FQ 128
#define FK 64
#define QOFF 0
#define KOFF (2*FQ*TS)             // 34816
#define VOFF (KOFF + 4*FK*TS)      // 69632
#define FLASH_SMEM ((VOFF + 4*FK*TS)*2)  // 208896 B

__global__ void __launch_bounds__(256, 1) flash_mma() {
    extern __shared__ __align__(16) __nv_bfloat16 fsm[];
    uint32_t sb = smem_u32(fsm);
    int tid = threadIdx.x;
    int lane = tid & 31;
    int w = tid >> 5;
    int gr = lane >> 2;
    int gq = lane & 3;
    int lq = lane & 7;
    int quad = lane >> 3;
    int bh = blockIdx.y;
    int qt = (int)gridDim.x - 1 - (int)blockIdx.x;   // heavy tiles first
    int nkv = 2 * qt + 2;

    const __nv_bfloat16* qsrc[2] = {
        g_qs[0] + ((size_t)bh * SEQ + qt * FQ) * DH,
        g_qs[1] + ((size_t)bh * SEQ + qt * FQ) * DH };
    const __nv_bfloat16* ksrc[2] = {
        g_ks[0] + (size_t)bh * SEQ * DH, g_ks[1] + (size_t)bh * SEQ * DH };
    const __nv_bfloat16* vsrc[2] = {
        g_vs[0] + (size_t)bh * SEQ * DH, g_vs[1] + (size_t)bh * SEQ * DH };

    #define LOADKV(kt_, st_) { \
        _Pragma("unroll") \
        for (int it = 0; it < 8; it++) { \
            int e = tid + it * 256; \
            int p = e >> 10; \
            int r = (e >> 4) & 63; \
            int c = (e & 15) * 8; \
            CP_ASYNC16(sb + (KOFF + ((st_) * 2 + p) * FK * TS + r * TS + c) * 2, \
                       ksrc[p] + ((size_t)(kt_) * FK + r) * DH + c); \
            CP_ASYNC16(sb + (VOFF + ((st_) * 2 + p) * FK * TS + r * TS + c) * 2, \
                       vsrc[p] + ((size_t)(kt_) * FK + r) * DH + c); \
        } }

    #pragma unroll
    for (int it = 0; it < 16; it++) {
        int e = tid + it * 256;
        int p = e >> 11;
        int r = (e >> 4) & 127;
        int c = (e & 15) * 8;
        CP_ASYNC16(sb + (QOFF + p * FQ * TS + r * TS + c) * 2,
                   qsrc[p] + (size_t)r * DH + c);
    }
    LOADKV(0, 0)
    CP_COMMIT();
    LOADKV(1, 1)
    CP_COMMIT();

    float hacc[16][4] = {};
    float mrow0 = -INFINITY, mrow1 = -INFINITY;
    float lrow0 = 0.f, lrow1 = 0.f;
    const float scale = 0.08838834764831845f;   // 1/sqrt(128)

    int arow = lq + (quad & 1) * 8;
    int acolh = (quad >> 1) * 8;
    int brow = lq + (quad >> 1) * 8;
    int bcolh = (quad & 1) * 8;
    int qrow0 = qt * FQ + w * 16 + gr;

    for (int kt = 0; kt < nkv; kt++) {
        int st = kt & 1;
        CP_WAIT1();
        __syncthreads();

        // ---- S = Q K^T (emulated) ----
        float sacc[8][4] = {};
        uint32_t qb0 = sb + (QOFF + (w * 16 + arow) * TS) * 2;
        uint32_t qb1 = qb0 + (FQ * TS) * 2;
        uint32_t kb0 = sb + (KOFF + (st * 2 + 0) * FK * TS) * 2;
        uint32_t kb1 = sb + (KOFF + (st * 2 + 1) * FK * TS) * 2;
        #pragma unroll
        for (int t = 0; t < 8; t++) {
            uint32_t a0[4], a1[4];
            LDSM_X4(a0[0], a0[1], a0[2], a0[3], qb0 + (16 * t + acolh) * 2);
            LDSM_X4(a1[0], a1[1], a1[2], a1[3], qb1 + (16 * t + acolh) * 2);
            uint32_t b0[8][2], b1[8][2];
            #pragma unroll
            for (int j = 0; j < 8; j += 2) {
                LDSM_X4(b0[j][0], b0[j][1], b0[j+1][0], b0[j+1][1],
                        kb0 + ((j * 8 + brow) * TS + 16 * t + bcolh) * 2);
                LDSM_X4(b1[j][0], b1[j][1], b1[j+1][0], b1[j+1][1],
                        kb1 + ((j * 8 + brow) * TS + 16 * t + bcolh) * 2);
            }
            #pragma unroll
            for (int j = 0; j < 8; j++) {
                mma16816(sacc[j], a0, b0[j]);
                mma16816(sacc[j], a0, b1[j]);
                mma16816(sacc[j], a1, b0[j]);
            }
        }

        // ---- scale + causal mask + row max ----
        bool maskblk = (kt >= 2 * qt);
        float mx0 = mrow0, mx1 = mrow1;
        #pragma unroll
        for (int j = 0; j < 8; j++) {
            int col = kt * FK + j * 8 + gq * 2;
            #pragma unroll
            for (int e = 0; e < 4; e++) {
                float v = sacc[j][e] * scale;
                if (maskblk) {
                    int cc = col + (e & 1);
                    int rr = qrow0 + (e >> 1) * 8;
                    if (cc > rr) v = -1e30f;
                }
                sacc[j][e] = v;
                if (e < 2) mx0 = fmaxf(mx0, v);
                else       mx1 = fmaxf(mx1, v);
            }
        }
        mx0 = fmaxf(mx0, __shfl_xor_sync(0xffffffffu, mx0, 1));
        mx0 = fmaxf(mx0, __shfl_xor_sync(0xffffffffu, mx0, 2));
        mx1 = fmaxf(mx1, __shfl_xor_sync(0xffffffffu, mx1, 1));
        mx1 = fmaxf(mx1, __shfl_xor_sync(0xffffffffu, mx1, 2));
        float c0 = __expf(mrow0 - mx0);
        float c1 = __expf(mrow1 - mx1);
        mrow0 = mx0; mrow1 = mx1;
        #pragma unroll
        for (int j2 = 0; j2 < 16; j2++) {
            hacc[j2][0] *= c0; hacc[j2][1] *= c0;
            hacc[j2][2] *= c1; hacc[j2][3] *= c1;
        }

        // ---- P = exp(S-m), accumulate l, split+pack to A-fragments ----
        float lt0 = 0.f, lt1 = 0.f;
        uint32_t pa0[4][4], pa1[4][4];
        #pragma unroll
        for (int t = 0; t < 4; t++) {
            #pragma unroll
            for (int half = 0; half < 2; half++) {
                int j = 2 * t + half;
                float p0 = __expf(sacc[j][0] - mx0);
                float p1 = __expf(sacc[j][1] - mx0);
                float p2 = __expf(sacc[j][2] - mx1);
                float p3 = __expf(sacc[j][3] - mx1);
                lt0 += p0 + p1;
                lt1 += p2 + p3;
                split_pack(p0, p1, pa0[t][half*2+0], pa1[t][half*2+0]);
                split_pack(p2, p3, pa0[t][half*2+1], pa1[t][half*2+1]);
            }
        }
        lt0 += __shfl_xor_sync(0xffffffffu, lt0, 1);
        lt0 += __shfl_xor_sync(0xffffffffu, lt0, 2);
        lt1 += __shfl_xor_sync(0xffffffffu, lt1, 1);
        lt1 += __shfl_xor_sync(0xffffffffu, lt1, 2);
        lrow0 = lrow0 * c0 + lt0;
        lrow1 = lrow1 * c1 + lt1;

        // ---- H += P V (emulated), V^T via ldmatrix.trans ----
        uint32_t vb0 = sb + (VOFF + (st * 2 + 0) * FK * TS) * 2;
        uint32_t vb1 = sb + (VOFF + (st * 2 + 1) * FK * TS) * 2;
        int vrow = lq + (quad & 1) * 8;
        int vcolh = (quad >> 1) * 8;
        #pragma unroll
        for (int t = 0; t < 4; t++) {
            #pragma unroll
            for (int j2 = 0; j2 < 16; j2 += 2) {
                uint32_t bv0[2][2], bv1[2][2];
                LDSM_X4_T(bv0[0][0], bv0[0][1], bv0[1][0], bv0[1][1],
                          vb0 + ((16 * t + vrow) * TS + 8 * j2 + vcolh) * 2);
                LDSM_X4_T(bv1[0][0], bv1[0][1], bv1[1][0], bv1[1][1],
                          vb1 + ((16 * t + vrow) * TS + 8 * j2 + vcolh) * 2);
                mma16816(hacc[j2],   pa0[t], bv0[0]);
                mma16816(hacc[j2],   pa0[t], bv1[0]);
                mma16816(hacc[j2],   pa1[t], bv0[0]);
                mma16816(hacc[j2+1], pa0[t], bv0[1]);
                mma16816(hacc[j2+1], pa0[t], bv1[1]);
                mma16816(hacc[j2+1], pa1[t], bv0[1]);
            }
        }

        __syncthreads();
        if (kt + 2 < nkv) { LOADKV(kt + 2, st) }
        CP_COMMIT();
    }
    #undef LOADKV

    // ---- epilogue: H/l -> bf16 split planes in g_hs ----
    float li0 = 1.f / lrow0;
    float li1 = 1.f / lrow1;
    int b = bh >> 4;
    int hd = bh & (NH - 1);
    int s0 = qt * FQ + w * 16 + gr;
    size_t base0 = ((size_t)(b * SEQ + s0)) * DM + hd * DH;
    size_t base1 = ((size_t)(b * SEQ + s0 + 8)) * DM + hd * DH;
    #pragma unroll
    for (int j2 = 0; j2 < 16; j2++) {
        int d = j2 * 8 + gq * 2;
        uint32_t u0, u1;
        split_pack(hacc[j2][0] * li0, hacc[j2][1] * li0, u0, u1);
        *(uint32_t*)(g_hs[0] + base0 + d) = u0;
        *(uint32_t*)(g_hs[1] + base0 + d) = u1;
        split_pack(hacc[j2][2] * li1, hacc[j2][3] * li1, u0, u1);
        *(uint32_t*)(g_hs[0] + base1 + d) = u0;
        *(uint32_t*)(g_hs[1] + base1 + d) = u1;
    }
}

// ---------------------------------------------------------------------------
extern "C" void kernel_launch(void* const* d_in, const int* in_sizes, int n_in,
                              void* d_out, int out_size) {
    const float* x  = (const float*)d_in[0];
    const float* wq = (const float*)d_in[1];
    const float* wk = (const float*)d_in[2];
    const float* wv = (const float*)d_in[3];
    const float* wo = (const float*)d_in[4];
    const int* tok  = (const int*)d_in[5];
    float* out = (float*)d_out;

    cudaFuncSetAttribute(gemm_mma<0>,
                         cudaFuncAttributeMaxDynamicSharedMemorySize, GEMM_SMEM);
    cudaFuncSetAttribute(gemm_mma<1>,
                         cudaFuncAttributeMaxDynamicSharedMemorySize, GEMM_SMEM);
    cudaFuncSetAttribute(flash_mma,
                         cudaFuncAttributeMaxDynamicSharedMemorySize, FLASH_SMEM);

    // Launch order: QKV GEMM is launch index 5 so the harness ncu capture
    // (-s 5 -c 1) profiles the dominant kernel.
    rope_table_kernel<<<SEQ, HALF>>>(tok);                 // 0
    split2_kernel<0><<<MROWS*DM/4/256, 256>>>(x);          // 1
    split2_kernel<1><<<DM*DM/4/256, 256>>>(wq);            // 2
    split2_kernel<2><<<DM*DM/4/256, 256>>>(wk);            // 3
    split2_kernel<3><<<DM*DM/4/256, 256>>>(wv);            // 4

    dim3 gq(DM / 128, MROWS / 128, 3);                     // 5: fused QKV
    gemm_mma<1><<<gq, 256, GEMM_SMEM>>>(nullptr);

    dim3 fgrid(SEQ / FQ, BATCH * NH);                      // 6
    flash_mma<<<fgrid, 256, FLASH_SMEM>>>();

    split2_kernel<4><<<DM*DM/4/256, 256>>>(wo);            // 7
    dim3 go(DM / 128, MROWS / 128);                        // 8
    gemm_mma<0><<<go, 256, GEMM_SMEM>>>(out);
}

// round 7
// speedup vs baseline: 6.8250x; 1.0200x over previous
#include <cuda_runtime.h>
#include <cuda_bf16.h>
#include <math.h>
#include <stdint.h>

#define BATCH 2
#define SEQ 2048
#define DM 2048
#define NH 16
#define DH 128
#define MROWS (BATCH*SEQ)   // 4096
#define HALF (DH/2)         // 64

// ---------------------------------------------------------------------------
// Scratch (__device__ globals; allocation-free rule)
// ---------------------------------------------------------------------------
__device__ float2 g_rope[SEQ*HALF];
__device__ __nv_bfloat16 g_xs[2][MROWS*DM];          // x split planes
__device__ __nv_bfloat16 g_hs[2][MROWS*DM];          // attention-out split planes
__device__ __nv_bfloat16 g_ws[4][2][DM*DM];          // wq,wk,wv,wo split planes
__device__ __nv_bfloat16 g_qs[2][BATCH*NH*SEQ*DH];   // Q (post-RoPE) split planes
__device__ __nv_bfloat16 g_ks[2][BATCH*NH*SEQ*DH];
__device__ __nv_bfloat16 g_vs[2][BATCH*NH*SEQ*DH];

// ---------------------------------------------------------------------------
// Helpers
// ---------------------------------------------------------------------------
__device__ __forceinline__ uint32_t smem_u32(const void* p) {
    uint32_t a;
    asm("{ .reg .u64 t; cvta.to.shared.u64 t, %1; cvt.u32.u64 %0, t; }"
        : "=r"(a) : "l"(p));
    return a;
}
__device__ __forceinline__ void mma16816(float* d, const uint32_t* a,
                                         const uint32_t* b) {
    asm volatile(
        "mma.sync.aligned.m16n8k16.row.col.f32.bf16.bf16.f32 "
        "{%0,%1,%2,%3}, {%4,%5,%6,%7}, {%8,%9}, {%0,%1,%2,%3};\n"
        : "+f"(d[0]), "+f"(d[1]), "+f"(d[2]), "+f"(d[3])
        : "r"(a[0]), "r"(a[1]), "r"(a[2]), "r"(a[3]), "r"(b[0]), "r"(b[1]));
}
#define LDSM_X4(r0, r1, r2, r3, addr) \
    asm volatile("ldmatrix.sync.aligned.m8n8.x4.shared.b16 {%0,%1,%2,%3}, [%4];" \
        : "=r"(r0), "=r"(r1), "=r"(r2), "=r"(r3) : "r"(addr))
#define LDSM_X4_T(r0, r1, r2, r3, addr) \
    asm volatile("ldmatrix.sync.aligned.m8n8.x4.trans.shared.b16 {%0,%1,%2,%3}, [%4];" \
        : "=r"(r0), "=r"(r1), "=r"(r2), "=r"(r3) : "r"(addr))
#define CP_ASYNC16(dst, src) \
    asm volatile("cp.async.cg.shared.global [%0], [%1], 16;" :: "r"(dst), "l"(src))
#define CP_COMMIT() asm volatile("cp.async.commit_group;" ::: "memory")
#define CP_WAIT1()  asm volatile("cp.async.wait_group 1;" ::: "memory")

// split x,y to bf16 hi-planes (m0) and residual planes (m1), packed as b16x2
__device__ __forceinline__ void split_pack(float x, float y,
                                           uint32_t& m0, uint32_t& m1) {
    __nv_bfloat16 x0 = __float2bfloat16_rn(x);
    __nv_bfloat16 y0 = __float2bfloat16_rn(y);
    __nv_bfloat16 x1 = __float2bfloat16_rn(x - __bfloat162float(x0));
    __nv_bfloat16 y1 = __float2bfloat16_rn(y - __bfloat162float(y0));
    __nv_bfloat162 a = {x0, y0};
    __nv_bfloat162 b = {x1, y1};
    m0 = *(uint32_t*)&a;
    m1 = *(uint32_t*)&b;
}

// ---------------------------------------------------------------------------
// RoPE table (fp64-accurate angles, matching reference bit patterns)
// ---------------------------------------------------------------------------
__global__ void rope_table_kernel(const int* __restrict__ pos) {
    int s = blockIdx.x;
    int i = threadIdx.x;
    double inv = exp(-((double)(2 * i) / (double)DH) * log(10000.0));
    float invf = (float)inv;
    float freq = (float)pos[s] * invf;
    double a = (double)freq;
    g_rope[s * HALF + i] = make_float2((float)cos(a), (float)sin(a));
}

// ---------------------------------------------------------------------------
// 2-way bf16 split. TGT: 0=x->g_xs, 1..4=w->g_ws[TGT-1]
// ---------------------------------------------------------------------------
template<int TGT>
__global__ void split2_kernel(const float* __restrict__ src) {
    const int n4 = (TGT == 0) ? (MROWS * DM / 4) : (DM * DM / 4);
    int i = blockIdx.x * 256 + threadIdx.x;
    if (i >= n4) return;
    __nv_bfloat16* p0;
    __nv_bfloat16* p1;
    if (TGT == 0) { p0 = g_xs[0]; p1 = g_xs[1]; }
    else          { p0 = g_ws[TGT-1][0]; p1 = g_ws[TGT-1][1]; }

    float4 a = ((const float4*)src)[i];
    uint32_t u0a, u1a, u0b, u1b;
    split_pack(a.x, a.y, u0a, u1a);
    split_pack(a.z, a.w, u0b, u1b);
    ((uint32_t*)p0)[i*2]   = u0a;
    ((uint32_t*)p0)[i*2+1] = u0b;
    ((uint32_t*)p1)[i*2]   = u1a;
    ((uint32_t*)p1)[i*2+1] = u1b;
}

// ---------------------------------------------------------------------------
// mma.sync bf16 GEMM, fp32 emulation (3 cross-terms of 2-way split).
// Term-major MMA ordering: same-accumulator reuse distance = 8 (hides HMMA
// RAW latency). Per-acc term order (00,01,10) preserved -> numerics identical.
// ---------------------------------------------------------------------------
#define BK 32
#define NKB (DM/BK)  // 64
#define TSTR 40      // smem row stride in bf16 (80B)
#define GEMM_SMEM (2*4*128*TSTR*2)   // 81920 B

template<int MODE>
__global__ void __launch_bounds__(256, 2) gemm_mma(float* __restrict__ Out) {
    extern __shared__ __align__(128) __nv_bfloat16 dsm[];
    uint32_t sbase = smem_u32(dsm);

    int tid = threadIdx.x;
    int lane = tid & 31;
    int wid = tid >> 5;
    int m0 = blockIdx.y * 128;
    int n0 = blockIdx.x * 128;
    int z = (MODE == 1) ? blockIdx.z : 3;
    int wm = (wid & 1) * 64;
    int wn = (wid >> 1) * 32;
    int gr = lane >> 2;
    int gq = lane & 3;
    int lq = lane & 7;
    int quad = lane >> 3;

    const __nv_bfloat16* srcs[4];
    srcs[0] = ((MODE == 0) ? g_hs[0] : g_xs[0]) + (size_t)m0 * DM;
    srcs[1] = ((MODE == 0) ? g_hs[1] : g_xs[1]) + (size_t)m0 * DM;
    srcs[2] = g_ws[z][0] + (size_t)n0 * DM;
    srcs[3] = g_ws[z][1] + (size_t)n0 * DM;

    #define LOAD_STAGE(kb, st) { \
        int k0 = (kb) * BK; \
        _Pragma("unroll") \
        for (int it = 0; it < 8; it++) { \
            int e = tid + it * 256; \
            int t = e >> 9; \
            int e5 = e & 511; \
            int r = e5 >> 2; \
            int c = (e5 & 3) * 8; \
            const __nv_bfloat16* src = srcs[t] + (size_t)r * DM + k0 + c; \
            uint32_t dst = sbase + ((((st) * 4 + t) * 128 + r) * TSTR + c) * 2; \
            CP_ASYNC16(dst, src); \
        } }

    LOAD_STAGE(0, 0) CP_COMMIT();
    LOAD_STAGE(1, 1) CP_COMMIT();

    float acc[4][4][4] = {};

    int arow = lq + (quad & 1) * 8;
    int acolq = (quad >> 1) * 8;
    int brow = lq + (quad >> 1) * 8;
    int bcolq = (quad & 1) * 8;

    for (int kb = 0; kb < NKB; kb++) {
        int st = kb & 1;
        CP_WAIT1();
        __syncthreads();

        uint32_t ab0 = sbase + (((st * 4 + 0) * 128 + wm + arow) * TSTR) * 2;
        uint32_t ab1 = sbase + (((st * 4 + 1) * 128 + wm + arow) * TSTR) * 2;
        uint32_t bb0 = sbase + (((st * 4 + 2) * 128 + wn + brow) * TSTR) * 2;
        uint32_t bb1 = sbase + (((st * 4 + 3) * 128 + wn + brow) * TSTR) * 2;

        #pragma unroll
        for (int ks = 0; ks < BK; ks += 16) {
            // A fragments resident: 2 planes x 4 m16 tiles (32 regs)
            uint32_t af[2][4][4];
            #pragma unroll
            for (int i = 0; i < 4; i++) {
                LDSM_X4(af[0][i][0], af[0][i][1], af[0][i][2], af[0][i][3],
                        ab0 + (i * 16 * TSTR + ks + acolq) * 2);
                LDSM_X4(af[1][i][0], af[1][i][1], af[1][i][2], af[1][i][3],
                        ab1 + (i * 16 * TSTR + ks + acolq) * 2);
            }
            // B fragments streamed per jj-pair; MMAs term-major (dist-8 RAW)
            #pragma unroll
            for (int jj = 0; jj < 4; jj += 2) {
                uint32_t bf0[2][2], bf1[2][2];
                LDSM_X4(bf0[0][0], bf0[0][1], bf0[1][0], bf0[1][1],
                        bb0 + ((jj * 8) * TSTR + ks + bcolq) * 2);
                LDSM_X4(bf1[0][0], bf1[0][1], bf1[1][0], bf1[1][1],
                        bb1 + ((jj * 8) * TSTR + ks + bcolq) * 2);
                #pragma unroll
                for (int c = 0; c < 2; c++)
                    #pragma unroll
                    for (int i = 0; i < 4; i++)
                        mma16816(acc[i][jj+c], af[0][i], bf0[c]);
                #pragma unroll
                for (int c = 0; c < 2; c++)
                    #pragma unroll
                    for (int i = 0; i < 4; i++)
                        mma16816(acc[i][jj+c], af[0][i], bf1[c]);
                #pragma unroll
                for (int c = 0; c < 2; c++)
                    #pragma unroll
                    for (int i = 0; i < 4; i++)
                        mma16816(acc[i][jj+c], af[1][i], bf0[c]);
            }
        }
        __syncthreads();
        if (kb + 2 < NKB) { LOAD_STAGE(kb + 2, st) }
        CP_COMMIT();
    }
    #undef LOAD_STAGE

    int h = blockIdx.x;   // BN == DH
    #pragma unroll
    for (int i = 0; i < 4; i++) {
        #pragma unroll
        for (int half = 0; half < 2; half++) {
            int row = m0 + wm + i * 16 + gr + half * 8;
            int s = row & (SEQ - 1);
            int b = row >> 11;
            #pragma unroll
            for (int j = 0; j < 4; j++) {
                int d = wn + j * 8 + gq * 2;
                float e = acc[i][j][half * 2 + 0];
                float o = acc[i][j][half * 2 + 1];
                if (MODE == 0) {
                    *(float2*)(Out + (size_t)row * DM + n0 + d) =
                        make_float2(e, o);
                } else {
                    if (z < 2) {
                        float2 cs = g_rope[s * HALF + (d >> 1)];
                        float e2 = e * cs.x - o * cs.y;
                        o = e * cs.y + o * cs.x;
                        e = e2;
                    }
                    __nv_bfloat16* t0 = (z == 0) ? g_qs[0] : (z == 1) ? g_ks[0] : g_vs[0];
                    __nv_bfloat16* t1 = (z == 0) ? g_qs[1] : (z == 1) ? g_ks[1] : g_vs[1];
                    size_t off = ((size_t)(b * NH + h) * SEQ + s) * DH + d;
                    uint32_t u0, u1;
                    split_pack(e, o, u0, u1);
                    *(uint32_t*)(t0 + off) = u0;
                    *(uint32_t*)(t1 + off) = u1;
                }
            }
        }
    }
}

// ---------------------------------------------------------------------------
// Tensor-core flash attention, fp32-emulated bf16 (3-term), term-major MMAs.
// ---------------------------------------------------------------------------
#define TS 136   // smem row stride bf16 (272B)
#define FQ 128
#define FK 64
#define QOFF 0
#define KOFF (2*FQ*TS)             // 34816
#define VOFF (KOFF + 4*FK*TS)      // 69632
#define FLASH_SMEM ((VOFF + 4*FK*TS)*2)  // 208896 B

__global__ void __launch_bounds__(256, 1) flash_mma() {
    extern __shared__ __align__(16) __nv_bfloat16 fsm[];
    uint32_t sb = smem_u32(fsm);
    int tid = threadIdx.x;
    int lane = tid & 31;
    int w = tid >> 5;
    int gr = lane >> 2;
    int gq = lane & 3;
    int lq = lane & 7;
    int quad = lane >> 3;
    int bh = blockIdx.y;
    int qt = (int)gridDim.x - 1 - (int)blockIdx.x;   // heavy tiles first
    int nkv = 2 * qt + 2;

    const __nv_bfloat16* qsrc[2] = {
        g_qs[0] + ((size_t)bh * SEQ + qt * FQ) * DH,
        g_qs[1] + ((size_t)bh * SEQ + qt * FQ) * DH };
    const __nv_bfloat16* ksrc[2] = {
        g_ks[0] + (size_t)bh * SEQ * DH, g_ks[1] + (size_t)bh * SEQ * DH };
    const __nv_bfloat16* vsrc[2] = {
        g_vs[0] + (size_t)bh * SEQ * DH, g_vs[1] + (size_t)bh * SEQ * DH };

    #define LOADKV(kt_, st_) { \
        _Pragma("unroll") \
        for (int it = 0; it < 8; it++) { \
            int e = tid + it * 256; \
            int p = e >> 10; \
            int r = (e >> 4) & 63; \
            int c = (e & 15) * 8; \
            CP_ASYNC16(sb + (KOFF + ((st_) * 2 + p) * FK * TS + r * TS + c) * 2, \
                       ksrc[p] + ((size_t)(kt_) * FK + r) * DH + c); \
            CP_ASYNC16(sb + (VOFF + ((st_) * 2 + p) * FK * TS + r * TS + c) * 2, \
                       vsrc[p] + ((size_t)(kt_) * FK + r) * DH + c); \
        } }

    #pragma unroll
    for (int it = 0; it < 16; it++) {
        int e = tid + it * 256;
        int p = e >> 11;
        int r = (e >> 4) & 127;
        int c = (e & 15) * 8;
        CP_ASYNC16(sb + (QOFF + p * FQ * TS + r * TS + c) * 2,
                   qsrc[p] + (size_t)r * DH + c);
    }
    LOADKV(0, 0)
    CP_COMMIT();
    LOADKV(1, 1)
    CP_COMMIT();

    float hacc[16][4] = {};
    float mrow0 = -INFINITY, mrow1 = -INFINITY;
    float lrow0 = 0.f, lrow1 = 0.f;
    const float scale = 0.08838834764831845f;   // 1/sqrt(128)

    int arow = lq + (quad & 1) * 8;
    int acolh = (quad >> 1) * 8;
    int brow = lq + (quad >> 1) * 8;
    int bcolh = (quad & 1) * 8;
    int qrow0 = qt * FQ + w * 16 + gr;

    for (int kt = 0; kt < nkv; kt++) {
        int st = kt & 1;
        CP_WAIT1();
        __syncthreads();

        // ---- S = Q K^T (emulated), term-major (dist-8 RAW) ----
        float sacc[8][4] = {};
        uint32_t qb0 = sb + (QOFF + (w * 16 + arow) * TS) * 2;
        uint32_t qb1 = qb0 + (FQ * TS) * 2;
        uint32_t kb0 = sb + (KOFF + (st * 2 + 0) * FK * TS) * 2;
        uint32_t kb1 = sb + (KOFF + (st * 2 + 1) * FK * TS) * 2;
        #pragma unroll
        for (int t = 0; t < 8; t++) {
            uint32_t a0[4], a1[4];
            LDSM_X4(a0[0], a0[1], a0[2], a0[3], qb0 + (16 * t + acolh) * 2);
            LDSM_X4(a1[0], a1[1], a1[2], a1[3], qb1 + (16 * t + acolh) * 2);
            uint32_t b0[8][2], b1[8][2];
            #pragma unroll
            for (int j = 0; j < 8; j += 2) {
                LDSM_X4(b0[j][0], b0[j][1], b0[j+1][0], b0[j+1][1],
                        kb0 + ((j * 8 + brow) * TS + 16 * t + bcolh) * 2);
                LDSM_X4(b1[j][0], b1[j][1], b1[j+1][0], b1[j+1][1],
                        kb1 + ((j * 8 + brow) * TS + 16 * t + bcolh) * 2);
            }
            #pragma unroll
            for (int j = 0; j < 8; j++) mma16816(sacc[j], a0, b0[j]);
            #pragma unroll
            for (int j = 0; j < 8; j++) mma16816(sacc[j], a0, b1[j]);
            #pragma unroll
            for (int j = 0; j < 8; j++) mma16816(sacc[j], a1, b0[j]);
        }

        // ---- scale + causal mask + row max ----
        bool maskblk = (kt >= 2 * qt);
        float mx0 = mrow0, mx1 = mrow1;
        #pragma unroll
        for (int j = 0; j < 8; j++) {
            int col = kt * FK + j * 8 + gq * 2;
            #pragma unroll
            for (int e = 0; e < 4; e++) {
                float v = sacc[j][e] * scale;
                if (maskblk) {
                    int cc = col + (e & 1);
                    int rr = qrow0 + (e >> 1) * 8;
                    if (cc > rr) v = -1e30f;
                }
                sacc[j][e] = v;
                if (e < 2) mx0 = fmaxf(mx0, v);
                else       mx1 = fmaxf(mx1, v);
            }
        }
        mx0 = fmaxf(mx0, __shfl_xor_sync(0xffffffffu, mx0, 1));
        mx0 = fmaxf(mx0, __shfl_xor_sync(0xffffffffu, mx0, 2));
        mx1 = fmaxf(mx1, __shfl_xor_sync(0xffffffffu, mx1, 1));
        mx1 = fmaxf(mx1, __shfl_xor_sync(0xffffffffu, mx1, 2));
        float c0 = __expf(mrow0 - mx0);
        float c1 = __expf(mrow1 - mx1);
        mrow0 = mx0; mrow1 = mx1;
        #pragma unroll
        for (int j2 = 0; j2 < 16; j2++) {
            hacc[j2][0] *= c0; hacc[j2][1] *= c0;
            hacc[j2][2] *= c1; hacc[j2][3] *= c1;
        }

        // ---- P = exp(S-m), accumulate l, split+pack to A-fragments ----
        float lt0 = 0.f, lt1 = 0.f;
        uint32_t pa0[4][4], pa1[4][4];
        #pragma unroll
        for (int t = 0; t < 4; t++) {
            #pragma unroll
            for (int half = 0; half < 2; half++) {
                int j = 2 * t + half;
                float p0 = __expf(sacc[j][0] - mx0);
                float p1 = __expf(sacc[j][1] - mx0);
                float p2 = __expf(sacc[j][2] - mx1);
                float p3 = __expf(sacc[j][3] - mx1);
                lt0 += p0 + p1;
                lt1 += p2 + p3;
                split_pack(p0, p1, pa0[t][half*2+0], pa1[t][half*2+0]);
                split_pack(p2, p3, pa0[t][half*2+1], pa1[t][half*2+1]);
            }
        }
        lt0 += __shfl_xor_sync(0xffffffffu, lt0, 1);
        lt0 += __shfl_xor_sync(0xffffffffu, lt0, 2);
        lt1 += __shfl_xor_sync(0xffffffffu, lt1, 1);
        lt1 += __shfl_xor_sync(0xffffffffu, lt1, 2);
        lrow0 = lrow0 * c0 + lt0;
        lrow1 = lrow1 * c1 + lt1;

        // ---- H += P V (emulated), 4 V-tiles per block, term-major ----
        uint32_t vb0 = sb + (VOFF + (st * 2 + 0) * FK * TS) * 2;
        uint32_t vb1 = sb + (VOFF + (st * 2 + 1) * FK * TS) * 2;
        int vrow = lq + (quad & 1) * 8;
        int vcolh = (quad >> 1) * 8;
        #pragma unroll
        for (int t = 0; t < 4; t++) {
            #pragma unroll
            for (int j4 = 0; j4 < 16; j4 += 4) {
                uint32_t bv0[4][2], bv1[4][2];
                LDSM_X4_T(bv0[0][0], bv0[0][1], bv0[1][0], bv0[1][1],
                          vb0 + ((16 * t + vrow) * TS + 8 * j4 + vcolh) * 2);
                LDSM_X4_T(bv0[2][0], bv0[2][1], bv0[3][0], bv0[3][1],
                          vb0 + ((16 * t + vrow) * TS + 8 * (j4 + 2) + vcolh) * 2);
                LDSM_X4_T(bv1[0][0], bv1[0][1], bv1[1][0], bv1[1][1],
                          vb1 + ((16 * t + vrow) * TS + 8 * j4 + vcolh) * 2);
                LDSM_X4_T(bv1[2][0], bv1[2][1], bv1[3][0], bv1[3][1],
                          vb1 + ((16 * t + vrow) * TS + 8 * (j4 + 2) + vcolh) * 2);
                #pragma unroll
                for (int c = 0; c < 4; c++) mma16816(hacc[j4+c], pa0[t], bv0[c]);
                #pragma unroll
                for (int c = 0; c < 4; c++) mma16816(hacc[j4+c], pa0[t], bv1[c]);
                #pragma unroll
                for (int c = 0; c < 4; c++) mma16816(hacc[j4+c], pa1[t], bv0[c]);
            }
        }

        __syncthreads();
        if (kt + 2 < nkv) { LOADKV(kt + 2, st) }
        CP_COMMIT();
    }
    #undef LOADKV

    // ---- epilogue: H/l -> bf16 split planes in g_hs ----
    float li0 = 1.f / lrow0;
    float li1 = 1.f / lrow1;
    int b = bh >> 4;
    int hd = bh & (NH - 1);
    int s0 = qt * FQ + w * 16 + gr;
    size_t base0 = ((size_t)(b * SEQ + s0)) * DM + hd * DH;
    size_t base1 = ((size_t)(b * SEQ + s0 + 8)) * DM + hd * DH;
    #pragma unroll
    for (int j2 = 0; j2 < 16; j2++) {
        int d = j2 * 8 + gq * 2;
        uint32_t u0, u1;
        split_pack(hacc[j2][0] * li0, hacc[j2][1] * li0, u0, u1);
        *(uint32_t*)(g_hs[0] + base0 + d) = u0;
        *(uint32_t*)(g_hs[1] + base0 + d) = u1;
        split_pack(hacc[j2][2] * li1, hacc[j2][3] * li1, u0, u1);
        *(uint32_t*)(g_hs[0] + base1 + d) = u0;
        *(uint32_t*)(g_hs[1] + base1 + d) = u1;
    }
}

// ---------------------------------------------------------------------------
extern "C" void kernel_launch(void* const* d_in, const int* in_sizes, int n_in,
                              void* d_out, int out_size) {
    const float* x  = (const float*)d_in[0];
    const float* wq = (const float*)d_in[1];
    const float* wk = (const float*)d_in[2];
    const float* wv = (const float*)d_in[3];
    const float* wo = (const float*)d_in[4];
    const int* tok  = (const int*)d_in[5];
    float* out = (float*)d_out;

    cudaFuncSetAttribute(gemm_mma<0>,
                         cudaFuncAttributeMaxDynamicSharedMemorySize, GEMM_SMEM);
    cudaFuncSetAttribute(gemm_mma<1>,
                         cudaFuncAttributeMaxDynamicSharedMemorySize, GEMM_SMEM);
    cudaFuncSetAttribute(flash_mma,
                         cudaFuncAttributeMaxDynamicSharedMemorySize, FLASH_SMEM);

    rope_table_kernel<<<SEQ, HALF>>>(tok);                 // 0
    split2_kernel<0><<<MROWS*DM/4/256, 256>>>(x);          // 1
    split2_kernel<1><<<DM*DM/4/256, 256>>>(wq);            // 2
    split2_kernel<2><<<DM*DM/4/256, 256>>>(wk);            // 3
    split2_kernel<3><<<DM*DM/4/256, 256>>>(wv);            // 4

    dim3 gq(DM / 128, MROWS / 128, 3);                     // 5: fused QKV
    gemm_mma<1><<<gq, 256, GEMM_SMEM>>>(nullptr);

    dim3 fgrid(SEQ / FQ, BATCH * NH);                      // 6
    flash_mma<<<fgrid, 256, FLASH_SMEM>>>();

    split2_kernel<4><<<DM*DM/4/256, 256>>>(wo);            // 7
    dim3 go(DM / 128, MROWS / 128);                        // 8
    gemm_mma<0><<<go, 256, GEMM_SMEM>>>(out);
}

// round 8
// speedup vs baseline: 6.9022x; 1.0113x over previous
#include <cuda_runtime.h>
#include <cuda_bf16.h>
#include <math.h>
#include <stdint.h>

#define BATCH 2
#define SEQ 2048
#define DM 2048
#define NH 16
#define DH 128
#define MROWS (BATCH*SEQ)   // 4096
#define HALF (DH/2)         // 64

// ---------------------------------------------------------------------------
// Scratch (__device__ globals; allocation-free rule)
// ---------------------------------------------------------------------------
__device__ float2 g_rope[SEQ*HALF];
__device__ __nv_bfloat16 g_xs[2][MROWS*DM];          // x split planes
__device__ __nv_bfloat16 g_hs[2][MROWS*DM];          // attention-out split planes
__device__ __nv_bfloat16 g_ws[4][2][DM*DM];          // wq,wk,wv,wo split planes
__device__ __nv_bfloat16 g_qs[2][BATCH*NH*SEQ*DH];   // Q (post-RoPE) split planes
__device__ __nv_bfloat16 g_ks[2][BATCH*NH*SEQ*DH];
__device__ __nv_bfloat16 g_vs[2][BATCH*NH*SEQ*DH];

// ---------------------------------------------------------------------------
// Helpers
// ---------------------------------------------------------------------------
__device__ __forceinline__ uint32_t smem_u32(const void* p) {
    uint32_t a;
    asm("{ .reg .u64 t; cvta.to.shared.u64 t, %1; cvt.u32.u64 %0, t; }"
        : "=r"(a) : "l"(p));
    return a;
}
__device__ __forceinline__ void mma16816(float* d, const uint32_t* a,
                                         const uint32_t* b) {
    asm volatile(
        "mma.sync.aligned.m16n8k16.row.col.f32.bf16.bf16.f32 "
        "{%0,%1,%2,%3}, {%4,%5,%6,%7}, {%8,%9}, {%0,%1,%2,%3};\n"
        : "+f"(d[0]), "+f"(d[1]), "+f"(d[2]), "+f"(d[3])
        : "r"(a[0]), "r"(a[1]), "r"(a[2]), "r"(a[3]), "r"(b[0]), "r"(b[1]));
}
#define LDSM_X4(r0, r1, r2, r3, addr) \
    asm volatile("ldmatrix.sync.aligned.m8n8.x4.shared.b16 {%0,%1,%2,%3}, [%4];" \
        : "=r"(r0), "=r"(r1), "=r"(r2), "=r"(r3) : "r"(addr))
#define LDSM_X4_T(r0, r1, r2, r3, addr) \
    asm volatile("ldmatrix.sync.aligned.m8n8.x4.trans.shared.b16 {%0,%1,%2,%3}, [%4];" \
        : "=r"(r0), "=r"(r1), "=r"(r2), "=r"(r3) : "r"(addr))
#define CP_ASYNC16(dst, src) \
    asm volatile("cp.async.cg.shared.global [%0], [%1], 16;" :: "r"(dst), "l"(src))
#define CP_COMMIT() asm volatile("cp.async.commit_group;" ::: "memory")
#define CP_WAIT1()  asm volatile("cp.async.wait_group 1;" ::: "memory")

// split x,y to bf16 hi-planes (m0) and residual planes (m1), packed as b16x2
__device__ __forceinline__ void split_pack(float x, float y,
                                           uint32_t& m0, uint32_t& m1) {
    __nv_bfloat16 x0 = __float2bfloat16_rn(x);
    __nv_bfloat16 y0 = __float2bfloat16_rn(y);
    __nv_bfloat16 x1 = __float2bfloat16_rn(x - __bfloat162float(x0));
    __nv_bfloat16 y1 = __float2bfloat16_rn(y - __bfloat162float(y0));
    __nv_bfloat162 a = {x0, y0};
    __nv_bfloat162 b = {x1, y1};
    m0 = *(uint32_t*)&a;
    m1 = *(uint32_t*)&b;
}

// ---------------------------------------------------------------------------
// RoPE table (fp64-accurate angles, matching reference bit patterns)
// ---------------------------------------------------------------------------
__global__ void rope_table_kernel(const int* __restrict__ pos) {
    int s = blockIdx.x;
    int i = threadIdx.x;
    double inv = exp(-((double)(2 * i) / (double)DH) * log(10000.0));
    float invf = (float)inv;
    float freq = (float)pos[s] * invf;
    double a = (double)freq;
    g_rope[s * HALF + i] = make_float2((float)cos(a), (float)sin(a));
}

// ---------------------------------------------------------------------------
// Merged 2-way bf16 split: x + wq + wk + wv + wo in one launch.
// Region sizes are powers of two -> all decode is shifts/masks.
// ---------------------------------------------------------------------------
#define N4X (MROWS*DM/4)   // 2^21
#define N4W (DM*DM/4)      // 2^20
__global__ void __launch_bounds__(256) split_all_kernel(
    const float* __restrict__ x,  const float* __restrict__ wq,
    const float* __restrict__ wk, const float* __restrict__ wv,
    const float* __restrict__ wo) {
    int i = blockIdx.x * 256 + threadIdx.x;
    const float* src;
    __nv_bfloat16* p0;
    __nv_bfloat16* p1;
    int idx;
    if (i < N4X) {
        src = x; p0 = g_xs[0]; p1 = g_xs[1]; idx = i;
    } else {
        int j = i - N4X;
        int wsel = j >> 20;
        idx = j & (N4W - 1);
        src = (wsel == 0) ? wq : (wsel == 1) ? wk : (wsel == 2) ? wv : wo;
        p0 = g_ws[wsel][0]; p1 = g_ws[wsel][1];
    }
    float4 a = ((const float4*)src)[idx];
    uint32_t u0a, u1a, u0b, u1b;
    split_pack(a.x, a.y, u0a, u1a);
    split_pack(a.z, a.w, u0b, u1b);
    ((uint32_t*)p0)[idx*2]   = u0a;
    ((uint32_t*)p0)[idx*2+1] = u0b;
    ((uint32_t*)p1)[idx*2]   = u1a;
    ((uint32_t*)p1)[idx*2+1] = u1b;
}

// ---------------------------------------------------------------------------
// mma.sync bf16 GEMM, fp32 emulation (3 cross-terms of 2-way split).
// 3-stage cp.async pipeline, XOR-swizzled smem (64B rows, granule ^= row&3),
// ONE __syncthreads per K-block.
// MODE 1 (QKV fused): z=0/1/2 -> g_qs(+RoPE)/g_ks(+RoPE)/g_vs split planes
// MODE 0 (O-proj):    Out row-major fp32
// ---------------------------------------------------------------------------
#define BK 32
#define NKB (DM/BK)            // 64
#define TILE_B 8192            // 128 rows * 64 B
#define STAGE_B (4*TILE_B)     // 32768
#define GEMM_SMEM (3*STAGE_B)  // 98304

template<int MODE>
__global__ void __launch_bounds__(256, 2) gemm_mma(float* __restrict__ Out) {
    extern __shared__ __align__(128) __nv_bfloat16 dsm[];
    uint32_t sbase = smem_u32(dsm);

    int tid = threadIdx.x;
    int lane = tid & 31;
    int wid = tid >> 5;
    int m0 = blockIdx.y * 128;
    int n0 = blockIdx.x * 128;
    int z = (MODE == 1) ? blockIdx.z : 3;
    int wm = (wid & 1) * 64;
    int wn = (wid >> 1) * 32;
    int gr = lane >> 2;
    int gq = lane & 3;
    int lq = lane & 7;
    int quad = lane >> 3;

    const __nv_bfloat16* srcs[4];
    srcs[0] = ((MODE == 0) ? g_hs[0] : g_xs[0]) + (size_t)m0 * DM;
    srcs[1] = ((MODE == 0) ? g_hs[1] : g_xs[1]) + (size_t)m0 * DM;
    srcs[2] = g_ws[z][0] + (size_t)n0 * DM;
    srcs[3] = g_ws[z][1] + (size_t)n0 * DM;

    // Swizzled store: granule (r,c) at r*64 + ((c ^ (r&3))<<4)
    #define LOAD_STAGE(kb, st) { \
        int k0 = (kb) * BK; \
        _Pragma("unroll") \
        for (int it = 0; it < 8; it++) { \
            int e = tid + it * 256; \
            int t = e >> 9; \
            int e5 = e & 511; \
            int r = e5 >> 2; \
            int c = e5 & 3; \
            const __nv_bfloat16* src = srcs[t] + (size_t)r * DM + k0 + c * 8; \
            uint32_t dst = sbase + (st) * STAGE_B + t * TILE_B + r * 64 \
                         + ((c ^ (r & 3)) << 4); \
            CP_ASYNC16(dst, src); \
        } }

    LOAD_STAGE(0, 0) CP_COMMIT();
    LOAD_STAGE(1, 1) CP_COMMIT();

    float acc[4][4][4] = {};

    int arow = lq + (quad & 1) * 8;
    int sa = arow & 3;
    int ca0 = (quad >> 1);            // A base granule (acolq>>3)
    int brow = lq + (quad >> 1) * 8;
    int sb2 = brow & 3;
    int cb0 = (quad & 1);             // B base granule

    int stc = 0;   // compute stage = kb%3
    int stn = 2;   // load stage for kb+2
    for (int kb = 0; kb < NKB; kb++) {
        CP_WAIT1();
        __syncthreads();   // all warps released stage stn (held kb-1); kb visible
        if (kb + 2 < NKB) { LOAD_STAGE(kb + 2, stn) }
        CP_COMMIT();

        uint32_t tb = sbase + stc * STAGE_B;
        #pragma unroll
        for (int ks = 0; ks < BK; ks += 16) {
            int cga = (ks >> 3) + ca0;          // A granule for this ks
            int cgb = (ks >> 3) + cb0;          // B granule
            uint32_t aoff = ((cga ^ sa) << 4) + arow * 64;
            uint32_t boff = ((cgb ^ sb2) << 4) + brow * 64;
            // A fragments resident: 2 planes x 4 m16 tiles
            uint32_t af[2][4][4];
            #pragma unroll
            for (int i = 0; i < 4; i++) {
                LDSM_X4(af[0][i][0], af[0][i][1], af[0][i][2], af[0][i][3],
                        tb + 0 * TILE_B + (wm + i * 16) * 64 + aoff);
                LDSM_X4(af[1][i][0], af[1][i][1], af[1][i][2], af[1][i][3],
                        tb + 1 * TILE_B + (wm + i * 16) * 64 + aoff);
            }
            #pragma unroll
            for (int jj = 0; jj < 4; jj += 2) {
                uint32_t bf0[2][2], bf1[2][2];
                LDSM_X4(bf0[0][0], bf0[0][1], bf0[1][0], bf0[1][1],
                        tb + 2 * TILE_B + (wn + jj * 8) * 64 + boff);
                LDSM_X4(bf1[0][0], bf1[0][1], bf1[1][0], bf1[1][1],
                        tb + 3 * TILE_B + (wn + jj * 8) * 64 + boff);
                #pragma unroll
                for (int c = 0; c < 2; c++)
                    #pragma unroll
                    for (int i = 0; i < 4; i++)
                        mma16816(acc[i][jj+c], af[0][i], bf0[c]);
                #pragma unroll
                for (int c = 0; c < 2; c++)
                    #pragma unroll
                    for (int i = 0; i < 4; i++)
                        mma16816(acc[i][jj+c], af[0][i], bf1[c]);
                #pragma unroll
                for (int c = 0; c < 2; c++)
                    #pragma unroll
                    for (int i = 0; i < 4; i++)
                        mma16816(acc[i][jj+c], af[1][i], bf0[c]);
            }
        }
        stc = (stc == 2) ? 0 : stc + 1;
        stn = (stn == 2) ? 0 : stn + 1;
    }
    #undef LOAD_STAGE

    int h = blockIdx.x;   // BN == DH
    #pragma unroll
    for (int i = 0; i < 4; i++) {
        #pragma unroll
        for (int half = 0; half < 2; half++) {
            int row = m0 + wm + i * 16 + gr + half * 8;
            int s = row & (SEQ - 1);
            int b = row >> 11;
            #pragma unroll
            for (int j = 0; j < 4; j++) {
                int d = wn + j * 8 + gq * 2;
                float e = acc[i][j][half * 2 + 0];
                float o = acc[i][j][half * 2 + 1];
                if (MODE == 0) {
                    *(float2*)(Out + (size_t)row * DM + n0 + d) =
                        make_float2(e, o);
                } else {
                    if (z < 2) {
                        float2 cs = g_rope[s * HALF + (d >> 1)];
                        float e2 = e * cs.x - o * cs.y;
                        o = e * cs.y + o * cs.x;
                        e = e2;
                    }
                    __nv_bfloat16* t0 = (z == 0) ? g_qs[0] : (z == 1) ? g_ks[0] : g_vs[0];
                    __nv_bfloat16* t1 = (z == 0) ? g_qs[1] : (z == 1) ? g_ks[1] : g_vs[1];
                    size_t off = ((size_t)(b * NH + h) * SEQ + s) * DH + d;
                    uint32_t u0, u1;
                    split_pack(e, o, u0, u1);
                    *(uint32_t*)(t0 + off) = u0;
                    *(uint32_t*)(t1 + off) = u1;
                }
            }
        }
    }
}

// ---------------------------------------------------------------------------
// Tensor-core flash attention, fp32-emulated bf16 (3-term), term-major MMAs.
// Warp-skip: in the last (fully-masked-for-low-warps) diagonal block, warps
// 0-3 skip all work (provably exact no-op: c=1, P=0 contributions).
// ---------------------------------------------------------------------------
#define TS 136   // smem row stride bf16 (272B)
#define FQ 128
#define FK 64
#define QOFF 0
#define KOFF (2*FQ*TS)             // 34816
#define VOFF (KOFF + 4*FK*TS)      // 69632
#define FLASH_SMEM ((VOFF + 4*FK*TS)*2)  // 208896 B

__global__ void __launch_bounds__(256, 1) flash_mma() {
    extern __shared__ __align__(16) __nv_bfloat16 fsm[];
    uint32_t sb = smem_u32(fsm);
    int tid = threadIdx.x;
    int lane = tid & 31;
    int w = tid >> 5;
    int gr = lane >> 2;
    int gq = lane & 3;
    int lq = lane & 7;
    int quad = lane >> 3;
    int bh = blockIdx.y;
    int qt = (int)gridDim.x - 1 - (int)blockIdx.x;   // heavy tiles first
    int nkv = 2 * qt + 2;

    const __nv_bfloat16* qsrc[2] = {
        g_qs[0] + ((size_t)bh * SEQ + qt * FQ) * DH,
        g_qs[1] + ((size_t)bh * SEQ + qt * FQ) * DH };
    const __nv_bfloat16* ksrc[2] = {
        g_ks[0] + (size_t)bh * SEQ * DH, g_ks[1] + (size_t)bh * SEQ * DH };
    const __nv_bfloat16* vsrc[2] = {
        g_vs[0] + (size_t)bh * SEQ * DH, g_vs[1] + (size_t)bh * SEQ * DH };

    #define LOADKV(kt_, st_) { \
        _Pragma("unroll") \
        for (int it = 0; it < 8; it++) { \
            int e = tid + it * 256; \
            int p = e >> 10; \
            int r = (e >> 4) & 63; \
            int c = (e & 15) * 8; \
            CP_ASYNC16(sb + (KOFF + ((st_) * 2 + p) * FK * TS + r * TS + c) * 2, \
                       ksrc[p] + ((size_t)(kt_) * FK + r) * DH + c); \
            CP_ASYNC16(sb + (VOFF + ((st_) * 2 + p) * FK * TS + r * TS + c) * 2, \
                       vsrc[p] + ((size_t)(kt_) * FK + r) * DH + c); \
        } }

    #pragma unroll
    for (int it = 0; it < 16; it++) {
        int e = tid + it * 256;
        int p = e >> 11;
        int r = (e >> 4) & 127;
        int c = (e & 15) * 8;
        CP_ASYNC16(sb + (QOFF + p * FQ * TS + r * TS + c) * 2,
                   qsrc[p] + (size_t)r * DH + c);
    }
    LOADKV(0, 0)
    CP_COMMIT();
    LOADKV(1, 1)
    CP_COMMIT();

    float hacc[16][4] = {};
    float mrow0 = -INFINITY, mrow1 = -INFINITY;
    float lrow0 = 0.f, lrow1 = 0.f;
    const float scale = 0.08838834764831845f;   // 1/sqrt(128)

    int arow = lq + (quad & 1) * 8;
    int acolh = (quad >> 1) * 8;
    int brow = lq + (quad >> 1) * 8;
    int bcolh = (quad & 1) * 8;
    int qrow0 = qt * FQ + w * 16 + gr;

    for (int kt = 0; kt < nkv; kt++) {
        int st = kt & 1;
        CP_WAIT1();
        __syncthreads();

        // Fully-masked warp-block: exact no-op, skip all compute.
        bool fullmask = (kt == 2 * qt + 1) && (w < 4);
        if (!fullmask) {

        // ---- S = Q K^T (emulated), term-major ----
        float sacc[8][4] = {};
        uint32_t qb0 = sb + (QOFF + (w * 16 + arow) * TS) * 2;
        uint32_t qb1 = qb0 + (FQ * TS) * 2;
        uint32_t kb0 = sb + (KOFF + (st * 2 + 0) * FK * TS) * 2;
        uint32_t kb1 = sb + (KOFF + (st * 2 + 1) * FK * TS) * 2;
        #pragma unroll
        for (int t = 0; t < 8; t++) {
            uint32_t a0[4], a1[4];
            LDSM_X4(a0[0], a0[1], a0[2], a0[3], qb0 + (16 * t + acolh) * 2);
            LDSM_X4(a1[0], a1[1], a1[2], a1[3], qb1 + (16 * t + acolh) * 2);
            uint32_t b0[8][2], b1[8][2];
            #pragma unroll
            for (int j = 0; j < 8; j += 2) {
                LDSM_X4(b0[j][0], b0[j][1], b0[j+1][0], b0[j+1][1],
                        kb0 + ((j * 8 + brow) * TS + 16 * t + bcolh) * 2);
                LDSM_X4(b1[j][0], b1[j][1], b1[j+1][0], b1[j+1][1],
                        kb1 + ((j * 8 + brow) * TS + 16 * t + bcolh) * 2);
            }
            #pragma unroll
            for (int j = 0; j < 8; j++) mma16816(sacc[j], a0, b0[j]);
            #pragma unroll
            for (int j = 0; j < 8; j++) mma16816(sacc[j], a0, b1[j]);
            #pragma unroll
            for (int j = 0; j < 8; j++) mma16816(sacc[j], a1, b0[j]);
        }

        // ---- scale + causal mask + row max ----
        bool maskblk = (kt >= 2 * qt);
        float mx0 = mrow0, mx1 = mrow1;
        #pragma unroll
        for (int j = 0; j < 8; j++) {
            int col = kt * FK + j * 8 + gq * 2;
            #pragma unroll
            for (int e = 0; e < 4; e++) {
                float v = sacc[j][e] * scale;
                if (maskblk) {
                    int cc = col + (e & 1);
                    int rr = qrow0 + (e >> 1) * 8;
                    if (cc > rr) v = -1e30f;
                }
                sacc[j][e] = v;
                if (e < 2) mx0 = fmaxf(mx0, v);
                else       mx1 = fmaxf(mx1, v);
            }
        }
        mx0 = fmaxf(mx0, __shfl_xor_sync(0xffffffffu, mx0, 1));
        mx0 = fmaxf(mx0, __shfl_xor_sync(0xffffffffu, mx0, 2));
        mx1 = fmaxf(mx1, __shfl_xor_sync(0xffffffffu, mx1, 1));
        mx1 = fmaxf(mx1, __shfl_xor_sync(0xffffffffu, mx1, 2));
        float c0 = __expf(mrow0 - mx0);
        float c1 = __expf(mrow1 - mx1);
        mrow0 = mx0; mrow1 = mx1;
        #pragma unroll
        for (int j2 = 0; j2 < 16; j2++) {
            hacc[j2][0] *= c0; hacc[j2][1] *= c0;
            hacc[j2][2] *= c1; hacc[j2][3] *= c1;
        }

        // ---- P = exp(S-m), accumulate l, split+pack to A-fragments ----
        float lt0 = 0.f, lt1 = 0.f;
        uint32_t pa0[4][4], pa1[4][4];
        #pragma unroll
        for (int t = 0; t < 4; t++) {
            #pragma unroll
            for (int half = 0; half < 2; half++) {
                int j = 2 * t + half;
                float p0 = __expf(sacc[j][0] - mx0);
                float p1 = __expf(sacc[j][1] - mx0);
                float p2 = __expf(sacc[j][2] - mx1);
                float p3 = __expf(sacc[j][3] - mx1);
                lt0 += p0 + p1;
                lt1 += p2 + p3;
                split_pack(p0, p1, pa0[t][half*2+0], pa1[t][half*2+0]);
                split_pack(p2, p3, pa0[t][half*2+1], pa1[t][half*2+1]);
            }
        }
        lt0 += __shfl_xor_sync(0xffffffffu, lt0, 1);
        lt0 += __shfl_xor_sync(0xffffffffu, lt0, 2);
        lt1 += __shfl_xor_sync(0xffffffffu, lt1, 1);
        lt1 += __shfl_xor_sync(0xffffffffu, lt1, 2);
        lrow0 = lrow0 * c0 + lt0;
        lrow1 = lrow1 * c1 + lt1;

        // ---- H += P V (emulated), 4 V-tiles per block, term-major ----
        uint32_t vb0 = sb + (VOFF + (st * 2 + 0) * FK * TS) * 2;
        uint32_t vb1 = sb + (VOFF + (st * 2 + 1) * FK * TS) * 2;
        int vrow = lq + (quad & 1) * 8;
        int vcolh = (quad >> 1) * 8;
        #pragma unroll
        for (int t = 0; t < 4; t++) {
            #pragma unroll
            for (int j4 = 0; j4 < 16; j4 += 4) {
                uint32_t bv0[4][2], bv1[4][2];
                LDSM_X4_T(bv0[0][0], bv0[0][1], bv0[1][0], bv0[1][1],
                          vb0 + ((16 * t + vrow) * TS + 8 * j4 + vcolh) * 2);
                LDSM_X4_T(bv0[2][0], bv0[2][1], bv0[3][0], bv0[3][1],
                          vb0 + ((16 * t + vrow) * TS + 8 * (j4 + 2) + vcolh) * 2);
                LDSM_X4_T(bv1[0][0], bv1[0][1], bv1[1][0], bv1[1][1],
                          vb1 + ((16 * t + vrow) * TS + 8 * j4 + vcolh) * 2);
                LDSM_X4_T(bv1[2][0], bv1[2][1], bv1[3][0], bv1[3][1],
                          vb1 + ((16 * t + vrow) * TS + 8 * (j4 + 2) + vcolh) * 2);
                #pragma unroll
                for (int c = 0; c < 4; c++) mma16816(hacc[j4+c], pa0[t], bv0[c]);
                #pragma unroll
                for (int c = 0; c < 4; c++) mma16816(hacc[j4+c], pa0[t], bv1[c]);
                #pragma unroll
                for (int c = 0; c < 4; c++) mma16816(hacc[j4+c], pa1[t], bv0[c]);
            }
        }

        }  // !fullmask

        __syncthreads();
        if (kt + 2 < nkv) { LOADKV(kt + 2, st) }
        CP_COMMIT();
    }
    #undef LOADKV

    // ---- epilogue: H/l -> bf16 split planes in g_hs ----
    float li0 = 1.f / lrow0;
    float li1 = 1.f / lrow1;
    int b = bh >> 4;
    int hd = bh & (NH - 1);
    int s0 = qt * FQ + w * 16 + gr;
    size_t base0 = ((size_t)(b * SEQ + s0)) * DM + hd * DH;
    size_t base1 = ((size_t)(b * SEQ + s0 + 8)) * DM + hd * DH;
    #pragma unroll
    for (int j2 = 0; j2 < 16; j2++) {
        int d = j2 * 8 + gq * 2;
        uint32_t u0, u1;
        split_pack(hacc[j2][0] * li0, hacc[j2][1] * li0, u0, u1);
        *(uint32_t*)(g_hs[0] + base0 + d) = u0;
        *(uint32_t*)(g_hs[1] + base0 + d) = u1;
        split_pack(hacc[j2][2] * li1, hacc[j2][3] * li1, u0, u1);
        *(uint32_t*)(g_hs[0] + base1 + d) = u0;
        *(uint32_t*)(g_hs[1] + base1 + d) = u1;
    }
}

// ---------------------------------------------------------------------------
extern "C" void kernel_launch(void* const* d_in, const int* in_sizes, int n_in,
                              void* d_out, int out_size) {
    const float* x  = (const float*)d_in[0];
    const float* wq = (const float*)d_in[1];
    const float* wk = (const float*)d_in[2];
    const float* wv = (const float*)d_in[3];
    const float* wo = (const float*)d_in[4];
    const int* tok  = (const int*)d_in[5];
    float* out = (float*)d_out;

    cudaFuncSetAttribute(gemm_mma<0>,
                         cudaFuncAttributeMaxDynamicSharedMemorySize, GEMM_SMEM);
    cudaFuncSetAttribute(gemm_mma<1>,
                         cudaFuncAttributeMaxDynamicSharedMemorySize, GEMM_SMEM);
    cudaFuncSetAttribute(flash_mma,
                         cudaFuncAttributeMaxDynamicSharedMemorySize, FLASH_SMEM);

    // Launch indices: profiler lands on index 3 -> put QKV GEMM there.
    rope_table_kernel<<<SEQ, HALF>>>(tok);                           // 0
    split_all_kernel<<<(N4X + 4*N4W)/256, 256>>>(x, wq, wk, wv, wo); // 1
    rope_table_kernel<<<SEQ, HALF>>>(tok);                           // 2 (filler, idempotent)

    dim3 gq(DM / 128, MROWS / 128, 3);                               // 3: fused QKV
    gemm_mma<1><<<gq, 256, GEMM_SMEM>>>(nullptr);

    dim3 fgrid(SEQ / FQ, BATCH * NH);                                // 4
    flash_mma<<<fgrid, 256, FLASH_SMEM>>>();

    dim3 go(DM / 128, MROWS / 128);                                  // 5
    gemm_mma<0><<<go, 256, GEMM_SMEM>>>(out);
}

// round 9
// speedup vs baseline: 7.2695x; 1.0532x over previous
#include <cuda_runtime.h>
#include <cuda_bf16.h>
#include <math.h>
#include <stdint.h>

#define BATCH 2
#define SEQ 2048
#define DM 2048
#define NH 16
#define DH 128
#define MROWS (BATCH*SEQ)   // 4096
#define HALF (DH/2)         // 64

// ---------------------------------------------------------------------------
// Scratch (__device__ globals; allocation-free rule)
// ---------------------------------------------------------------------------
__device__ float2 g_rope[SEQ*HALF];
__device__ __nv_bfloat16 g_xs[2][MROWS*DM];          // x split planes
__device__ __nv_bfloat16 g_hs[2][MROWS*DM];          // attention-out split planes
__device__ __nv_bfloat16 g_ws[4][2][DM*DM];          // wq,wk,wv,wo split planes
__device__ __nv_bfloat16 g_qs[2][BATCH*NH*SEQ*DH];   // Q (post-RoPE) split planes
__device__ __nv_bfloat16 g_ks[2][BATCH*NH*SEQ*DH];
__device__ __nv_bfloat16 g_vs[2][BATCH*NH*SEQ*DH];

// ---------------------------------------------------------------------------
// Helpers
// ---------------------------------------------------------------------------
__device__ __forceinline__ uint32_t smem_u32(const void* p) {
    uint32_t a;
    asm("{ .reg .u64 t; cvta.to.shared.u64 t, %1; cvt.u32.u64 %0, t; }"
        : "=r"(a) : "l"(p));
    return a;
}
__device__ __forceinline__ void mma16816(float* d, const uint32_t* a,
                                         const uint32_t* b) {
    asm volatile(
        "mma.sync.aligned.m16n8k16.row.col.f32.bf16.bf16.f32 "
        "{%0,%1,%2,%3}, {%4,%5,%6,%7}, {%8,%9}, {%0,%1,%2,%3};\n"
        : "+f"(d[0]), "+f"(d[1]), "+f"(d[2]), "+f"(d[3])
        : "r"(a[0]), "r"(a[1]), "r"(a[2]), "r"(a[3]), "r"(b[0]), "r"(b[1]));
}
#define LDSM_X4(r0, r1, r2, r3, addr) \
    asm volatile("ldmatrix.sync.aligned.m8n8.x4.shared.b16 {%0,%1,%2,%3}, [%4];" \
        : "=r"(r0), "=r"(r1), "=r"(r2), "=r"(r3) : "r"(addr))
#define LDSM_X4_T(r0, r1, r2, r3, addr) \
    asm volatile("ldmatrix.sync.aligned.m8n8.x4.trans.shared.b16 {%0,%1,%2,%3}, [%4];" \
        : "=r"(r0), "=r"(r1), "=r"(r2), "=r"(r3) : "r"(addr))
#define CP_ASYNC16(dst, src) \
    asm volatile("cp.async.cg.shared.global [%0], [%1], 16;" :: "r"(dst), "l"(src))
#define CP_COMMIT() asm volatile("cp.async.commit_group;" ::: "memory")
#define CP_WAIT1()  asm volatile("cp.async.wait_group 1;" ::: "memory")

// split x,y to bf16 hi-planes (m0) and residual planes (m1), packed as b16x2
__device__ __forceinline__ void split_pack(float x, float y,
                                           uint32_t& m0, uint32_t& m1) {
    __nv_bfloat16 x0 = __float2bfloat16_rn(x);
    __nv_bfloat16 y0 = __float2bfloat16_rn(y);
    __nv_bfloat16 x1 = __float2bfloat16_rn(x - __bfloat162float(x0));
    __nv_bfloat16 y1 = __float2bfloat16_rn(y - __bfloat162float(y0));
    __nv_bfloat162 a = {x0, y0};
    __nv_bfloat162 b = {x1, y1};
    m0 = *(uint32_t*)&a;
    m1 = *(uint32_t*)&b;
}

// ---------------------------------------------------------------------------
// RoPE table (fp64-accurate angles, matching reference bit patterns)
// ---------------------------------------------------------------------------
__global__ void rope_table_kernel(const int* __restrict__ pos) {
    int s = blockIdx.x;
    int i = threadIdx.x;
    double inv = exp(-((double)(2 * i) / (double)DH) * log(10000.0));
    float invf = (float)inv;
    float freq = (float)pos[s] * invf;
    double a = (double)freq;
    g_rope[s * HALF + i] = make_float2((float)cos(a), (float)sin(a));
}

// ---------------------------------------------------------------------------
// Merged 2-way bf16 split: x + wq + wk + wv + wo in one launch.
// ---------------------------------------------------------------------------
#define N4X (MROWS*DM/4)   // 2^21
#define N4W (DM*DM/4)      // 2^20
__global__ void __launch_bounds__(256) split_all_kernel(
    const float* __restrict__ x,  const float* __restrict__ wq,
    const float* __restrict__ wk, const float* __restrict__ wv,
    const float* __restrict__ wo) {
    int i = blockIdx.x * 256 + threadIdx.x;
    const float* src;
    __nv_bfloat16* p0;
    __nv_bfloat16* p1;
    int idx;
    if (i < N4X) {
        src = x; p0 = g_xs[0]; p1 = g_xs[1]; idx = i;
    } else {
        int j = i - N4X;
        int wsel = j >> 20;
        idx = j & (N4W - 1);
        src = (wsel == 0) ? wq : (wsel == 1) ? wk : (wsel == 2) ? wv : wo;
        p0 = g_ws[wsel][0]; p1 = g_ws[wsel][1];
    }
    float4 a = ((const float4*)src)[idx];
    uint32_t u0a, u1a, u0b, u1b;
    split_pack(a.x, a.y, u0a, u1a);
    split_pack(a.z, a.w, u0b, u1b);
    ((uint32_t*)p0)[idx*2]   = u0a;
    ((uint32_t*)p0)[idx*2+1] = u0b;
    ((uint32_t*)p1)[idx*2]   = u1a;
    ((uint32_t*)p1)[idx*2+1] = u1b;
}

// ---------------------------------------------------------------------------
// mma.sync bf16 GEMM, fp32 emulation (3 cross-terms of 2-way split).
// 64x64 warp tiles (4 warps / 128 threads, CTA 128x128) -> halves LDSM bytes
// per MMA; 3-stage cp.async, XOR-swizzled smem, one barrier per K-block.
// Per-acc term/k order preserved -> bit-identical numerics.
// ---------------------------------------------------------------------------
#define BK 32
#define NKB (DM/BK)            // 64
#define TILE_B 8192            // 128 rows * 64 B
#define STAGE_B (4*TILE_B)     // 32768
#define GEMM_SMEM (3*STAGE_B)  // 98304

template<int MODE>
__global__ void __launch_bounds__(128, 2) gemm_mma(float* __restrict__ Out) {
    extern __shared__ __align__(128) __nv_bfloat16 dsm[];
    uint32_t sbase = smem_u32(dsm);

    int tid = threadIdx.x;
    int lane = tid & 31;
    int wid = tid >> 5;          // 0..3
    int m0 = blockIdx.y * 128;
    int n0 = blockIdx.x * 128;
    int z = (MODE == 1) ? blockIdx.z : 3;
    int wm = (wid & 1) * 64;
    int wn = (wid >> 1) * 64;
    int gr = lane >> 2;
    int gq = lane & 3;
    int lq = lane & 7;
    int quad = lane >> 3;

    const __nv_bfloat16* srcs[4];
    srcs[0] = ((MODE == 0) ? g_hs[0] : g_xs[0]) + (size_t)m0 * DM;
    srcs[1] = ((MODE == 0) ? g_hs[1] : g_xs[1]) + (size_t)m0 * DM;
    srcs[2] = g_ws[z][0] + (size_t)n0 * DM;
    srcs[3] = g_ws[z][1] + (size_t)n0 * DM;

    // Swizzled store: granule (r,c) at r*64 + ((c ^ (r&3))<<4). 128 threads.
    #define LOAD_STAGE(kb, st) { \
        int k0 = (kb) * BK; \
        _Pragma("unroll") \
        for (int it = 0; it < 16; it++) { \
            int e = tid + it * 128; \
            int t = e >> 9; \
            int e5 = e & 511; \
            int r = e5 >> 2; \
            int c = e5 & 3; \
            const __nv_bfloat16* src = srcs[t] + (size_t)r * DM + k0 + c * 8; \
            uint32_t dst = sbase + (st) * STAGE_B + t * TILE_B + r * 64 \
                         + ((c ^ (r & 3)) << 4); \
            CP_ASYNC16(dst, src); \
        } }

    LOAD_STAGE(0, 0) CP_COMMIT();
    LOAD_STAGE(1, 1) CP_COMMIT();

    float acc[4][8][4] = {};

    int arow = lq + (quad & 1) * 8;
    int sa = arow & 3;
    int ca0 = (quad >> 1);
    int brow = lq + (quad >> 1) * 8;
    int sb2 = brow & 3;
    int cb0 = (quad & 1);

    int stc = 0;
    int stn = 2;
    for (int kb = 0; kb < NKB; kb++) {
        CP_WAIT1();
        __syncthreads();
        if (kb + 2 < NKB) { LOAD_STAGE(kb + 2, stn) }
        CP_COMMIT();

        uint32_t tb = sbase + stc * STAGE_B;
        #pragma unroll
        for (int ks = 0; ks < BK; ks += 16) {
            int cga = (ks >> 3) + ca0;
            int cgb = (ks >> 3) + cb0;
            uint32_t aoff = ((cga ^ sa) << 4) + arow * 64;
            uint32_t boff = ((cgb ^ sb2) << 4) + brow * 64;
            // A fragments resident: 2 planes x 4 m16 tiles (32 regs)
            uint32_t af[2][4][4];
            #pragma unroll
            for (int i = 0; i < 4; i++) {
                LDSM_X4(af[0][i][0], af[0][i][1], af[0][i][2], af[0][i][3],
                        tb + 0 * TILE_B + (wm + i * 16) * 64 + aoff);
                LDSM_X4(af[1][i][0], af[1][i][1], af[1][i][2], af[1][i][3],
                        tb + 1 * TILE_B + (wm + i * 16) * 64 + aoff);
            }
            // B streamed per jj-pair over 64-wide warp tile (8 n8 tiles)
            #pragma unroll
            for (int jj = 0; jj < 8; jj += 2) {
                uint32_t bf0[2][2], bf1[2][2];
                LDSM_X4(bf0[0][0], bf0[0][1], bf0[1][0], bf0[1][1],
                        tb + 2 * TILE_B + (wn + jj * 8) * 64 + boff);
                LDSM_X4(bf1[0][0], bf1[0][1], bf1[1][0], bf1[1][1],
                        tb + 3 * TILE_B + (wn + jj * 8) * 64 + boff);
                #pragma unroll
                for (int c = 0; c < 2; c++)
                    #pragma unroll
                    for (int i = 0; i < 4; i++)
                        mma16816(acc[i][jj+c], af[0][i], bf0[c]);
                #pragma unroll
                for (int c = 0; c < 2; c++)
                    #pragma unroll
                    for (int i = 0; i < 4; i++)
                        mma16816(acc[i][jj+c], af[0][i], bf1[c]);
                #pragma unroll
                for (int c = 0; c < 2; c++)
                    #pragma unroll
                    for (int i = 0; i < 4; i++)
                        mma16816(acc[i][jj+c], af[1][i], bf0[c]);
            }
        }
        stc = (stc == 2) ? 0 : stc + 1;
        stn = (stn == 2) ? 0 : stn + 1;
    }
    #undef LOAD_STAGE

    int h = blockIdx.x;   // BN == DH
    #pragma unroll
    for (int i = 0; i < 4; i++) {
        #pragma unroll
        for (int half = 0; half < 2; half++) {
            int row = m0 + wm + i * 16 + gr + half * 8;
            int s = row & (SEQ - 1);
            int b = row >> 11;
            #pragma unroll
            for (int j = 0; j < 8; j++) {
                int d = wn + j * 8 + gq * 2;
                float e = acc[i][j][half * 2 + 0];
                float o = acc[i][j][half * 2 + 1];
                if (MODE == 0) {
                    *(float2*)(Out + (size_t)row * DM + n0 + d) =
                        make_float2(e, o);
                } else {
                    if (z < 2) {
                        float2 cs = g_rope[s * HALF + (d >> 1)];
                        float e2 = e * cs.x - o * cs.y;
                        o = e * cs.y + o * cs.x;
                        e = e2;
                    }
                    __nv_bfloat16* t0 = (z == 0) ? g_qs[0] : (z == 1) ? g_ks[0] : g_vs[0];
                    __nv_bfloat16* t1 = (z == 0) ? g_qs[1] : (z == 1) ? g_ks[1] : g_vs[1];
                    size_t off = ((size_t)(b * NH + h) * SEQ + s) * DH + d;
                    uint32_t u0, u1;
                    split_pack(e, o, u0, u1);
                    *(uint32_t*)(t0 + off) = u0;
                    *(uint32_t*)(t1 + off) = u1;
                }
            }
        }
    }
}

// ---------------------------------------------------------------------------
// Tensor-core flash attention, fp32-emulated bf16 (3-term). Unchanged.
// ---------------------------------------------------------------------------
#define TS 136   // smem row stride bf16 (272B)
#define FQ 128
#define FK 64
#define QOFF 0
#define KOFF (2*FQ*TS)             // 34816
#define VOFF (KOFF + 4*FK*TS)      // 69632
#define FLASH_SMEM ((VOFF + 4*FK*TS)*2)  // 208896 B

__global__ void __launch_bounds__(256, 1) flash_mma() {
    extern __shared__ __align__(16) __nv_bfloat16 fsm[];
    uint32_t sb = smem_u32(fsm);
    int tid = threadIdx.x;
    int lane = tid & 31;
    int w = tid >> 5;
    int gr = lane >> 2;
    int gq = lane & 3;
    int lq = lane & 7;
    int quad = lane >> 3;
    int bh = blockIdx.y;
    int qt = (int)gridDim.x - 1 - (int)blockIdx.x;   // heavy tiles first
    int nkv = 2 * qt + 2;

    const __nv_bfloat16* qsrc[2] = {
        g_qs[0] + ((size_t)bh * SEQ + qt * FQ) * DH,
        g_qs[1] + ((size_t)bh * SEQ + qt * FQ) * DH };
    const __nv_bfloat16* ksrc[2] = {
        g_ks[0] + (size_t)bh * SEQ * DH, g_ks[1] + (size_t)bh * SEQ * DH };
    const __nv_bfloat16* vsrc[2] = {
        g_vs[0] + (size_t)bh * SEQ * DH, g_vs[1] + (size_t)bh * SEQ * DH };

    #define LOADKV(kt_, st_) { \
        _Pragma("unroll") \
        for (int it = 0; it < 8; it++) { \
            int e = tid + it * 256; \
            int p = e >> 10; \
            int r = (e >> 4) & 63; \
            int c = (e & 15) * 8; \
            CP_ASYNC16(sb + (KOFF + ((st_) * 2 + p) * FK * TS + r * TS + c) * 2, \
                       ksrc[p] + ((size_t)(kt_) * FK + r) * DH + c); \
            CP_ASYNC16(sb + (VOFF + ((st_) * 2 + p) * FK * TS + r * TS + c) * 2, \
                       vsrc[p] + ((size_t)(kt_) * FK + r) * DH + c); \
        } }

    #pragma unroll
    for (int it = 0; it < 16; it++) {
        int e = tid + it * 256;
        int p = e >> 11;
        int r = (e >> 4) & 127;
        int c = (e & 15) * 8;
        CP_ASYNC16(sb + (QOFF + p * FQ * TS + r * TS + c) * 2,
                   qsrc[p] + (size_t)r * DH + c);
    }
    LOADKV(0, 0)
    CP_COMMIT();
    LOADKV(1, 1)
    CP_COMMIT();

    float hacc[16][4] = {};
    float mrow0 = -INFINITY, mrow1 = -INFINITY;
    float lrow0 = 0.f, lrow1 = 0.f;
    const float scale = 0.08838834764831845f;   // 1/sqrt(128)

    int arow = lq + (quad & 1) * 8;
    int acolh = (quad >> 1) * 8;
    int brow = lq + (quad >> 1) * 8;
    int bcolh = (quad & 1) * 8;
    int qrow0 = qt * FQ + w * 16 + gr;

    for (int kt = 0; kt < nkv; kt++) {
        int st = kt & 1;
        CP_WAIT1();
        __syncthreads();

        bool fullmask = (kt == 2 * qt + 1) && (w < 4);
        if (!fullmask) {

        float sacc[8][4] = {};
        uint32_t qb0 = sb + (QOFF + (w * 16 + arow) * TS) * 2;
        uint32_t qb1 = qb0 + (FQ * TS) * 2;
        uint32_t kb0 = sb + (KOFF + (st * 2 + 0) * FK * TS) * 2;
        uint32_t kb1 = sb + (KOFF + (st * 2 + 1) * FK * TS) * 2;
        #pragma unroll
        for (int t = 0; t < 8; t++) {
            uint32_t a0[4], a1[4];
            LDSM_X4(a0[0], a0[1], a0[2], a0[3], qb0 + (16 * t + acolh) * 2);
            LDSM_X4(a1[0], a1[1], a1[2], a1[3], qb1 + (16 * t + acolh) * 2);
            uint32_t b0[8][2], b1[8][2];
            #pragma unroll
            for (int j = 0; j < 8; j += 2) {
                LDSM_X4(b0[j][0], b0[j][1], b0[j+1][0], b0[j+1][1],
                        kb0 + ((j * 8 + brow) * TS + 16 * t + bcolh) * 2);
                LDSM_X4(b1[j][0], b1[j][1], b1[j+1][0], b1[j+1][1],
                        kb1 + ((j * 8 + brow) * TS + 16 * t + bcolh) * 2);
            }
            #pragma unroll
            for (int j = 0; j < 8; j++) mma16816(sacc[j], a0, b0[j]);
            #pragma unroll
            for (int j = 0; j < 8; j++) mma16816(sacc[j], a0, b1[j]);
            #pragma unroll
            for (int j = 0; j < 8; j++) mma16816(sacc[j], a1, b0[j]);
        }

        bool maskblk = (kt >= 2 * qt);
        float mx0 = mrow0, mx1 = mrow1;
        #pragma unroll
        for (int j = 0; j < 8; j++) {
            int col = kt * FK + j * 8 + gq * 2;
            #pragma unroll
            for (int e = 0; e < 4; e++) {
                float v = sacc[j][e] * scale;
                if (maskblk) {
                    int cc = col + (e & 1);
                    int rr = qrow0 + (e >> 1) * 8;
                    if (cc > rr) v = -1e30f;
                }
                sacc[j][e] = v;
                if (e < 2) mx0 = fmaxf(mx0, v);
                else       mx1 = fmaxf(mx1, v);
            }
        }
        mx0 = fmaxf(mx0, __shfl_xor_sync(0xffffffffu, mx0, 1));
        mx0 = fmaxf(mx0, __shfl_xor_sync(0xffffffffu, mx0, 2));
        mx1 = fmaxf(mx1, __shfl_xor_sync(0xffffffffu, mx1, 1));
        mx1 = fmaxf(mx1, __shfl_xor_sync(0xffffffffu, mx1, 2));
        float c0 = __expf(mrow0 - mx0);
        float c1 = __expf(mrow1 - mx1);
        mrow0 = mx0; mrow1 = mx1;
        #pragma unroll
        for (int j2 = 0; j2 < 16; j2++) {
            hacc[j2][0] *= c0; hacc[j2][1] *= c0;
            hacc[j2][2] *= c1; hacc[j2][3] *= c1;
        }

        float lt0 = 0.f, lt1 = 0.f;
        uint32_t pa0[4][4], pa1[4][4];
        #pragma unroll
        for (int t = 0; t < 4; t++) {
            #pragma unroll
            for (int half = 0; half < 2; half++) {
                int j = 2 * t + half;
                float p0 = __expf(sacc[j][0] - mx0);
                float p1 = __expf(sacc[j][1] - mx0);
                float p2 = __expf(sacc[j][2] - mx1);
                float p3 = __expf(sacc[j][3] - mx1);
                lt0 += p0 + p1;
                lt1 += p2 + p3;
                split_pack(p0, p1, pa0[t][half*2+0], pa1[t][half*2+0]);
                split_pack(p2, p3, pa0[t][half*2+1], pa1[t][half*2+1]);
            }
        }
        lt0 += __shfl_xor_sync(0xffffffffu, lt0, 1);
        lt0 += __shfl_xor_sync(0xffffffffu, lt0, 2);
        lt1 += __shfl_xor_sync(0xffffffffu, lt1, 1);
        lt1 += __shfl_xor_sync(0xffffffffu, lt1, 2);
        lrow0 = lrow0 * c0 + lt0;
        lrow1 = lrow1 * c1 + lt1;

        uint32_t vb0 = sb + (VOFF + (st * 2 + 0) * FK * TS) * 2;
        uint32_t vb1 = sb + (VOFF + (st * 2 + 1) * FK * TS) * 2;
        int vrow = lq + (quad & 1) * 8;
        int vcolh = (quad >> 1) * 8;
        #pragma unroll
        for (int t = 0; t < 4; t++) {
            #pragma unroll
            for (int j4 = 0; j4 < 16; j4 += 4) {
                uint32_t bv0[4][2], bv1[4][2];
                LDSM_X4_T(bv0[0][0], bv0[0][1], bv0[1][0], bv0[1][1],
                          vb0 + ((16 * t + vrow) * TS + 8 * j4 + vcolh) * 2);
                LDSM_X4_T(bv0[2][0], bv0[2][1], bv0[3][0], bv0[3][1],
                          vb0 + ((16 * t + vrow) * TS + 8 * (j4 + 2) + vcolh) * 2);
                LDSM_X4_T(bv1[0][0], bv1[0][1], bv1[1][0], bv1[1][1],
                          vb1 + ((16 * t + vrow) * TS + 8 * j4 + vcolh) * 2);
                LDSM_X4_T(bv1[2][0], bv1[2][1], bv1[3][0], bv1[3][1],
                          vb1 + ((16 * t + vrow) * TS + 8 * (j4 + 2) + vcolh) * 2);
                #pragma unroll
                for (int c = 0; c < 4; c++) mma16816(hacc[j4+c], pa0[t], bv0[c]);
                #pragma unroll
                for (int c = 0; c < 4; c++) mma16816(hacc[j4+c], pa0[t], bv1[c]);
                #pragma unroll
                for (int c = 0; c < 4; c++) mma16816(hacc[j4+c], pa1[t], bv0[c]);
            }
        }

        }  // !fullmask

        __syncthreads();
        if (kt + 2 < nkv) { LOADKV(kt + 2, st) }
        CP_COMMIT();
    }
    #undef LOADKV

    float li0 = 1.f / lrow0;
    float li1 = 1.f / lrow1;
    int b = bh >> 4;
    int hd = bh & (NH - 1);
    int s0 = qt * FQ + w * 16 + gr;
    size_t base0 = ((size_t)(b * SEQ + s0)) * DM + hd * DH;
    size_t base1 = ((size_t)(b * SEQ + s0 + 8)) * DM + hd * DH;
    #pragma unroll
    for (int j2 = 0; j2 < 16; j2++) {
        int d = j2 * 8 + gq * 2;
        uint32_t u0, u1;
        split_pack(hacc[j2][0] * li0, hacc[j2][1] * li0, u0, u1);
        *(uint32_t*)(g_hs[0] + base0 + d) = u0;
        *(uint32_t*)(g_hs[1] + base0 + d) = u1;
        split_pack(hacc[j2][2] * li1, hacc[j2][3] * li1, u0, u1);
        *(uint32_t*)(g_hs[0] + base1 + d) = u0;
        *(uint32_t*)(g_hs[1] + base1 + d) = u1;
    }
}

// ---------------------------------------------------------------------------
extern "C" void kernel_launch(void* const* d_in, const int* in_sizes, int n_in,
                              void* d_out, int out_size) {
    const float* x  = (const float*)d_in[0];
    const float* wq = (const float*)d_in[1];
    const float* wk = (const float*)d_in[2];
    const float* wv = (const float*)d_in[3];
    const float* wo = (const float*)d_in[4];
    const int* tok  = (const int*)d_in[5];
    float* out = (float*)d_out;

    cudaFuncSetAttribute(gemm_mma<0>,
                         cudaFuncAttributeMaxDynamicSharedMemorySize, GEMM_SMEM);
    cudaFuncSetAttribute(gemm_mma<1>,
                         cudaFuncAttributeMaxDynamicSharedMemorySize, GEMM_SMEM);
    cudaFuncSetAttribute(flash_mma,
                         cudaFuncAttributeMaxDynamicSharedMemorySize, FLASH_SMEM);

    rope_table_kernel<<<SEQ, HALF>>>(tok);                           // 0
    split_all_kernel<<<(N4X + 4*N4W)/256, 256>>>(x, wq, wk, wv, wo); // 1

    dim3 gq(DM / 128, MROWS / 128, 3);                               // 2: fused QKV
    gemm_mma<1><<<gq, 128, GEMM_SMEM>>>(nullptr);

    dim3 fgrid(SEQ / FQ, BATCH * NH);                                // 3: flash (profiled)
    flash_mma<<<fgrid, 256, FLASH_SMEM>>>();

    dim3 go(DM / 128, MROWS / 128);                                  // 4
    gemm_mma<0><<<go, 128, GEMM_SMEM>>>(out);
}

// round 10
// speedup vs baseline: 7.2824x; 1.0018x over previous
#include <cuda_runtime.h>
#include <cuda_bf16.h>
#include <math.h>
#include <stdint.h>

#define BATCH 2
#define SEQ 2048
#define DM 2048
#define NH 16
#define DH 128
#define MROWS (BATCH*SEQ)   // 4096
#define HALF (DH/2)         // 64

// ---------------------------------------------------------------------------
// Scratch (__device__ globals; allocation-free rule)
// ---------------------------------------------------------------------------
__device__ float2 g_rope[SEQ*HALF];
__device__ __nv_bfloat16 g_xs[2][MROWS*DM];          // x split planes
__device__ __nv_bfloat16 g_hs[2][MROWS*DM];          // attention-out split planes
__device__ __nv_bfloat16 g_ws[4][2][DM*DM];          // wq,wk,wv,wo split planes
__device__ __nv_bfloat16 g_qs[2][BATCH*NH*SEQ*DH];   // Q (post-RoPE) split planes
__device__ __nv_bfloat16 g_ks[2][BATCH*NH*SEQ*DH];
__device__ __nv_bfloat16 g_vs[2][BATCH*NH*SEQ*DH];

// ---------------------------------------------------------------------------
// Helpers
// ---------------------------------------------------------------------------
__device__ __forceinline__ uint32_t smem_u32(const void* p) {
    uint32_t a;
    asm("{ .reg .u64 t; cvta.to.shared.u64 t, %1; cvt.u32.u64 %0, t; }"
        : "=r"(a) : "l"(p));
    return a;
}
__device__ __forceinline__ void mma16816(float* d, const uint32_t* a,
                                         const uint32_t* b) {
    asm volatile(
        "mma.sync.aligned.m16n8k16.row.col.f32.bf16.bf16.f32 "
        "{%0,%1,%2,%3}, {%4,%5,%6,%7}, {%8,%9}, {%0,%1,%2,%3};\n"
        : "+f"(d[0]), "+f"(d[1]), "+f"(d[2]), "+f"(d[3])
        : "r"(a[0]), "r"(a[1]), "r"(a[2]), "r"(a[3]), "r"(b[0]), "r"(b[1]));
}
#define LDSM_X4(r0, r1, r2, r3, addr) \
    asm volatile("ldmatrix.sync.aligned.m8n8.x4.shared.b16 {%0,%1,%2,%3}, [%4];" \
        : "=r"(r0), "=r"(r1), "=r"(r2), "=r"(r3) : "r"(addr))
#define LDSM_X4_T(r0, r1, r2, r3, addr) \
    asm volatile("ldmatrix.sync.aligned.m8n8.x4.trans.shared.b16 {%0,%1,%2,%3}, [%4];" \
        : "=r"(r0), "=r"(r1), "=r"(r2), "=r"(r3) : "r"(addr))
#define CP_ASYNC16(dst, src) \
    asm volatile("cp.async.cg.shared.global [%0], [%1], 16;" :: "r"(dst), "l"(src))
#define CP_COMMIT() asm volatile("cp.async.commit_group;" ::: "memory")
#define CP_WAIT1()  asm volatile("cp.async.wait_group 1;" ::: "memory")
#define CP_WAIT2()  asm volatile("cp.async.wait_group 2;" ::: "memory")

// split x,y to bf16 hi-planes (m0) and residual planes (m1), packed as b16x2
__device__ __forceinline__ void split_pack(float x, float y,
                                           uint32_t& m0, uint32_t& m1) {
    __nv_bfloat16 x0 = __float2bfloat16_rn(x);
    __nv_bfloat16 y0 = __float2bfloat16_rn(y);
    __nv_bfloat16 x1 = __float2bfloat16_rn(x - __bfloat162float(x0));
    __nv_bfloat16 y1 = __float2bfloat16_rn(y - __bfloat162float(y0));
    __nv_bfloat162 a = {x0, y0};
    __nv_bfloat162 b = {x1, y1};
    m0 = *(uint32_t*)&a;
    m1 = *(uint32_t*)&b;
}

// ---------------------------------------------------------------------------
// RoPE table (fp64-accurate angles, matching reference bit patterns)
// ---------------------------------------------------------------------------
__global__ void rope_table_kernel(const int* __restrict__ pos) {
    int s = blockIdx.x;
    int i = threadIdx.x;
    double inv = exp(-((double)(2 * i) / (double)DH) * log(10000.0));
    float invf = (float)inv;
    float freq = (float)pos[s] * invf;
    double a = (double)freq;
    g_rope[s * HALF + i] = make_float2((float)cos(a), (float)sin(a));
}

// ---------------------------------------------------------------------------
// Merged 2-way bf16 split: x + wq + wk + wv + wo in one launch.
// ---------------------------------------------------------------------------
#define N4X (MROWS*DM/4)   // 2^21
#define N4W (DM*DM/4)      // 2^20
__global__ void __launch_bounds__(256) split_all_kernel(
    const float* __restrict__ x,  const float* __restrict__ wq,
    const float* __restrict__ wk, const float* __restrict__ wv,
    const float* __restrict__ wo) {
    int i = blockIdx.x * 256 + threadIdx.x;
    const float* src;
    __nv_bfloat16* p0;
    __nv_bfloat16* p1;
    int idx;
    if (i < N4X) {
        src = x; p0 = g_xs[0]; p1 = g_xs[1]; idx = i;
    } else {
        int j = i - N4X;
        int wsel = j >> 20;
        idx = j & (N4W - 1);
        src = (wsel == 0) ? wq : (wsel == 1) ? wk : (wsel == 2) ? wv : wo;
        p0 = g_ws[wsel][0]; p1 = g_ws[wsel][1];
    }
    float4 a = ((const float4*)src)[idx];
    uint32_t u0a, u1a, u0b, u1b;
    split_pack(a.x, a.y, u0a, u1a);
    split_pack(a.z, a.w, u0b, u1b);
    ((uint32_t*)p0)[idx*2]   = u0a;
    ((uint32_t*)p0)[idx*2+1] = u0b;
    ((uint32_t*)p1)[idx*2]   = u1a;
    ((uint32_t*)p1)[idx*2+1] = u1b;
}

// ---------------------------------------------------------------------------
// mma.sync bf16 GEMM (unchanged from R9): 64x64 warp tiles, 4 warps,
// 3-stage cp.async, XOR swizzle, one barrier per K-block, 2 CTAs/SM.
// ---------------------------------------------------------------------------
#define BK 32
#define NKB (DM/BK)            // 64
#define TILE_B 8192            // 128 rows * 64 B
#define STAGE_B (4*TILE_B)     // 32768
#define GEMM_SMEM (3*STAGE_B)  // 98304

template<int MODE>
__global__ void __launch_bounds__(128, 2) gemm_mma(float* __restrict__ Out) {
    extern __shared__ __align__(128) __nv_bfloat16 dsm[];
    uint32_t sbase = smem_u32(dsm);

    int tid = threadIdx.x;
    int lane = tid & 31;
    int wid = tid >> 5;          // 0..3
    int m0 = blockIdx.y * 128;
    int n0 = blockIdx.x * 128;
    int z = (MODE == 1) ? blockIdx.z : 3;
    int wm = (wid & 1) * 64;
    int wn = (wid >> 1) * 64;
    int gr = lane >> 2;
    int gq = lane & 3;
    int lq = lane & 7;
    int quad = lane >> 3;

    const __nv_bfloat16* srcs[4];
    srcs[0] = ((MODE == 0) ? g_hs[0] : g_xs[0]) + (size_t)m0 * DM;
    srcs[1] = ((MODE == 0) ? g_hs[1] : g_xs[1]) + (size_t)m0 * DM;
    srcs[2] = g_ws[z][0] + (size_t)n0 * DM;
    srcs[3] = g_ws[z][1] + (size_t)n0 * DM;

    #define LOAD_STAGE(kb, st) { \
        int k0 = (kb) * BK; \
        _Pragma("unroll") \
        for (int it = 0; it < 16; it++) { \
            int e = tid + it * 128; \
            int t = e >> 9; \
            int e5 = e & 511; \
            int r = e5 >> 2; \
            int c = e5 & 3; \
            const __nv_bfloat16* src = srcs[t] + (size_t)r * DM + k0 + c * 8; \
            uint32_t dst = sbase + (st) * STAGE_B + t * TILE_B + r * 64 \
                         + ((c ^ (r & 3)) << 4); \
            CP_ASYNC16(dst, src); \
        } }

    LOAD_STAGE(0, 0) CP_COMMIT();
    LOAD_STAGE(1, 1) CP_COMMIT();

    float acc[4][8][4] = {};

    int arow = lq + (quad & 1) * 8;
    int sa = arow & 3;
    int ca0 = (quad >> 1);
    int brow = lq + (quad >> 1) * 8;
    int sb2 = brow & 3;
    int cb0 = (quad & 1);

    int stc = 0;
    int stn = 2;
    for (int kb = 0; kb < NKB; kb++) {
        CP_WAIT1();
        __syncthreads();
        if (kb + 2 < NKB) { LOAD_STAGE(kb + 2, stn) }
        CP_COMMIT();

        uint32_t tb = sbase + stc * STAGE_B;
        #pragma unroll
        for (int ks = 0; ks < BK; ks += 16) {
            int cga = (ks >> 3) + ca0;
            int cgb = (ks >> 3) + cb0;
            uint32_t aoff = ((cga ^ sa) << 4) + arow * 64;
            uint32_t boff = ((cgb ^ sb2) << 4) + brow * 64;
            uint32_t af[2][4][4];
            #pragma unroll
            for (int i = 0; i < 4; i++) {
                LDSM_X4(af[0][i][0], af[0][i][1], af[0][i][2], af[0][i][3],
                        tb + 0 * TILE_B + (wm + i * 16) * 64 + aoff);
                LDSM_X4(af[1][i][0], af[1][i][1], af[1][i][2], af[1][i][3],
                        tb + 1 * TILE_B + (wm + i * 16) * 64 + aoff);
            }
            #pragma unroll
            for (int jj = 0; jj < 8; jj += 2) {
                uint32_t bf0[2][2], bf1[2][2];
                LDSM_X4(bf0[0][0], bf0[0][1], bf0[1][0], bf0[1][1],
                        tb + 2 * TILE_B + (wn + jj * 8) * 64 + boff);
                LDSM_X4(bf1[0][0], bf1[0][1], bf1[1][0], bf1[1][1],
                        tb + 3 * TILE_B + (wn + jj * 8) * 64 + boff);
                #pragma unroll
                for (int c = 0; c < 2; c++)
                    #pragma unroll
                    for (int i = 0; i < 4; i++)
                        mma16816(acc[i][jj+c], af[0][i], bf0[c]);
                #pragma unroll
                for (int c = 0; c < 2; c++)
                    #pragma unroll
                    for (int i = 0; i < 4; i++)
                        mma16816(acc[i][jj+c], af[0][i], bf1[c]);
                #pragma unroll
                for (int c = 0; c < 2; c++)
                    #pragma unroll
                    for (int i = 0; i < 4; i++)
                        mma16816(acc[i][jj+c], af[1][i], bf0[c]);
            }
        }
        stc = (stc == 2) ? 0 : stc + 1;
        stn = (stn == 2) ? 0 : stn + 1;
    }
    #undef LOAD_STAGE

    int h = blockIdx.x;   // BN == DH
    #pragma unroll
    for (int i = 0; i < 4; i++) {
        #pragma unroll
        for (int half = 0; half < 2; half++) {
            int row = m0 + wm + i * 16 + gr + half * 8;
            int s = row & (SEQ - 1);
            int b = row >> 11;
            #pragma unroll
            for (int j = 0; j < 8; j++) {
                int d = wn + j * 8 + gq * 2;
                float e = acc[i][j][half * 2 + 0];
                float o = acc[i][j][half * 2 + 1];
                if (MODE == 0) {
                    *(float2*)(Out + (size_t)row * DM + n0 + d) =
                        make_float2(e, o);
                } else {
                    if (z < 2) {
                        float2 cs = g_rope[s * HALF + (d >> 1)];
                        float e2 = e * cs.x - o * cs.y;
                        o = e * cs.y + o * cs.x;
                        e = e2;
                    }
                    __nv_bfloat16* t0 = (z == 0) ? g_qs[0] : (z == 1) ? g_ks[0] : g_vs[0];
                    __nv_bfloat16* t1 = (z == 0) ? g_qs[1] : (z == 1) ? g_ks[1] : g_vs[1];
                    size_t off = ((size_t)(b * NH + h) * SEQ + s) * DH + d;
                    uint32_t u0, u1;
                    split_pack(e, o, u0, u1);
                    *(uint32_t*)(t0 + off) = u0;
                    *(uint32_t*)(t1 + off) = u1;
                }
            }
        }
    }
}

// ---------------------------------------------------------------------------
// Tensor-core flash attention v2: FQ=64, FK=32, 128 threads (4 warps),
// 104 KB smem -> 2 CTAs/SM; Q fragments register-resident (loaded once).
// fp32-emulated bf16 (3-term), term-major MMAs.
// ---------------------------------------------------------------------------
#define TS 136                 // smem row stride bf16 (272B)
#define FQ 64
#define FK 32
#define QPL (FQ*TS)            // 8704 bf16 per Q plane
#define KOFF (2*QPL)           // 17408
#define KBLK (FK*TS)           // 4352 bf16 per K/V stage-plane block
#define VOFF (KOFF + 4*KBLK)   // 34816
#define FLASH_SMEM ((VOFF + 4*KBLK)*2)  // 104448 B

__global__ void __launch_bounds__(128, 2) flash_mma() {
    extern __shared__ __align__(16) __nv_bfloat16 fsm[];
    uint32_t sb = smem_u32(fsm);
    int tid = threadIdx.x;
    int lane = tid & 31;
    int w = tid >> 5;            // 0..3, warp = 16 q-rows
    int gr = lane >> 2;
    int gq = lane & 3;
    int lq = lane & 7;
    int quad = lane >> 3;
    int bh = blockIdx.y;
    int qt = (int)gridDim.x - 1 - (int)blockIdx.x;   // heavy tiles first
    int nkv = 2 * qt + 2;                            // FK=32 blocks

    const __nv_bfloat16* qsrc[2] = {
        g_qs[0] + ((size_t)bh * SEQ + qt * FQ) * DH,
        g_qs[1] + ((size_t)bh * SEQ + qt * FQ) * DH };
    const __nv_bfloat16* ksrc[2] = {
        g_ks[0] + (size_t)bh * SEQ * DH, g_ks[1] + (size_t)bh * SEQ * DH };
    const __nv_bfloat16* vsrc[2] = {
        g_vs[0] + (size_t)bh * SEQ * DH, g_vs[1] + (size_t)bh * SEQ * DH };

    // KV stage load: K,V x 2 planes x 32 rows x 256B = 32 KB, 16 chunks/thread
    #define LOADKV(kt_, st_) { \
        _Pragma("unroll") \
        for (int it = 0; it < 16; it++) { \
            int e = tid + it * 128; \
            int r = (e >> 4) & 31; \
            int c = (e & 15) * 8; \
            int p = (e >> 9) & 1; \
            uint32_t off = (((st_) * 2 + p) * KBLK + r * TS + c) * 2; \
            if (e < 1024) \
                CP_ASYNC16(sb + KOFF * 2 + off, \
                           ksrc[p] + ((size_t)(kt_) * FK + r) * DH + c); \
            else \
                CP_ASYNC16(sb + VOFF * 2 + off, \
                           vsrc[p] + ((size_t)(kt_) * FK + r) * DH + c); \
        } }

    // Q load: 2 planes x 64 rows x 256B = 32 KB, 16 chunks/thread
    #pragma unroll
    for (int it = 0; it < 16; it++) {
        int e = tid + it * 128;
        int p = e >> 10;
        int r = (e >> 4) & 63;
        int c = (e & 15) * 8;
        CP_ASYNC16(sb + (p * QPL + r * TS + c) * 2,
                   qsrc[p] + (size_t)r * DH + c);
    }
    CP_COMMIT();
    LOADKV(0, 0)
    CP_COMMIT();
    LOADKV(1, 1)
    CP_COMMIT();

    int arow = lq + (quad & 1) * 8;
    int acolh = (quad >> 1) * 8;
    int brow = lq + (quad >> 1) * 8;
    int bcolh = (quad & 1) * 8;
    int vrow = lq + (quad & 1) * 8;
    int vcolh = (quad >> 1) * 8;
    int qrow0 = qt * FQ + w * 16 + gr;

    // Q fragments resident: 2 planes x 8 k16 tiles x 4 regs = 64 regs
    CP_WAIT2();
    __syncthreads();
    uint32_t qf0[8][4], qf1[8][4];
    {
        uint32_t qb0 = sb + ((w * 16 + arow) * TS) * 2;
        uint32_t qb1 = qb0 + QPL * 2;
        #pragma unroll
        for (int t = 0; t < 8; t++) {
            LDSM_X4(qf0[t][0], qf0[t][1], qf0[t][2], qf0[t][3],
                    qb0 + (16 * t + acolh) * 2);
            LDSM_X4(qf1[t][0], qf1[t][1], qf1[t][2], qf1[t][3],
                    qb1 + (16 * t + acolh) * 2);
        }
    }

    float hacc[16][4] = {};
    float mrow0 = -INFINITY, mrow1 = -INFINITY;
    float lrow0 = 0.f, lrow1 = 0.f;
    const float scale = 0.08838834764831845f;   // 1/sqrt(128)

    for (int kt = 0; kt < nkv; kt++) {
        int st = kt & 1;
        CP_WAIT1();
        __syncthreads();

        // Fully-masked warp-block (cols all > rows): exact no-op, skip.
        bool fullmask = (32 * kt > qt * FQ + w * 16 + 15);
        if (!fullmask) {

        // ---- S = Q K^T (emulated), term-major; Q from registers ----
        float sacc[4][4] = {};
        uint32_t kb0 = sb + (KOFF + (st * 2 + 0) * KBLK) * 2;
        uint32_t kb1 = sb + (KOFF + (st * 2 + 1) * KBLK) * 2;
        #pragma unroll
        for (int t = 0; t < 8; t++) {
            uint32_t b0[4][2], b1[4][2];
            #pragma unroll
            for (int j = 0; j < 4; j += 2) {
                LDSM_X4(b0[j][0], b0[j][1], b0[j+1][0], b0[j+1][1],
                        kb0 + ((j * 8 + brow) * TS + 16 * t + bcolh) * 2);
                LDSM_X4(b1[j][0], b1[j][1], b1[j+1][0], b1[j+1][1],
                        kb1 + ((j * 8 + brow) * TS + 16 * t + bcolh) * 2);
            }
            #pragma unroll
            for (int j = 0; j < 4; j++) mma16816(sacc[j], qf0[t], b0[j]);
            #pragma unroll
            for (int j = 0; j < 4; j++) mma16816(sacc[j], qf0[t], b1[j]);
            #pragma unroll
            for (int j = 0; j < 4; j++) mma16816(sacc[j], qf1[t], b0[j]);
        }

        // ---- scale + causal mask + row max ----
        bool maskblk = (32 * kt + 31 > qt * FQ + w * 16);
        float mx0 = mrow0, mx1 = mrow1;
        #pragma unroll
        for (int j = 0; j < 4; j++) {
            int col = kt * FK + j * 8 + gq * 2;
            #pragma unroll
            for (int e = 0; e < 4; e++) {
                float v = sacc[j][e] * scale;
                if (maskblk) {
                    int cc = col + (e & 1);
                    int rr = qrow0 + (e >> 1) * 8;
                    if (cc > rr) v = -1e30f;
                }
                sacc[j][e] = v;
                if (e < 2) mx0 = fmaxf(mx0, v);
                else       mx1 = fmaxf(mx1, v);
            }
        }
        mx0 = fmaxf(mx0, __shfl_xor_sync(0xffffffffu, mx0, 1));
        mx0 = fmaxf(mx0, __shfl_xor_sync(0xffffffffu, mx0, 2));
        mx1 = fmaxf(mx1, __shfl_xor_sync(0xffffffffu, mx1, 1));
        mx1 = fmaxf(mx1, __shfl_xor_sync(0xffffffffu, mx1, 2));
        float c0 = __expf(mrow0 - mx0);
        float c1 = __expf(mrow1 - mx1);
        mrow0 = mx0; mrow1 = mx1;
        #pragma unroll
        for (int j2 = 0; j2 < 16; j2++) {
            hacc[j2][0] *= c0; hacc[j2][1] *= c0;
            hacc[j2][2] *= c1; hacc[j2][3] *= c1;
        }

        // ---- P = exp(S-m), accumulate l, split+pack to A-fragments ----
        float lt0 = 0.f, lt1 = 0.f;
        uint32_t pa0[2][4], pa1[2][4];
        #pragma unroll
        for (int t = 0; t < 2; t++) {
            #pragma unroll
            for (int half = 0; half < 2; half++) {
                int j = 2 * t + half;
                float p0 = __expf(sacc[j][0] - mx0);
                float p1 = __expf(sacc[j][1] - mx0);
                float p2 = __expf(sacc[j][2] - mx1);
                float p3 = __expf(sacc[j][3] - mx1);
                lt0 += p0 + p1;
                lt1 += p2 + p3;
                split_pack(p0, p1, pa0[t][half*2+0], pa1[t][half*2+0]);
                split_pack(p2, p3, pa0[t][half*2+1], pa1[t][half*2+1]);
            }
        }
        lt0 += __shfl_xor_sync(0xffffffffu, lt0, 1);
        lt0 += __shfl_xor_sync(0xffffffffu, lt0, 2);
        lt1 += __shfl_xor_sync(0xffffffffu, lt1, 1);
        lt1 += __shfl_xor_sync(0xffffffffu, lt1, 2);
        lrow0 = lrow0 * c0 + lt0;
        lrow1 = lrow1 * c1 + lt1;

        // ---- H += P V (emulated), term-major, V^T via ldmatrix.trans ----
        uint32_t vb0 = sb + (VOFF + (st * 2 + 0) * KBLK) * 2;
        uint32_t vb1 = sb + (VOFF + (st * 2 + 1) * KBLK) * 2;
        #pragma unroll
        for (int t = 0; t < 2; t++) {
            #pragma unroll
            for (int j4 = 0; j4 < 16; j4 += 4) {
                uint32_t bv0[4][2], bv1[4][2];
                LDSM_X4_T(bv0[0][0], bv0[0][1], bv0[1][0], bv0[1][1],
                          vb0 + ((16 * t + vrow) * TS + 8 * j4 + vcolh) * 2);
                LDSM_X4_T(bv0[2][0], bv0[2][1], bv0[3][0], bv0[3][1],
                          vb0 + ((16 * t + vrow) * TS + 8 * (j4 + 2) + vcolh) * 2);
                LDSM_X4_T(bv1[0][0], bv1[0][1], bv1[1][0], bv1[1][1],
                          vb1 + ((16 * t + vrow) * TS + 8 * j4 + vcolh) * 2);
                LDSM_X4_T(bv1[2][0], bv1[2][1], bv1[3][0], bv1[3][1],
                          vb1 + ((16 * t + vrow) * TS + 8 * (j4 + 2) + vcolh) * 2);
                #pragma unroll
                for (int c = 0; c < 4; c++) mma16816(hacc[j4+c], pa0[t], bv0[c]);
                #pragma unroll
                for (int c = 0; c < 4; c++) mma16816(hacc[j4+c], pa0[t], bv1[c]);
                #pragma unroll
                for (int c = 0; c < 4; c++) mma16816(hacc[j4+c], pa1[t], bv0[c]);
            }
        }

        }  // !fullmask

        __syncthreads();
        if (kt + 2 < nkv) { LOADKV(kt + 2, st) }
        CP_COMMIT();
    }
    #undef LOADKV

    // ---- epilogue: H/l -> bf16 split planes in g_hs ----
    float li0 = 1.f / lrow0;
    float li1 = 1.f / lrow1;
    int b = bh >> 4;
    int hd = bh & (NH - 1);
    int s0 = qt * FQ + w * 16 + gr;
    size_t base0 = ((size_t)(b * SEQ + s0)) * DM + hd * DH;
    size_t base1 = ((size_t)(b * SEQ + s0 + 8)) * DM + hd * DH;
    #pragma unroll
    for (int j2 = 0; j2 < 16; j2++) {
        int d = j2 * 8 + gq * 2;
        uint32_t u0, u1;
        split_pack(hacc[j2][0] * li0, hacc[j2][1] * li0, u0, u1);
        *(uint32_t*)(g_hs[0] + base0 + d) = u0;
        *(uint32_t*)(g_hs[1] + base0 + d) = u1;
        split_pack(hacc[j2][2] * li1, hacc[j2][3] * li1, u0, u1);
        *(uint32_t*)(g_hs[0] + base1 + d) = u0;
        *(uint32_t*)(g_hs[1] + base1 + d) = u1;
    }
}

// ---------------------------------------------------------------------------
extern "C" void kernel_launch(void* const* d_in, const int* in_sizes, int n_in,
                              void* d_out, int out_size) {
    const float* x  = (const float*)d_in[0];
    const float* wq = (const float*)d_in[1];
    const float* wk = (const float*)d_in[2];
    const float* wv = (const float*)d_in[3];
    const float* wo = (const float*)d_in[4];
    const int* tok  = (const int*)d_in[5];
    float* out = (float*)d_out;

    cudaFuncSetAttribute(gemm_mma<0>,
                         cudaFuncAttributeMaxDynamicSharedMemorySize, GEMM_SMEM);
    cudaFuncSetAttribute(gemm_mma<1>,
                         cudaFuncAttributeMaxDynamicSharedMemorySize, GEMM_SMEM);
    cudaFuncSetAttribute(flash_mma,
                         cudaFuncAttributeMaxDynamicSharedMemorySize, FLASH_SMEM);

    rope_table_kernel<<<SEQ, HALF>>>(tok);                           // 0
    split_all_kernel<<<(N4X + 4*N4W)/256, 256>>>(x, wq, wk, wv, wo); // 1

    dim3 gq(DM / 128, MROWS / 128, 3);                               // 2: fused QKV
    gemm_mma<1><<<gq, 128, GEMM_SMEM>>>(nullptr);

    dim3 fgrid(SEQ / FQ, BATCH * NH);                                // 3: flash (profiled)
    flash_mma<<<fgrid, 128, FLASH_SMEM>>>();

    dim3 go(DM / 128, MROWS / 128);                                  // 4
    gemm_mma<0><<<go, 128, GEMM_SMEM>>>(out);
}